// round 6
// baseline (speedup 1.0000x reference)
#include <cuda_runtime.h>
#include <cstdint>

// Problem constants
#define B_    2
#define S_    2048
#define HID_  4096
#define NH_   32
#define NKV_  8
#define D_    128

// ---------------- scratch (__device__ globals; allocation-free) -------------
__device__ float g_Q[(size_t)B_ * S_ * NH_ * D_];    // [B,S,NH,D] (pre-rope)
__device__ float g_K[(size_t)B_ * S_ * NKV_ * D_];   // roped in-place
__device__ float g_V[(size_t)B_ * S_ * NKV_ * D_];
__device__ float g_A[(size_t)B_ * S_ * NH_ * D_];    // attn out (tf32-rounded)
__device__ float g_Wqt[(size_t)(NH_ * D_) * HID_];   // [N,K] transposed+rounded
__device__ float g_Wkt[(size_t)(NKV_ * D_) * HID_];
__device__ float g_Wvt[(size_t)(NKV_ * D_) * HID_];
__device__ float g_Wot[(size_t)HID_ * (NH_ * D_)];

__device__ __forceinline__ float tf32rn(float x) {
    uint32_t u;
    asm("cvt.rn.tf32.f32 %0, %1;" : "=r"(u) : "f"(x));
    return __uint_as_float(u);
}

// ---------------- pre-pass: W[K,N] -> Wt[N,K], tf32-rounded ------------------
__global__ void transpose_round_kernel(const float* __restrict__ W, float* __restrict__ Wt,
                                       int K, int N) {
    __shared__ float t[32][33];
    const int n0 = blockIdx.x * 32, k0 = blockIdx.y * 32;
    const int tx = threadIdx.x, ty = threadIdx.y;
#pragma unroll
    for (int j = 0; j < 32; j += 8)
        t[ty + j][tx] = W[(size_t)(k0 + ty + j) * N + n0 + tx];
    __syncthreads();
#pragma unroll
    for (int j = 0; j < 32; j += 8)
        Wt[(size_t)(n0 + ty + j) * K + k0 + tx] = tf32rn(t[tx][ty + j]);
}

// ---------------- mma helper -------------------------------------------------
__device__ __forceinline__ void mma_tf32(float* c, const uint32_t* a, const uint32_t* b) {
    asm volatile(
        "mma.sync.aligned.m16n8k8.row.col.f32.tf32.tf32.f32 "
        "{%0,%1,%2,%3}, {%4,%5,%6,%7}, {%8,%9}, {%0,%1,%2,%3};"
        : "+f"(c[0]), "+f"(c[1]), "+f"(c[2]), "+f"(c[3])
        : "r"(a[0]), "r"(a[1]), "r"(a[2]), "r"(a[3]), "r"(b[0]), "r"(b[1]));
}

// ---------------- tf32 mma.sync GEMM: C[M,N] = A[M,K] @ Bt[N,K]^T ------------
#define BM 128
#define BN 128
#define BK 32
#define TSTR 36
#define TILE_FLOATS (128 * TSTR)
#define GSM_BYTES (4 * TILE_FLOATS * 4)

__device__ __forceinline__ void g2s_tile(const float* __restrict__ G, float* sm,
                                         int row0, int K, int k0, int tid) {
#pragma unroll
    for (int i = 0; i < 4; i++) {
        int lin = tid + i * 256;
        int r = lin >> 3, c = lin & 7;
        float4 v = *(const float4*)(G + (size_t)(row0 + r) * K + k0 + c * 4);
        v.x = tf32rn(v.x); v.y = tf32rn(v.y); v.z = tf32rn(v.z); v.w = tf32rn(v.w);
        *(float4*)(sm + r * TSTR + c * 4) = v;
    }
}

__global__ __launch_bounds__(256) void tc_gemm(const float* __restrict__ A,
                                               const float* __restrict__ Bt,
                                               float* __restrict__ C,
                                               int M, int N, int K) {
    extern __shared__ float sm[];
    float* As[2] = {sm, sm + 2 * TILE_FLOATS};
    float* Bs[2] = {sm + TILE_FLOATS, sm + 3 * TILE_FLOATS};

    const int tid = threadIdx.x;
    const int lane = tid & 31, wid = tid >> 5;
    const int warpM = wid & 3;
    const int warpN = wid >> 2;
    const int ty8 = lane >> 2;
    const int tx4 = lane & 3;
    const int bm = blockIdx.y * BM, bn = blockIdx.x * BN;

    float acc[2][8][4];
#pragma unroll
    for (int mi = 0; mi < 2; mi++)
#pragma unroll
        for (int ni = 0; ni < 8; ni++)
#pragma unroll
            for (int r = 0; r < 4; r++) acc[mi][ni][r] = 0.f;

    g2s_tile(A, As[0], bm, K, 0, tid);
    g2s_tile(Bt, Bs[0], bn, K, 0, tid);
    __syncthreads();

    const int NK = K / BK;
    for (int kt = 0; kt < NK; kt++) {
        const int buf = kt & 1;
        if (kt + 1 < NK) {
            g2s_tile(A, As[buf ^ 1], bm, K, (kt + 1) * BK, tid);
            g2s_tile(Bt, Bs[buf ^ 1], bn, K, (kt + 1) * BK, tid);
        }
        const float* Ab = As[buf];
        const float* Bb = Bs[buf];
#pragma unroll
        for (int ks = 0; ks < 4; ks++) {
            const int k8 = ks * 8;
            uint32_t af[2][4];
#pragma unroll
            for (int mi = 0; mi < 2; mi++) {
                const int rb = warpM * 32 + mi * 16 + ty8;
                af[mi][0] = __float_as_uint(Ab[(rb) * TSTR + k8 + tx4]);
                af[mi][1] = __float_as_uint(Ab[(rb + 8) * TSTR + k8 + tx4]);
                af[mi][2] = __float_as_uint(Ab[(rb) * TSTR + k8 + 4 + tx4]);
                af[mi][3] = __float_as_uint(Ab[(rb + 8) * TSTR + k8 + 4 + tx4]);
            }
            uint32_t bf[8][2];
#pragma unroll
            for (int ni = 0; ni < 8; ni++) {
                const int nc = warpN * 64 + ni * 8 + ty8;
                bf[ni][0] = __float_as_uint(Bb[nc * TSTR + k8 + tx4]);
                bf[ni][1] = __float_as_uint(Bb[nc * TSTR + k8 + 4 + tx4]);
            }
#pragma unroll
            for (int mi = 0; mi < 2; mi++)
#pragma unroll
                for (int ni = 0; ni < 8; ni++)
                    mma_tf32(acc[mi][ni], af[mi], bf[ni]);
        }
        __syncthreads();
    }

#pragma unroll
    for (int mi = 0; mi < 2; mi++) {
        const int r0 = bm + warpM * 32 + mi * 16 + ty8;
#pragma unroll
        for (int ni = 0; ni < 8; ni++) {
            const int cc = bn + warpN * 64 + ni * 8 + 2 * tx4;
            *(float2*)(C + (size_t)r0 * N + cc)       = make_float2(acc[mi][ni][0], acc[mi][ni][1]);
            *(float2*)(C + (size_t)(r0 + 8) * N + cc) = make_float2(acc[mi][ni][2], acc[mi][ni][3]);
        }
    }
}

// ---------------- K RoPE (in-place, float4, 256-thread blocks) ---------------
__global__ __launch_bounds__(256) void rope_k_kernel(float* __restrict__ K,
                                                     const float* __restrict__ cosc,
                                                     const float* __restrict__ sinc) {
    const int idx = blockIdx.x * 256 + threadIdx.x;
    const int r = idx >> 4;
    const int c4 = (idx & 15) << 2;
    const int s = (r / NKV_) % S_;
    float* row = K + (size_t)r * D_;
    float4 x1 = *(float4*)(row + c4);
    float4 x2 = *(float4*)(row + c4 + 64);
    float4 c0 = *(const float4*)(cosc + s * D_ + c4);
    float4 s0 = *(const float4*)(sinc + s * D_ + c4);
    float4 c1 = *(const float4*)(cosc + s * D_ + c4 + 64);
    float4 s1 = *(const float4*)(sinc + s * D_ + c4 + 64);
    float4 o1, o2;
    o1.x = x1.x * c0.x - x2.x * s0.x;  o2.x = x2.x * c1.x + x1.x * s1.x;
    o1.y = x1.y * c0.y - x2.y * s0.y;  o2.y = x2.y * c1.y + x1.y * s1.y;
    o1.z = x1.z * c0.z - x2.z * s0.z;  o2.z = x2.z * c1.z + x1.z * s1.z;
    o1.w = x1.w * c0.w - x2.w * s0.w;  o2.w = x2.w * c1.w + x1.w * s1.w;
    *(float4*)(row + c4) = o1;
    *(float4*)(row + c4 + 64) = o2;
}

// ---------------- mma flash attention (round-4 base + packed K frags) --------
// 256 threads, 8 warps (warp = 16 q-rows x full 64 kv cols).
// Q roped+scaled+tf32 in regs (qf). K split hi/lo, packed so each (ni,ks)
// B-fragment pair {bh0,bh1,bl0,bl1} is ONE LDS.128. QK = Qr*Khi + Qr*Klo.
#define KHL_RS 260                       // floats per kv-row (16 ks * 16 + pad)
#define FKHL 0
#define FVS (FKHL + 64 * KHL_RS)         // 16640
#define FPS (FVS + 64 * 132)             // 25088
#define FL_FLOATS (FPS + 128 * 68)       // 33792
#define FL_SMEM_BYTES (FL_FLOATS * 4)    // 135168

__global__ __launch_bounds__(256) void flash_mma_kernel(
    const float* __restrict__ Qg, const float* __restrict__ Kg,
    const float* __restrict__ Vg, const float* __restrict__ cosc,
    const float* __restrict__ sinc, float* __restrict__ Og) {
    extern __shared__ float sm[];
    float* KHL = sm + FKHL;
    float* Vs  = sm + FVS;
    float* Ps  = sm + FPS;
    float* Qstage = sm;                  // temp 128x132, overlaps KHL/Vs

    const int tid = threadIdx.x;
    const int lane = tid & 31, wid = tid >> 5;
    const int ty8 = lane >> 2;
    const int tx4 = lane & 3;
    const int qt = blockIdx.x;
    const int h  = blockIdx.y;
    const int b  = blockIdx.z;
    const int kvh = h >> 2;
    const int qbase = qt * 128;
    const int wrow = wid * 16;
    const float scale = 0.08838834764831845f;

    // ---- stage Q: RoPE + scale + tf32 round ----
#pragma unroll
    for (int i = 0; i < 8; i++) {
        int lin = i * 256 + tid;         // 2048 = 128 rows * 16 pair-positions
        int r = lin >> 4;
        int c4 = (lin & 15) << 2;
        const int sg = qbase + r;
        const float* qrow = Qg + ((size_t)((b * S_ + sg) * NH_ + h)) * D_;
        float4 x1 = *(const float4*)(qrow + c4);
        float4 x2 = *(const float4*)(qrow + c4 + 64);
        float4 c0 = *(const float4*)(cosc + sg * D_ + c4);
        float4 s0 = *(const float4*)(sinc + sg * D_ + c4);
        float4 c1 = *(const float4*)(cosc + sg * D_ + c4 + 64);
        float4 s1 = *(const float4*)(sinc + sg * D_ + c4 + 64);
        float o1[4], o2[4];
        o1[0] = x1.x * c0.x - x2.x * s0.x;  o2[0] = x2.x * c1.x + x1.x * s1.x;
        o1[1] = x1.y * c0.y - x2.y * s0.y;  o2[1] = x2.y * c1.y + x1.y * s1.y;
        o1[2] = x1.z * c0.z - x2.z * s0.z;  o2[2] = x2.z * c1.z + x1.z * s1.z;
        o1[3] = x1.w * c0.w - x2.w * s0.w;  o2[3] = x2.w * c1.w + x1.w * s1.w;
#pragma unroll
        for (int j = 0; j < 4; j++) {
            Qstage[r * 132 + c4 + j]      = tf32rn(o1[j] * scale);
            Qstage[r * 132 + c4 + 64 + j] = tf32rn(o2[j] * scale);
        }
    }
    __syncthreads();

    // ---- Q fragments in registers: 16 ksteps x 4 regs ----
    uint32_t qf[16][4];
#pragma unroll
    for (int ks = 0; ks < 16; ks++) {
        const int k8 = ks * 8;
        qf[ks][0] = __float_as_uint(Qstage[(wrow + ty8) * 132 + k8 + tx4]);
        qf[ks][1] = __float_as_uint(Qstage[(wrow + ty8 + 8) * 132 + k8 + tx4]);
        qf[ks][2] = __float_as_uint(Qstage[(wrow + ty8) * 132 + k8 + 4 + tx4]);
        qf[ks][3] = __float_as_uint(Qstage[(wrow + ty8 + 8) * 132 + k8 + 4 + tx4]);
    }
    __syncthreads();    // Qstage region now reusable (KHL/Vs)

    float m_i[2] = {-1e30f, -1e30f};
    float l_i[2] = {0.f, 0.f};
    float oacc[16][4];
#pragma unroll
    for (int ni = 0; ni < 16; ni++)
#pragma unroll
        for (int r = 0; r < 4; r++) oacc[ni][r] = 0.f;

    const int NKT = 2 * qt + 2;
    for (int kt = 0; kt < NKT; kt++) {
        const int kbase = kt * 64;
        // ---- stage K (hi/lo, fragment-packed) and V (tf32) ----
#pragma unroll
        for (int i = 0; i < 8; i++) {
            int lin = i * 256 + tid;     // 2048 = 64 rows * 32 float4
            int r = lin >> 5;
            int c4 = (lin & 31) << 2;
            size_t gofs = ((size_t)((b * S_ + kbase + r) * NKV_ + kvh)) * D_ + c4;
            float4 kv = *(const float4*)(Kg + gofs);
            float kk[4] = {kv.x, kv.y, kv.z, kv.w};
#pragma unroll
            for (int j = 0; j < 4; j++) {
                const int c = c4 + j;
                const int g = c >> 3;            // k8 group
                const int p = c & 7;
                const int pos = r * KHL_RS + g * 16 + (p & 3) * 4 + (p >> 2);
                float hi = tf32rn(kk[j]);
                KHL[pos]     = hi;               // hi slot
                KHL[pos + 2] = tf32rn(kk[j] - hi); // lo slot
            }
            float4 vv = *(const float4*)(Vg + gofs);
            Vs[r * 132 + c4 + 0] = tf32rn(vv.x);
            Vs[r * 132 + c4 + 1] = tf32rn(vv.y);
            Vs[r * 132 + c4 + 2] = tf32rn(vv.z);
            Vs[r * 132 + c4 + 3] = tf32rn(vv.w);
        }
        __syncthreads();

        // ---- QK^T: sc = Qr*Khi + Qr*Klo, one LDS.128 per (ni,ks) ----
        float sc[8][4];
#pragma unroll
        for (int ni = 0; ni < 8; ni++)
#pragma unroll
            for (int r = 0; r < 4; r++) sc[ni][r] = 0.f;

#pragma unroll
        for (int ks = 0; ks < 16; ks++) {
#pragma unroll
            for (int ni = 0; ni < 8; ni++) {
                const int n = ni * 8 + ty8;
                float4 khl = *(const float4*)&KHL[n * KHL_RS + ks * 16 + tx4 * 4];
                uint32_t bh[2] = {__float_as_uint(khl.x), __float_as_uint(khl.y)};
                uint32_t bl[2] = {__float_as_uint(khl.z), __float_as_uint(khl.w)};
                mma_tf32(sc[ni], qf[ks], bh);
                mma_tf32(sc[ni], qf[ks], bl);
            }
        }

        // ---- causal mask (last two k-tiles only) ----
        if (kbase + 63 > qbase) {
#pragma unroll
            for (int ni = 0; ni < 8; ni++) {
#pragma unroll
                for (int r = 0; r < 4; r++) {
                    int row = qbase + wrow + ty8 + ((r >= 2) ? 8 : 0);
                    int col = kbase + ni * 8 + 2 * tx4 + (r & 1);
                    if (col > row) sc[ni][r] = -1e30f;
                }
            }
        }

        // ---- online softmax ----
#pragma unroll
        for (int rh = 0; rh < 2; rh++) {
            const int i0 = rh * 2, i1 = rh * 2 + 1;
            float mloc = -1e30f;
#pragma unroll
            for (int ni = 0; ni < 8; ni++)
                mloc = fmaxf(mloc, fmaxf(sc[ni][i0], sc[ni][i1]));
            mloc = fmaxf(mloc, __shfl_xor_sync(0xffffffffu, mloc, 1));
            mloc = fmaxf(mloc, __shfl_xor_sync(0xffffffffu, mloc, 2));
            const float mnew = fmaxf(m_i[rh], mloc);
            const float fac = __expf(m_i[rh] - mnew);
            m_i[rh] = mnew;
            float rsum = 0.f;
#pragma unroll
            for (int ni = 0; ni < 8; ni++) {
                float p0 = __expf(sc[ni][i0] - mnew);
                float p1 = __expf(sc[ni][i1] - mnew);
                sc[ni][i0] = p0; sc[ni][i1] = p1;
                rsum += p0 + p1;
            }
            rsum += __shfl_xor_sync(0xffffffffu, rsum, 1);
            rsum += __shfl_xor_sync(0xffffffffu, rsum, 2);
            l_i[rh] = l_i[rh] * fac + rsum;
#pragma unroll
            for (int ni = 0; ni < 16; ni++) {
                oacc[ni][i0] *= fac;
                oacc[ni][i1] *= fac;
            }
        }

        // ---- P to smem (warp-private rows) ----
#pragma unroll
        for (int ni = 0; ni < 8; ni++) {
            const int cc = ni * 8 + 2 * tx4;
            *(float2*)&Ps[(wrow + ty8) * 68 + cc] =
                make_float2(tf32rn(sc[ni][0]), tf32rn(sc[ni][1]));
            *(float2*)&Ps[(wrow + ty8 + 8) * 68 + cc] =
                make_float2(tf32rn(sc[ni][2]), tf32rn(sc[ni][3]));
        }
        __syncwarp();

        // ---- PV: oacc += P @ V ----
#pragma unroll
        for (int ks = 0; ks < 8; ks++) {
            const int k8 = ks * 8;
            uint32_t af[4];
            af[0] = __float_as_uint(Ps[(wrow + ty8) * 68 + k8 + tx4]);
            af[1] = __float_as_uint(Ps[(wrow + ty8 + 8) * 68 + k8 + tx4]);
            af[2] = __float_as_uint(Ps[(wrow + ty8) * 68 + k8 + 4 + tx4]);
            af[3] = __float_as_uint(Ps[(wrow + ty8 + 8) * 68 + k8 + 4 + tx4]);
#pragma unroll
            for (int ni = 0; ni < 16; ni++) {
                const int n = ni * 8 + ty8;
                uint32_t bf[2];
                bf[0] = __float_as_uint(Vs[(k8 + tx4) * 132 + n]);
                bf[1] = __float_as_uint(Vs[(k8 + 4 + tx4) * 132 + n]);
                mma_tf32(oacc[ni], af, bf);
            }
        }
        __syncthreads();
    }

    // ---- epilogue: normalize, tf32-round, store ----
    const float inv0 = 1.0f / l_i[0];
    const float inv1 = 1.0f / l_i[1];
    const int r0 = qbase + wrow + ty8;
#pragma unroll
    for (int ni = 0; ni < 16; ni++) {
        const int cc = ni * 8 + 2 * tx4;
        float* p0 = Og + ((size_t)((b * S_ + r0) * NH_ + h)) * D_ + cc;
        float* p1 = Og + ((size_t)((b * S_ + r0 + 8) * NH_ + h)) * D_ + cc;
        *(float2*)p0 = make_float2(tf32rn(oacc[ni][0] * inv0), tf32rn(oacc[ni][1] * inv0));
        *(float2*)p1 = make_float2(tf32rn(oacc[ni][2] * inv1), tf32rn(oacc[ni][3] * inv1));
    }
}

// ---------------- launch ----------------------------------------------------
extern "C" void kernel_launch(void* const* d_in, const int* in_sizes, int n_in,
                              void* d_out, int out_size) {
    const float* X    = (const float*)d_in[0];
    const float* Wq   = (const float*)d_in[1];
    const float* Wk   = (const float*)d_in[2];
    const float* Wv   = (const float*)d_in[3];
    const float* Wo   = (const float*)d_in[4];
    const float* cosc = (const float*)d_in[5];
    const float* sinc = (const float*)d_in[6];
    float* out = (float*)d_out;

    float *Qp, *Kp, *Vp, *Ap, *Wqt, *Wkt, *Wvt, *Wot;
    cudaGetSymbolAddress((void**)&Qp, g_Q);
    cudaGetSymbolAddress((void**)&Kp, g_K);
    cudaGetSymbolAddress((void**)&Vp, g_V);
    cudaGetSymbolAddress((void**)&Ap, g_A);
    cudaGetSymbolAddress((void**)&Wqt, g_Wqt);
    cudaGetSymbolAddress((void**)&Wkt, g_Wkt);
    cudaGetSymbolAddress((void**)&Wvt, g_Wvt);
    cudaGetSymbolAddress((void**)&Wot, g_Wot);

    const int M = B_ * S_;          // 4096
    const int NQ = NH_ * D_;        // 4096
    const int NKVD = NKV_ * D_;     // 1024

    {
        dim3 blk(32, 8);
        transpose_round_kernel<<<dim3(NQ / 32, HID_ / 32), blk>>>(Wq, Wqt, HID_, NQ);
        transpose_round_kernel<<<dim3(NKVD / 32, HID_ / 32), blk>>>(Wk, Wkt, HID_, NKVD);
        transpose_round_kernel<<<dim3(NKVD / 32, HID_ / 32), blk>>>(Wv, Wvt, HID_, NKVD);
        transpose_round_kernel<<<dim3(HID_ / 32, NQ / 32), blk>>>(Wo, Wot, NQ, HID_);
    }

    cudaFuncSetAttribute(tc_gemm, cudaFuncAttributeMaxDynamicSharedMemorySize, GSM_BYTES);

    tc_gemm<<<dim3(NQ / BN, M / BM), 256, GSM_BYTES>>>(X, Wqt, Qp, M, NQ, HID_);
    tc_gemm<<<dim3(NKVD / BN, M / BM), 256, GSM_BYTES>>>(X, Wkt, Kp, M, NKVD, HID_);
    tc_gemm<<<dim3(NKVD / BN, M / BM), 256, GSM_BYTES>>>(X, Wvt, Vp, M, NKVD, HID_);

    rope_k_kernel<<<(M * NKV_ * 16) / 256, 256>>>(Kp, cosc, sinc);

    cudaFuncSetAttribute(flash_mma_kernel, cudaFuncAttributeMaxDynamicSharedMemorySize, FL_SMEM_BYTES);
    flash_mma_kernel<<<dim3(S_ / 128, NH_, B_), 256, FL_SMEM_BYTES>>>(Qp, Kp, Vp, cosc, sinc, Ap);

    tc_gemm<<<dim3(HID_ / BN, M / BM), 256, GSM_BYTES>>>(Ap, Wot, out, M, HID_, NQ);
}

// round 7
// speedup vs baseline: 1.1670x; 1.1670x over previous
#include <cuda_runtime.h>
#include <cstdint>

// Problem constants
#define B_    2
#define S_    2048
#define HID_  4096
#define NH_   32
#define NKV_  8
#define D_    128

// ---------------- scratch (__device__ globals; allocation-free) -------------
__device__ float g_Q[(size_t)B_ * S_ * NH_ * D_];    // [B,S,NH,D] (pre-rope)
__device__ float g_K[(size_t)B_ * S_ * NKV_ * D_];   // roped in-place
__device__ float g_V[(size_t)B_ * S_ * NKV_ * D_];
__device__ float g_A[(size_t)B_ * S_ * NH_ * D_];    // attn out (tf32-rounded)
__device__ float g_Xr[(size_t)B_ * S_ * HID_];       // tf32-rounded hidden states
__device__ float g_Wqt[(size_t)(NH_ * D_) * HID_];   // [N,K] transposed+rounded
__device__ float g_Wkt[(size_t)(NKV_ * D_) * HID_];
__device__ float g_Wvt[(size_t)(NKV_ * D_) * HID_];
__device__ float g_Wot[(size_t)HID_ * (NH_ * D_)];

__device__ __forceinline__ float tf32rn(float x) {
    uint32_t u;
    asm("cvt.rn.tf32.f32 %0, %1;" : "=r"(u) : "f"(x));
    return __uint_as_float(u);
}
__device__ __forceinline__ uint32_t smem_u32(const void* p) {
    uint32_t a;
    asm("{ .reg .u64 t; cvta.to.shared.u64 t, %1; cvt.u32.u64 %0, t; }" : "=r"(a) : "l"(p));
    return a;
}

// ---------------- pre-pass kernels ------------------------------------------
__global__ void round_tf32_kernel(const float* __restrict__ in, float* __restrict__ out, int n4) {
    int i = blockIdx.x * blockDim.x + threadIdx.x;
    if (i < n4) {
        float4 v = ((const float4*)in)[i];
        v.x = tf32rn(v.x); v.y = tf32rn(v.y); v.z = tf32rn(v.z); v.w = tf32rn(v.w);
        ((float4*)out)[i] = v;
    }
}
__global__ void transpose_round_kernel(const float* __restrict__ W, float* __restrict__ Wt,
                                       int K, int N) {
    __shared__ float t[32][33];
    const int n0 = blockIdx.x * 32, k0 = blockIdx.y * 32;
    const int tx = threadIdx.x, ty = threadIdx.y;
#pragma unroll
    for (int j = 0; j < 32; j += 8)
        t[ty + j][tx] = W[(size_t)(k0 + ty + j) * N + n0 + tx];
    __syncthreads();
#pragma unroll
    for (int j = 0; j < 32; j += 8)
        Wt[(size_t)(n0 + ty + j) * K + k0 + tx] = tf32rn(t[tx][ty + j]);
}

// ---------------- mma helper -------------------------------------------------
__device__ __forceinline__ void mma_tf32(float* c, const uint32_t* a, const uint32_t* b) {
    asm volatile(
        "mma.sync.aligned.m16n8k8.row.col.f32.tf32.tf32.f32 "
        "{%0,%1,%2,%3}, {%4,%5,%6,%7}, {%8,%9}, {%0,%1,%2,%3};"
        : "+f"(c[0]), "+f"(c[1]), "+f"(c[2]), "+f"(c[3])
        : "r"(a[0]), "r"(a[1]), "r"(a[2]), "r"(a[3]), "r"(b[0]), "r"(b[1]));
}

// ---------------- tf32 mma.sync GEMM with cp.async pipeline ------------------
// C[M,N] = A[M,K] @ Bt[N,K]^T. CTA 128x128, BK=32, 256 threads, 2-stage cp.async.
// Operands must be PRE-ROUNDED to tf32 in gmem.
#define BM 128
#define BN 128
#define BK 32
#define TSTR 36
#define TILE_FLOATS (128 * TSTR)
#define GSM_BYTES (4 * TILE_FLOATS * 4)

__device__ __forceinline__ void g2s_cp(const float* __restrict__ G, uint32_t sbase,
                                       int row0, int K, int k0, int tid) {
#pragma unroll
    for (int i = 0; i < 4; i++) {
        int lin = tid + i * 256;
        int r = lin >> 3, c = lin & 7;
        uint32_t saddr = sbase + (uint32_t)(r * TSTR + c * 4) * 4u;
        const float* g = G + (size_t)(row0 + r) * K + k0 + c * 4;
        asm volatile("cp.async.cg.shared.global [%0], [%1], 16;" :: "r"(saddr), "l"(g));
    }
}

__global__ __launch_bounds__(256) void tc_gemm(const float* __restrict__ A,
                                               const float* __restrict__ Bt,
                                               float* __restrict__ C,
                                               int M, int N, int K) {
    extern __shared__ float sm[];
    float* As[2] = {sm, sm + 2 * TILE_FLOATS};
    float* Bs[2] = {sm + TILE_FLOATS, sm + 3 * TILE_FLOATS};
    const uint32_t asu[2] = {smem_u32(As[0]), smem_u32(As[1])};
    const uint32_t bsu[2] = {smem_u32(Bs[0]), smem_u32(Bs[1])};

    const int tid = threadIdx.x;
    const int lane = tid & 31, wid = tid >> 5;
    const int warpM = wid & 3;
    const int warpN = wid >> 2;
    const int ty8 = lane >> 2;
    const int tx4 = lane & 3;
    const int bm = blockIdx.y * BM, bn = blockIdx.x * BN;

    float acc[2][8][4];
#pragma unroll
    for (int mi = 0; mi < 2; mi++)
#pragma unroll
        for (int ni = 0; ni < 8; ni++)
#pragma unroll
            for (int r = 0; r < 4; r++) acc[mi][ni][r] = 0.f;

    g2s_cp(A, asu[0], bm, K, 0, tid);
    g2s_cp(Bt, bsu[0], bn, K, 0, tid);
    asm volatile("cp.async.commit_group;" ::: "memory");

    const int NK = K / BK;
    for (int kt = 0; kt < NK; kt++) {
        const int buf = kt & 1;
        if (kt + 1 < NK) {
            g2s_cp(A, asu[buf ^ 1], bm, K, (kt + 1) * BK, tid);
            g2s_cp(Bt, bsu[buf ^ 1], bn, K, (kt + 1) * BK, tid);
            asm volatile("cp.async.commit_group;" ::: "memory");
            asm volatile("cp.async.wait_group 1;" ::: "memory");
        } else {
            asm volatile("cp.async.wait_group 0;" ::: "memory");
        }
        __syncthreads();

        const float* Ab = As[buf];
        const float* Bb = Bs[buf];
#pragma unroll
        for (int ks = 0; ks < 4; ks++) {
            const int k8 = ks * 8;
            uint32_t af[2][4];
#pragma unroll
            for (int mi = 0; mi < 2; mi++) {
                const int rb = warpM * 32 + mi * 16 + ty8;
                af[mi][0] = __float_as_uint(Ab[(rb) * TSTR + k8 + tx4]);
                af[mi][1] = __float_as_uint(Ab[(rb + 8) * TSTR + k8 + tx4]);
                af[mi][2] = __float_as_uint(Ab[(rb) * TSTR + k8 + 4 + tx4]);
                af[mi][3] = __float_as_uint(Ab[(rb + 8) * TSTR + k8 + 4 + tx4]);
            }
            uint32_t bf[8][2];
#pragma unroll
            for (int ni = 0; ni < 8; ni++) {
                const int nc = warpN * 64 + ni * 8 + ty8;
                bf[ni][0] = __float_as_uint(Bb[nc * TSTR + k8 + tx4]);
                bf[ni][1] = __float_as_uint(Bb[nc * TSTR + k8 + 4 + tx4]);
            }
#pragma unroll
            for (int mi = 0; mi < 2; mi++)
#pragma unroll
                for (int ni = 0; ni < 8; ni++)
                    mma_tf32(acc[mi][ni], af[mi], bf[ni]);
        }
        __syncthreads();
    }

#pragma unroll
    for (int mi = 0; mi < 2; mi++) {
        const int r0 = bm + warpM * 32 + mi * 16 + ty8;
#pragma unroll
        for (int ni = 0; ni < 8; ni++) {
            const int cc = bn + warpN * 64 + ni * 8 + 2 * tx4;
            *(float2*)(C + (size_t)r0 * N + cc)       = make_float2(acc[mi][ni][0], acc[mi][ni][1]);
            *(float2*)(C + (size_t)(r0 + 8) * N + cc) = make_float2(acc[mi][ni][2], acc[mi][ni][3]);
        }
    }
}

// ---------------- K RoPE (in-place, float4) -----------------------------------
__global__ __launch_bounds__(256) void rope_k_kernel(float* __restrict__ K,
                                                     const float* __restrict__ cosc,
                                                     const float* __restrict__ sinc) {
    const int idx = blockIdx.x * 256 + threadIdx.x;
    const int r = idx >> 4;
    const int c4 = (idx & 15) << 2;
    const int s = (r / NKV_) % S_;
    float* row = K + (size_t)r * D_;
    float4 x1 = *(float4*)(row + c4);
    float4 x2 = *(float4*)(row + c4 + 64);
    float4 c0 = *(const float4*)(cosc + s * D_ + c4);
    float4 s0 = *(const float4*)(sinc + s * D_ + c4);
    float4 c1 = *(const float4*)(cosc + s * D_ + c4 + 64);
    float4 s1 = *(const float4*)(sinc + s * D_ + c4 + 64);
    float4 o1, o2;
    o1.x = x1.x * c0.x - x2.x * s0.x;  o2.x = x2.x * c1.x + x1.x * s1.x;
    o1.y = x1.y * c0.y - x2.y * s0.y;  o2.y = x2.y * c1.y + x1.y * s1.y;
    o1.z = x1.z * c0.z - x2.z * s0.z;  o2.z = x2.z * c1.z + x1.z * s1.z;
    o1.w = x1.w * c0.w - x2.w * s0.w;  o2.w = x2.w * c1.w + x1.w * s1.w;
    *(float4*)(row + c4) = o1;
    *(float4*)(row + c4 + 64) = o2;
}

// ---------------- mma flash attention (round-4 structure, fused Q-RoPE) ------
// Q-tile 128 rows, K-tile 64 cols, 8 warps (warp = 16 q-rows).
// QK^T in tf32x2 (hi/lo split); softmax fp32; PV in tf32.
#define QLO_STR 132
#define KS_STR  132
#define VS_STR  132
#define PS_STR  68
#define OFF_QLO 0
#define OFF_KH  (OFF_QLO + 128 * QLO_STR)     // 16896
#define OFF_KL  (OFF_KH + 64 * KS_STR)        // 25344
#define OFF_VS  (OFF_KL + 64 * KS_STR)        // 33792
#define OFF_PS  (OFF_VS + 64 * VS_STR)        // 42240
#define FL_FLOATS (OFF_PS + 128 * PS_STR)     // 50944
#define FL_SMEM_BYTES (FL_FLOATS * 4)         // 203776

__global__ __launch_bounds__(256) void flash_mma_kernel(
    const float* __restrict__ Qg, const float* __restrict__ Kg,
    const float* __restrict__ Vg, const float* __restrict__ cosc,
    const float* __restrict__ sinc, float* __restrict__ Og) {
    extern __shared__ float sm[];
    float* Qlo = sm + OFF_QLO;
    float* Kh  = sm + OFF_KH;
    float* Kl  = sm + OFF_KL;
    float* Vs  = sm + OFF_VS;
    float* Ps  = sm + OFF_PS;
    float* Qhstage = sm + OFF_KH;   // temporary, spans Kh+Kl

    const int tid = threadIdx.x;
    const int lane = tid & 31, wid = tid >> 5;
    const int ty8 = lane >> 2;
    const int tx4 = lane & 3;
    const int qt = blockIdx.x;
    const int h  = blockIdx.y;
    const int b  = blockIdx.z;
    const int kvh = h >> 2;
    const int qbase = qt * 128;
    const int wrow = wid * 16;
    const float scale = 0.08838834764831845f;

    // ---- stage Q: fused RoPE + scale + hi/lo tf32 split ----
#pragma unroll
    for (int i = 0; i < 8; i++) {
        int lin = i * 256 + tid;            // 2048 = 128 rows * 16 quad-pairs
        int r = lin >> 4;
        int c4 = (lin & 15) << 2;           // 0..60
        const int sg = qbase + r;
        const float* qrow = Qg + ((size_t)((b * S_ + sg) * NH_ + h)) * D_;
        float4 x1 = *(const float4*)(qrow + c4);
        float4 x2 = *(const float4*)(qrow + c4 + 64);
        float4 c0 = *(const float4*)(cosc + sg * D_ + c4);
        float4 s0 = *(const float4*)(sinc + sg * D_ + c4);
        float4 c1 = *(const float4*)(cosc + sg * D_ + c4 + 64);
        float4 s1 = *(const float4*)(sinc + sg * D_ + c4 + 64);
        float o1[4], o2[4];
        o1[0] = x1.x * c0.x - x2.x * s0.x;  o2[0] = x2.x * c1.x + x1.x * s1.x;
        o1[1] = x1.y * c0.y - x2.y * s0.y;  o2[1] = x2.y * c1.y + x1.y * s1.y;
        o1[2] = x1.z * c0.z - x2.z * s0.z;  o2[2] = x2.z * c1.z + x1.z * s1.z;
        o1[3] = x1.w * c0.w - x2.w * s0.w;  o2[3] = x2.w * c1.w + x1.w * s1.w;
#pragma unroll
        for (int j = 0; j < 4; j++) {
            float q1 = o1[j] * scale;
            float h1 = tf32rn(q1);
            Qhstage[r * QLO_STR + c4 + j] = h1;
            Qlo[r * QLO_STR + c4 + j] = tf32rn(q1 - h1);
            float q2 = o2[j] * scale;
            float h2 = tf32rn(q2);
            Qhstage[r * QLO_STR + c4 + 64 + j] = h2;
            Qlo[r * QLO_STR + c4 + 64 + j] = tf32rn(q2 - h2);
        }
    }
    __syncthreads();

    // ---- Q_hi fragments in registers: 16 ksteps x 4 regs ----
    uint32_t qf[16][4];
#pragma unroll
    for (int ks = 0; ks < 16; ks++) {
        const int k8 = ks * 8;
        qf[ks][0] = __float_as_uint(Qhstage[(wrow + ty8) * QLO_STR + k8 + tx4]);
        qf[ks][1] = __float_as_uint(Qhstage[(wrow + ty8 + 8) * QLO_STR + k8 + tx4]);
        qf[ks][2] = __float_as_uint(Qhstage[(wrow + ty8) * QLO_STR + k8 + 4 + tx4]);
        qf[ks][3] = __float_as_uint(Qhstage[(wrow + ty8 + 8) * QLO_STR + k8 + 4 + tx4]);
    }
    __syncthreads();   // Qhstage region (Kh/Kl) now reusable

    float m_i[2] = {-1e30f, -1e30f};
    float l_i[2] = {0.f, 0.f};
    float oacc[16][4];
#pragma unroll
    for (int ni = 0; ni < 16; ni++)
#pragma unroll
        for (int r = 0; r < 4; r++) oacc[ni][r] = 0.f;

    const int NKT = 2 * qt + 2;
    for (int kt = 0; kt < NKT; kt++) {
        const int kbase = kt * 64;
#pragma unroll
        for (int i = 0; i < 8; i++) {
            int lin = i * 256 + tid;        // 2048 float4
            int r = lin >> 5;
            int c4 = (lin & 31) << 2;
            size_t gofs = ((size_t)((b * S_ + kbase + r) * NKV_ + kvh)) * D_ + c4;
            float4 kv = *(const float4*)(Kg + gofs);
            float kk[4] = {kv.x, kv.y, kv.z, kv.w};
#pragma unroll
            for (int j = 0; j < 4; j++) {
                float hi = tf32rn(kk[j]);
                Kh[r * KS_STR + c4 + j] = hi;
                Kl[r * KS_STR + c4 + j] = tf32rn(kk[j] - hi);
            }
            float4 vv = *(const float4*)(Vg + gofs);
            Vs[r * VS_STR + c4 + 0] = tf32rn(vv.x);
            Vs[r * VS_STR + c4 + 1] = tf32rn(vv.y);
            Vs[r * VS_STR + c4 + 2] = tf32rn(vv.z);
            Vs[r * VS_STR + c4 + 3] = tf32rn(vv.w);
        }
        __syncthreads();

        // ---- QK^T (tf32x2): sc = Qhi*Khi + Qhi*Klo + Qlo*Khi ----
        float sc[8][4];
#pragma unroll
        for (int ni = 0; ni < 8; ni++)
#pragma unroll
            for (int r = 0; r < 4; r++) sc[ni][r] = 0.f;

#pragma unroll
        for (int ks = 0; ks < 16; ks++) {
            const int k8 = ks * 8;
            uint32_t ql[4];
            ql[0] = __float_as_uint(Qlo[(wrow + ty8) * QLO_STR + k8 + tx4]);
            ql[1] = __float_as_uint(Qlo[(wrow + ty8 + 8) * QLO_STR + k8 + tx4]);
            ql[2] = __float_as_uint(Qlo[(wrow + ty8) * QLO_STR + k8 + 4 + tx4]);
            ql[3] = __float_as_uint(Qlo[(wrow + ty8 + 8) * QLO_STR + k8 + 4 + tx4]);
#pragma unroll
            for (int ni = 0; ni < 8; ni++) {
                const int n = ni * 8 + ty8;
                uint32_t bh[2], bl[2];
                bh[0] = __float_as_uint(Kh[n * KS_STR + k8 + tx4]);
                bh[1] = __float_as_uint(Kh[n * KS_STR + k8 + 4 + tx4]);
                bl[0] = __float_as_uint(Kl[n * KS_STR + k8 + tx4]);
                bl[1] = __float_as_uint(Kl[n * KS_STR + k8 + 4 + tx4]);
                mma_tf32(sc[ni], qf[ks], bh);
                mma_tf32(sc[ni], qf[ks], bl);
                mma_tf32(sc[ni], ql, bh);
            }
        }

        // ---- causal mask (last two k-tiles only) ----
        if (kbase + 63 > qbase) {
#pragma unroll
            for (int ni = 0; ni < 8; ni++) {
#pragma unroll
                for (int r = 0; r < 4; r++) {
                    int row = qbase + wrow + ty8 + ((r >= 2) ? 8 : 0);
                    int col = kbase + ni * 8 + 2 * tx4 + (r & 1);
                    if (col > row) sc[ni][r] = -1e30f;
                }
            }
        }

        // ---- online softmax ----
#pragma unroll
        for (int rh = 0; rh < 2; rh++) {
            const int i0 = rh * 2, i1 = rh * 2 + 1;
            float mloc = -1e30f;
#pragma unroll
            for (int ni = 0; ni < 8; ni++)
                mloc = fmaxf(mloc, fmaxf(sc[ni][i0], sc[ni][i1]));
            mloc = fmaxf(mloc, __shfl_xor_sync(0xffffffffu, mloc, 1));
            mloc = fmaxf(mloc, __shfl_xor_sync(0xffffffffu, mloc, 2));
            const float mnew = fmaxf(m_i[rh], mloc);
            const float fac = __expf(m_i[rh] - mnew);
            m_i[rh] = mnew;
            float rsum = 0.f;
#pragma unroll
            for (int ni = 0; ni < 8; ni++) {
                float p0 = __expf(sc[ni][i0] - mnew);
                float p1 = __expf(sc[ni][i1] - mnew);
                sc[ni][i0] = p0; sc[ni][i1] = p1;
                rsum += p0 + p1;
            }
            rsum += __shfl_xor_sync(0xffffffffu, rsum, 1);
            rsum += __shfl_xor_sync(0xffffffffu, rsum, 2);
            l_i[rh] = l_i[rh] * fac + rsum;
#pragma unroll
            for (int ni = 0; ni < 16; ni++) {
                oacc[ni][i0] *= fac;
                oacc[ni][i1] *= fac;
            }
        }

        // ---- P to smem (warp-private rows) ----
#pragma unroll
        for (int ni = 0; ni < 8; ni++) {
            const int cc = ni * 8 + 2 * tx4;
            *(float2*)&Ps[(wrow + ty8) * PS_STR + cc] =
                make_float2(tf32rn(sc[ni][0]), tf32rn(sc[ni][1]));
            *(float2*)&Ps[(wrow + ty8 + 8) * PS_STR + cc] =
                make_float2(tf32rn(sc[ni][2]), tf32rn(sc[ni][3]));
        }
        __syncwarp();

        // ---- PV: oacc += P @ V ----
#pragma unroll
        for (int ks = 0; ks < 8; ks++) {
            const int k8 = ks * 8;
            uint32_t af[4];
            af[0] = __float_as_uint(Ps[(wrow + ty8) * PS_STR + k8 + tx4]);
            af[1] = __float_as_uint(Ps[(wrow + ty8 + 8) * PS_STR + k8 + tx4]);
            af[2] = __float_as_uint(Ps[(wrow + ty8) * PS_STR + k8 + 4 + tx4]);
            af[3] = __float_as_uint(Ps[(wrow + ty8 + 8) * PS_STR + k8 + 4 + tx4]);
#pragma unroll
            for (int ni = 0; ni < 16; ni++) {
                const int n = ni * 8 + ty8;     // d-column
                uint32_t bf[2];
                bf[0] = __float_as_uint(Vs[(k8 + tx4) * VS_STR + n]);
                bf[1] = __float_as_uint(Vs[(k8 + 4 + tx4) * VS_STR + n]);
                mma_tf32(oacc[ni], af, bf);
            }
        }
        __syncthreads();
    }

    // ---- epilogue: normalize, tf32-round (feeds O-proj mma), store ----
    const float inv0 = 1.0f / l_i[0];
    const float inv1 = 1.0f / l_i[1];
    const int r0 = qbase + wrow + ty8;
#pragma unroll
    for (int ni = 0; ni < 16; ni++) {
        const int cc = ni * 8 + 2 * tx4;
        float* p0 = Og + ((size_t)((b * S_ + r0) * NH_ + h)) * D_ + cc;
        float* p1 = Og + ((size_t)((b * S_ + r0 + 8) * NH_ + h)) * D_ + cc;
        *(float2*)p0 = make_float2(tf32rn(oacc[ni][0] * inv0), tf32rn(oacc[ni][1] * inv0));
        *(float2*)p1 = make_float2(tf32rn(oacc[ni][2] * inv1), tf32rn(oacc[ni][3] * inv1));
    }
}

// ---------------- launch ----------------------------------------------------
extern "C" void kernel_launch(void* const* d_in, const int* in_sizes, int n_in,
                              void* d_out, int out_size) {
    const float* X    = (const float*)d_in[0];
    const float* Wq   = (const float*)d_in[1];
    const float* Wk   = (const float*)d_in[2];
    const float* Wv   = (const float*)d_in[3];
    const float* Wo   = (const float*)d_in[4];
    const float* cosc = (const float*)d_in[5];
    const float* sinc = (const float*)d_in[6];
    float* out = (float*)d_out;

    float *Qp, *Kp, *Vp, *Ap, *Xr, *Wqt, *Wkt, *Wvt, *Wot;
    cudaGetSymbolAddress((void**)&Qp, g_Q);
    cudaGetSymbolAddress((void**)&Kp, g_K);
    cudaGetSymbolAddress((void**)&Vp, g_V);
    cudaGetSymbolAddress((void**)&Ap, g_A);
    cudaGetSymbolAddress((void**)&Xr, g_Xr);
    cudaGetSymbolAddress((void**)&Wqt, g_Wqt);
    cudaGetSymbolAddress((void**)&Wkt, g_Wkt);
    cudaGetSymbolAddress((void**)&Wvt, g_Wvt);
    cudaGetSymbolAddress((void**)&Wot, g_Wot);

    const int M = B_ * S_;          // 4096
    const int NQ = NH_ * D_;        // 4096
    const int NKVD = NKV_ * D_;     // 1024

    // Pre-pass: round X (cp.async GEMM needs pre-rounded A); transpose+round weights
    {
        int n4 = M * HID_ / 4;
        round_tf32_kernel<<<(n4 + 255) / 256, 256>>>(X, Xr, n4);
        dim3 blk(32, 8);
        transpose_round_kernel<<<dim3(NQ / 32, HID_ / 32), blk>>>(Wq, Wqt, HID_, NQ);
        transpose_round_kernel<<<dim3(NKVD / 32, HID_ / 32), blk>>>(Wk, Wkt, HID_, NKVD);
        transpose_round_kernel<<<dim3(NKVD / 32, HID_ / 32), blk>>>(Wv, Wvt, HID_, NKVD);
        transpose_round_kernel<<<dim3(HID_ / 32, NQ / 32), blk>>>(Wo, Wot, NQ, HID_);
    }

    cudaFuncSetAttribute(tc_gemm, cudaFuncAttributeMaxDynamicSharedMemorySize, GSM_BYTES);

    // Projections (mma.sync tf32, cp.async pipeline)
    tc_gemm<<<dim3(NQ / BN, M / BM), 256, GSM_BYTES>>>(Xr, Wqt, Qp, M, NQ, HID_);
    tc_gemm<<<dim3(NKVD / BN, M / BM), 256, GSM_BYTES>>>(Xr, Wkt, Kp, M, NKVD, HID_);
    tc_gemm<<<dim3(NKVD / BN, M / BM), 256, GSM_BYTES>>>(Xr, Wvt, Vp, M, NKVD, HID_);

    // K RoPE in-place (Q RoPE fused into flash staging)
    rope_k_kernel<<<(M * NKV_ * 16) / 256, 256>>>(Kp, cosc, sinc);

    // Flash attention (round-4 structure)
    cudaFuncSetAttribute(flash_mma_kernel, cudaFuncAttributeMaxDynamicSharedMemorySize, FL_SMEM_BYTES);
    flash_mma_kernel<<<dim3(S_ / 128, NH_, B_), 256, FL_SMEM_BYTES>>>(Qp, Kp, Vp, cosc, sinc, Ap);

    // Output projection (g_A pre-rounded by flash epilogue)
    tc_gemm<<<dim3(HID_ / BN, M / BM), 256, GSM_BYTES>>>(Ap, Wot, out, M, HID_, NQ);
}

// round 8
// speedup vs baseline: 1.2182x; 1.0439x over previous
#include <cuda_runtime.h>
#include <cstdint>

// Problem constants
#define B_    2
#define S_    2048
#define HID_  4096
#define NH_   32
#define NKV_  8
#define D_    128

// ---------------- scratch (__device__ globals; allocation-free) -------------
__device__ float g_Q[(size_t)B_ * S_ * NH_ * D_];    // [B,S,NH,D] (pre-rope)
__device__ float g_K[(size_t)B_ * S_ * NKV_ * D_];   // roped in-place
__device__ float g_V[(size_t)B_ * S_ * NKV_ * D_];
__device__ float g_A[(size_t)B_ * S_ * NH_ * D_];    // attn out (tf32-rounded)
__device__ float g_Xr[(size_t)B_ * S_ * HID_];       // tf32-rounded hidden states
__device__ float g_Wqt[(size_t)(NH_ * D_) * HID_];   // [N,K] transposed+rounded
__device__ float g_Wkt[(size_t)(NKV_ * D_) * HID_];
__device__ float g_Wvt[(size_t)(NKV_ * D_) * HID_];
__device__ float g_Wot[(size_t)HID_ * (NH_ * D_)];

__device__ __forceinline__ float tf32rn(float x) {
    uint32_t u;
    asm("cvt.rn.tf32.f32 %0, %1;" : "=r"(u) : "f"(x));
    return __uint_as_float(u);
}
__device__ __forceinline__ uint32_t smem_u32(const void* p) {
    uint32_t a;
    asm("{ .reg .u64 t; cvta.to.shared.u64 t, %1; cvt.u32.u64 %0, t; }" : "=r"(a) : "l"(p));
    return a;
}

// ---------------- pre-pass kernels ------------------------------------------
__global__ void round_tf32_kernel(const float* __restrict__ in, float* __restrict__ out, int n4) {
    int i = blockIdx.x * blockDim.x + threadIdx.x;
    if (i < n4) {
        float4 v = ((const float4*)in)[i];
        v.x = tf32rn(v.x); v.y = tf32rn(v.y); v.z = tf32rn(v.z); v.w = tf32rn(v.w);
        ((float4*)out)[i] = v;
    }
}
__global__ void transpose_round_kernel(const float* __restrict__ W, float* __restrict__ Wt,
                                       int K, int N) {
    __shared__ float t[32][33];
    const int n0 = blockIdx.x * 32, k0 = blockIdx.y * 32;
    const int tx = threadIdx.x, ty = threadIdx.y;
#pragma unroll
    for (int j = 0; j < 32; j += 8)
        t[ty + j][tx] = W[(size_t)(k0 + ty + j) * N + n0 + tx];
    __syncthreads();
#pragma unroll
    for (int j = 0; j < 32; j += 8)
        Wt[(size_t)(n0 + ty + j) * K + k0 + tx] = tf32rn(t[tx][ty + j]);
}

// ---------------- mma helper -------------------------------------------------
__device__ __forceinline__ void mma_tf32(float* c, const uint32_t* a, const uint32_t* b) {
    asm volatile(
        "mma.sync.aligned.m16n8k8.row.col.f32.tf32.tf32.f32 "
        "{%0,%1,%2,%3}, {%4,%5,%6,%7}, {%8,%9}, {%0,%1,%2,%3};"
        : "+f"(c[0]), "+f"(c[1]), "+f"(c[2]), "+f"(c[3])
        : "r"(a[0]), "r"(a[1]), "r"(a[2]), "r"(a[3]), "r"(b[0]), "r"(b[1]));
}

// ---------------- tf32 mma.sync GEMM with cp.async pipeline ------------------
// C[M,N] = A[M,K] @ Bt[N,K]^T. CTA 128x128, BK=32, 256 threads, 2-stage cp.async.
// Operands must be PRE-ROUNDED to tf32 in gmem.
#define BM 128
#define BN 128
#define BK 32
#define TSTR 36
#define TILE_FLOATS (128 * TSTR)
#define GSM_BYTES (4 * TILE_FLOATS * 4)

__device__ __forceinline__ void g2s_cp(const float* __restrict__ G, uint32_t sbase,
                                       int row0, int K, int k0, int tid) {
#pragma unroll
    for (int i = 0; i < 4; i++) {
        int lin = tid + i * 256;
        int r = lin >> 3, c = lin & 7;
        uint32_t saddr = sbase + (uint32_t)(r * TSTR + c * 4) * 4u;
        const float* g = G + (size_t)(row0 + r) * K + k0 + c * 4;
        asm volatile("cp.async.cg.shared.global [%0], [%1], 16;" :: "r"(saddr), "l"(g));
    }
}

__global__ __launch_bounds__(256) void tc_gemm(const float* __restrict__ A,
                                               const float* __restrict__ Bt,
                                               float* __restrict__ C,
                                               int M, int N, int K) {
    extern __shared__ float sm[];
    float* As[2] = {sm, sm + 2 * TILE_FLOATS};
    float* Bs[2] = {sm + TILE_FLOATS, sm + 3 * TILE_FLOATS};
    const uint32_t asu[2] = {smem_u32(As[0]), smem_u32(As[1])};
    const uint32_t bsu[2] = {smem_u32(Bs[0]), smem_u32(Bs[1])};

    const int tid = threadIdx.x;
    const int lane = tid & 31, wid = tid >> 5;
    const int warpM = wid & 3;
    const int warpN = wid >> 2;
    const int ty8 = lane >> 2;
    const int tx4 = lane & 3;
    const int bm = blockIdx.y * BM, bn = blockIdx.x * BN;

    float acc[2][8][4];
#pragma unroll
    for (int mi = 0; mi < 2; mi++)
#pragma unroll
        for (int ni = 0; ni < 8; ni++)
#pragma unroll
            for (int r = 0; r < 4; r++) acc[mi][ni][r] = 0.f;

    g2s_cp(A, asu[0], bm, K, 0, tid);
    g2s_cp(Bt, bsu[0], bn, K, 0, tid);
    asm volatile("cp.async.commit_group;" ::: "memory");

    const int NK = K / BK;
    for (int kt = 0; kt < NK; kt++) {
        const int buf = kt & 1;
        if (kt + 1 < NK) {
            g2s_cp(A, asu[buf ^ 1], bm, K, (kt + 1) * BK, tid);
            g2s_cp(Bt, bsu[buf ^ 1], bn, K, (kt + 1) * BK, tid);
            asm volatile("cp.async.commit_group;" ::: "memory");
            asm volatile("cp.async.wait_group 1;" ::: "memory");
        } else {
            asm volatile("cp.async.wait_group 0;" ::: "memory");
        }
        __syncthreads();

        const float* Ab = As[buf];
        const float* Bb = Bs[buf];
#pragma unroll
        for (int ks = 0; ks < 4; ks++) {
            const int k8 = ks * 8;
            uint32_t af[2][4];
#pragma unroll
            for (int mi = 0; mi < 2; mi++) {
                const int rb = warpM * 32 + mi * 16 + ty8;
                af[mi][0] = __float_as_uint(Ab[(rb) * TSTR + k8 + tx4]);
                af[mi][1] = __float_as_uint(Ab[(rb + 8) * TSTR + k8 + tx4]);
                af[mi][2] = __float_as_uint(Ab[(rb) * TSTR + k8 + 4 + tx4]);
                af[mi][3] = __float_as_uint(Ab[(rb + 8) * TSTR + k8 + 4 + tx4]);
            }
            uint32_t bf[8][2];
#pragma unroll
            for (int ni = 0; ni < 8; ni++) {
                const int nc = warpN * 64 + ni * 8 + ty8;
                bf[ni][0] = __float_as_uint(Bb[nc * TSTR + k8 + tx4]);
                bf[ni][1] = __float_as_uint(Bb[nc * TSTR + k8 + 4 + tx4]);
            }
#pragma unroll
            for (int mi = 0; mi < 2; mi++)
#pragma unroll
                for (int ni = 0; ni < 8; ni++)
                    mma_tf32(acc[mi][ni], af[mi], bf[ni]);
        }
        __syncthreads();
    }

#pragma unroll
    for (int mi = 0; mi < 2; mi++) {
        const int r0 = bm + warpM * 32 + mi * 16 + ty8;
#pragma unroll
        for (int ni = 0; ni < 8; ni++) {
            const int cc = bn + warpN * 64 + ni * 8 + 2 * tx4;
            *(float2*)(C + (size_t)r0 * N + cc)       = make_float2(acc[mi][ni][0], acc[mi][ni][1]);
            *(float2*)(C + (size_t)(r0 + 8) * N + cc) = make_float2(acc[mi][ni][2], acc[mi][ni][3]);
        }
    }
}

// ---------------- K RoPE (in-place, float4) -----------------------------------
__global__ __launch_bounds__(256) void rope_k_kernel(float* __restrict__ K,
                                                     const float* __restrict__ cosc,
                                                     const float* __restrict__ sinc) {
    const int idx = blockIdx.x * 256 + threadIdx.x;
    const int r = idx >> 4;
    const int c4 = (idx & 15) << 2;
    const int s = (r / NKV_) % S_;
    float* row = K + (size_t)r * D_;
    float4 x1 = *(float4*)(row + c4);
    float4 x2 = *(float4*)(row + c4 + 64);
    float4 c0 = *(const float4*)(cosc + s * D_ + c4);
    float4 s0 = *(const float4*)(sinc + s * D_ + c4);
    float4 c1 = *(const float4*)(cosc + s * D_ + c4 + 64);
    float4 s1 = *(const float4*)(sinc + s * D_ + c4 + 64);
    float4 o1, o2;
    o1.x = x1.x * c0.x - x2.x * s0.x;  o2.x = x2.x * c1.x + x1.x * s1.x;
    o1.y = x1.y * c0.y - x2.y * s0.y;  o2.y = x2.y * c1.y + x1.y * s1.y;
    o1.z = x1.z * c0.z - x2.z * s0.z;  o2.z = x2.z * c1.z + x1.z * s1.z;
    o1.w = x1.w * c0.w - x2.w * s0.w;  o2.w = x2.w * c1.w + x1.w * s1.w;
    *(float4*)(row + c4) = o1;
    *(float4*)(row + c4 + 64) = o2;
}

// ---------------- mma flash attention (round-7 structure, 2-MMA QK) ----------
// Q-tile 128 rows, K-tile 64 cols, 8 warps (warp = 16 q-rows).
// QK = Qr*Khi + Qr*Klo (K hi/lo split, Q single tf32-RN); softmax fp32; PV tf32.
#define KS_STR  132
#define VS_STR  132
#define PS_STR  68
#define OFF_KH  0
#define OFF_KL  (OFF_KH + 64 * KS_STR)        // 8448
#define OFF_VS  (OFF_KL + 64 * KS_STR)        // 16896
#define OFF_PS  (OFF_VS + 64 * VS_STR)        // 25344
#define FL_FLOATS (OFF_PS + 128 * PS_STR)     // 34048
#define FL_SMEM_BYTES (FL_FLOATS * 4)         // 136192

__global__ __launch_bounds__(256) void flash_mma_kernel(
    const float* __restrict__ Qg, const float* __restrict__ Kg,
    const float* __restrict__ Vg, const float* __restrict__ cosc,
    const float* __restrict__ sinc, float* __restrict__ Og) {
    extern __shared__ float sm[];
    float* Kh  = sm + OFF_KH;
    float* Kl  = sm + OFF_KL;
    float* Vs  = sm + OFF_VS;
    float* Ps  = sm + OFF_PS;
    float* Qstage = sm + OFF_KH;    // temporary 128x132 = 16896 floats, spans Kh+Kl

    const int tid = threadIdx.x;
    const int lane = tid & 31, wid = tid >> 5;
    const int ty8 = lane >> 2;
    const int tx4 = lane & 3;
    const int qt = blockIdx.x;
    const int h  = blockIdx.y;
    const int b  = blockIdx.z;
    const int kvh = h >> 2;
    const int qbase = qt * 128;
    const int wrow = wid * 16;
    const float scale = 0.08838834764831845f;

    // ---- stage Q: fused RoPE + scale + tf32-RN ----
#pragma unroll
    for (int i = 0; i < 8; i++) {
        int lin = i * 256 + tid;            // 2048 = 128 rows * 16 quad-pairs
        int r = lin >> 4;
        int c4 = (lin & 15) << 2;           // 0..60
        const int sg = qbase + r;
        const float* qrow = Qg + ((size_t)((b * S_ + sg) * NH_ + h)) * D_;
        float4 x1 = *(const float4*)(qrow + c4);
        float4 x2 = *(const float4*)(qrow + c4 + 64);
        float4 c0 = *(const float4*)(cosc + sg * D_ + c4);
        float4 s0 = *(const float4*)(sinc + sg * D_ + c4);
        float4 c1 = *(const float4*)(cosc + sg * D_ + c4 + 64);
        float4 s1 = *(const float4*)(sinc + sg * D_ + c4 + 64);
        float o1[4], o2[4];
        o1[0] = x1.x * c0.x - x2.x * s0.x;  o2[0] = x2.x * c1.x + x1.x * s1.x;
        o1[1] = x1.y * c0.y - x2.y * s0.y;  o2[1] = x2.y * c1.y + x1.y * s1.y;
        o1[2] = x1.z * c0.z - x2.z * s0.z;  o2[2] = x2.z * c1.z + x1.z * s1.z;
        o1[3] = x1.w * c0.w - x2.w * s0.w;  o2[3] = x2.w * c1.w + x1.w * s1.w;
#pragma unroll
        for (int j = 0; j < 4; j++) {
            Qstage[r * 132 + c4 + j]      = tf32rn(o1[j] * scale);
            Qstage[r * 132 + c4 + 64 + j] = tf32rn(o2[j] * scale);
        }
    }
    __syncthreads();

    // ---- Q fragments in registers: 16 ksteps x 4 regs ----
    uint32_t qf[16][4];
#pragma unroll
    for (int ks = 0; ks < 16; ks++) {
        const int k8 = ks * 8;
        qf[ks][0] = __float_as_uint(Qstage[(wrow + ty8) * 132 + k8 + tx4]);
        qf[ks][1] = __float_as_uint(Qstage[(wrow + ty8 + 8) * 132 + k8 + tx4]);
        qf[ks][2] = __float_as_uint(Qstage[(wrow + ty8) * 132 + k8 + 4 + tx4]);
        qf[ks][3] = __float_as_uint(Qstage[(wrow + ty8 + 8) * 132 + k8 + 4 + tx4]);
    }
    __syncthreads();   // Qstage region (Kh/Kl) now reusable

    float m_i[2] = {-1e30f, -1e30f};
    float l_i[2] = {0.f, 0.f};
    float oacc[16][4];
#pragma unroll
    for (int ni = 0; ni < 16; ni++)
#pragma unroll
        for (int r = 0; r < 4; r++) oacc[ni][r] = 0.f;

    const int NKT = 2 * qt + 2;
    for (int kt = 0; kt < NKT; kt++) {
        const int kbase = kt * 64;
        // ---- stage K (hi/lo split) and V (tf32) ----
#pragma unroll
        for (int i = 0; i < 8; i++) {
            int lin = i * 256 + tid;        // 2048 float4
            int r = lin >> 5;
            int c4 = (lin & 31) << 2;
            size_t gofs = ((size_t)((b * S_ + kbase + r) * NKV_ + kvh)) * D_ + c4;
            float4 kv = *(const float4*)(Kg + gofs);
            float kk[4] = {kv.x, kv.y, kv.z, kv.w};
#pragma unroll
            for (int j = 0; j < 4; j++) {
                float hi = tf32rn(kk[j]);
                Kh[r * KS_STR + c4 + j] = hi;
                Kl[r * KS_STR + c4 + j] = tf32rn(kk[j] - hi);
            }
            float4 vv = *(const float4*)(Vg + gofs);
            Vs[r * VS_STR + c4 + 0] = tf32rn(vv.x);
            Vs[r * VS_STR + c4 + 1] = tf32rn(vv.y);
            Vs[r * VS_STR + c4 + 2] = tf32rn(vv.z);
            Vs[r * VS_STR + c4 + 3] = tf32rn(vv.w);
        }
        __syncthreads();

        // ---- QK^T: sc = Qr*Khi + Qr*Klo ----
        float sc[8][4];
#pragma unroll
        for (int ni = 0; ni < 8; ni++)
#pragma unroll
            for (int r = 0; r < 4; r++) sc[ni][r] = 0.f;

#pragma unroll
        for (int ks = 0; ks < 16; ks++) {
            const int k8 = ks * 8;
#pragma unroll
            for (int ni = 0; ni < 8; ni++) {
                const int n = ni * 8 + ty8;
                uint32_t bh[2], bl[2];
                bh[0] = __float_as_uint(Kh[n * KS_STR + k8 + tx4]);
                bh[1] = __float_as_uint(Kh[n * KS_STR + k8 + 4 + tx4]);
                bl[0] = __float_as_uint(Kl[n * KS_STR + k8 + tx4]);
                bl[1] = __float_as_uint(Kl[n * KS_STR + k8 + 4 + tx4]);
                mma_tf32(sc[ni], qf[ks], bh);
                mma_tf32(sc[ni], qf[ks], bl);
            }
        }

        // ---- causal mask (last two k-tiles only) ----
        if (kbase + 63 > qbase) {
#pragma unroll
            for (int ni = 0; ni < 8; ni++) {
#pragma unroll
                for (int r = 0; r < 4; r++) {
                    int row = qbase + wrow + ty8 + ((r >= 2) ? 8 : 0);
                    int col = kbase + ni * 8 + 2 * tx4 + (r & 1);
                    if (col > row) sc[ni][r] = -1e30f;
                }
            }
        }

        // ---- online softmax ----
#pragma unroll
        for (int rh = 0; rh < 2; rh++) {
            const int i0 = rh * 2, i1 = rh * 2 + 1;
            float mloc = -1e30f;
#pragma unroll
            for (int ni = 0; ni < 8; ni++)
                mloc = fmaxf(mloc, fmaxf(sc[ni][i0], sc[ni][i1]));
            mloc = fmaxf(mloc, __shfl_xor_sync(0xffffffffu, mloc, 1));
            mloc = fmaxf(mloc, __shfl_xor_sync(0xffffffffu, mloc, 2));
            const float mnew = fmaxf(m_i[rh], mloc);
            const float fac = __expf(m_i[rh] - mnew);
            m_i[rh] = mnew;
            float rsum = 0.f;
#pragma unroll
            for (int ni = 0; ni < 8; ni++) {
                float p0 = __expf(sc[ni][i0] - mnew);
                float p1 = __expf(sc[ni][i1] - mnew);
                sc[ni][i0] = p0; sc[ni][i1] = p1;
                rsum += p0 + p1;
            }
            rsum += __shfl_xor_sync(0xffffffffu, rsum, 1);
            rsum += __shfl_xor_sync(0xffffffffu, rsum, 2);
            l_i[rh] = l_i[rh] * fac + rsum;
#pragma unroll
            for (int ni = 0; ni < 16; ni++) {
                oacc[ni][i0] *= fac;
                oacc[ni][i1] *= fac;
            }
        }

        // ---- P to smem (warp-private rows) ----
#pragma unroll
        for (int ni = 0; ni < 8; ni++) {
            const int cc = ni * 8 + 2 * tx4;
            *(float2*)&Ps[(wrow + ty8) * PS_STR + cc] =
                make_float2(tf32rn(sc[ni][0]), tf32rn(sc[ni][1]));
            *(float2*)&Ps[(wrow + ty8 + 8) * PS_STR + cc] =
                make_float2(tf32rn(sc[ni][2]), tf32rn(sc[ni][3]));
        }
        __syncwarp();

        // ---- PV: oacc += P @ V ----
#pragma unroll
        for (int ks = 0; ks < 8; ks++) {
            const int k8 = ks * 8;
            uint32_t af[4];
            af[0] = __float_as_uint(Ps[(wrow + ty8) * PS_STR + k8 + tx4]);
            af[1] = __float_as_uint(Ps[(wrow + ty8 + 8) * PS_STR + k8 + tx4]);
            af[2] = __float_as_uint(Ps[(wrow + ty8) * PS_STR + k8 + 4 + tx4]);
            af[3] = __float_as_uint(Ps[(wrow + ty8 + 8) * PS_STR + k8 + 4 + tx4]);
#pragma unroll
            for (int ni = 0; ni < 16; ni++) {
                const int n = ni * 8 + ty8;     // d-column
                uint32_t bf[2];
                bf[0] = __float_as_uint(Vs[(k8 + tx4) * VS_STR + n]);
                bf[1] = __float_as_uint(Vs[(k8 + 4 + tx4) * VS_STR + n]);
                mma_tf32(oacc[ni], af, bf);
            }
        }
        __syncthreads();
    }

    // ---- epilogue: normalize, tf32-round (feeds O-proj mma), store ----
    const float inv0 = 1.0f / l_i[0];
    const float inv1 = 1.0f / l_i[1];
    const int r0 = qbase + wrow + ty8;
#pragma unroll
    for (int ni = 0; ni < 16; ni++) {
        const int cc = ni * 8 + 2 * tx4;
        float* p0 = Og + ((size_t)((b * S_ + r0) * NH_ + h)) * D_ + cc;
        float* p1 = Og + ((size_t)((b * S_ + r0 + 8) * NH_ + h)) * D_ + cc;
        *(float2*)p0 = make_float2(tf32rn(oacc[ni][0] * inv0), tf32rn(oacc[ni][1] * inv0));
        *(float2*)p1 = make_float2(tf32rn(oacc[ni][2] * inv1), tf32rn(oacc[ni][3] * inv1));
    }
}

// ---------------- launch ----------------------------------------------------
extern "C" void kernel_launch(void* const* d_in, const int* in_sizes, int n_in,
                              void* d_out, int out_size) {
    const float* X    = (const float*)d_in[0];
    const float* Wq   = (const float*)d_in[1];
    const float* Wk   = (const float*)d_in[2];
    const float* Wv   = (const float*)d_in[3];
    const float* Wo   = (const float*)d_in[4];
    const float* cosc = (const float*)d_in[5];
    const float* sinc = (const float*)d_in[6];
    float* out = (float*)d_out;

    float *Qp, *Kp, *Vp, *Ap, *Xr, *Wqt, *Wkt, *Wvt, *Wot;
    cudaGetSymbolAddress((void**)&Qp, g_Q);
    cudaGetSymbolAddress((void**)&Kp, g_K);
    cudaGetSymbolAddress((void**)&Vp, g_V);
    cudaGetSymbolAddress((void**)&Ap, g_A);
    cudaGetSymbolAddress((void**)&Xr, g_Xr);
    cudaGetSymbolAddress((void**)&Wqt, g_Wqt);
    cudaGetSymbolAddress((void**)&Wkt, g_Wkt);
    cudaGetSymbolAddress((void**)&Wvt, g_Wvt);
    cudaGetSymbolAddress((void**)&Wot, g_Wot);

    const int M = B_ * S_;          // 4096
    const int NQ = NH_ * D_;        // 4096
    const int NKVD = NKV_ * D_;     // 1024

    // Pre-pass: round X (cp.async GEMM needs pre-rounded A); transpose+round weights
    {
        int n4 = M * HID_ / 4;
        round_tf32_kernel<<<(n4 + 255) / 256, 256>>>(X, Xr, n4);
        dim3 blk(32, 8);
        transpose_round_kernel<<<dim3(NQ / 32, HID_ / 32), blk>>>(Wq, Wqt, HID_, NQ);
        transpose_round_kernel<<<dim3(NKVD / 32, HID_ / 32), blk>>>(Wk, Wkt, HID_, NKVD);
        transpose_round_kernel<<<dim3(NKVD / 32, HID_ / 32), blk>>>(Wv, Wvt, HID_, NKVD);
        transpose_round_kernel<<<dim3(HID_ / 32, NQ / 32), blk>>>(Wo, Wot, NQ, HID_);
    }

    cudaFuncSetAttribute(tc_gemm, cudaFuncAttributeMaxDynamicSharedMemorySize, GSM_BYTES);

    // Projections (mma.sync tf32, cp.async pipeline)
    tc_gemm<<<dim3(NQ / BN, M / BM), 256, GSM_BYTES>>>(Xr, Wqt, Qp, M, NQ, HID_);
    tc_gemm<<<dim3(NKVD / BN, M / BM), 256, GSM_BYTES>>>(Xr, Wkt, Kp, M, NKVD, HID_);
    tc_gemm<<<dim3(NKVD / BN, M / BM), 256, GSM_BYTES>>>(Xr, Wvt, Vp, M, NKVD, HID_);

    // K RoPE in-place (Q RoPE fused into flash staging)
    rope_k_kernel<<<(M * NKV_ * 16) / 256, 256>>>(Kp, cosc, sinc);

    // Flash attention (2-MMA QK)
    cudaFuncSetAttribute(flash_mma_kernel, cudaFuncAttributeMaxDynamicSharedMemorySize, FL_SMEM_BYTES);
    flash_mma_kernel<<<dim3(S_ / 128, NH_, B_), 256, FL_SMEM_BYTES>>>(Qp, Kp, Vp, cosc, sinc, Ap);

    // Output projection (g_A pre-rounded by flash epilogue)
    tc_gemm<<<dim3(HID_ / BN, M / BM), 256, GSM_BYTES>>>(Ap, Wot, out, M, HID_, NQ);
}

// round 9
// speedup vs baseline: 2.0200x; 1.6581x over previous
#include <cuda_runtime.h>
#include <cuda_fp16.h>
#include <cstdint>

// Problem constants
#define B_    2
#define S_    2048
#define HID_  4096
#define NH_   32
#define NKV_  8
#define D_    128

// ---------------- scratch (__device__ globals; allocation-free) -------------
__device__ float  g_Q[(size_t)B_ * S_ * NH_ * D_];    // fp32 (pre-rope)
__device__ float  g_K[(size_t)B_ * S_ * NKV_ * D_];   // fp32, roped in-place
__device__ float  g_V[(size_t)B_ * S_ * NKV_ * D_];
__device__ __half g_Ah[(size_t)B_ * S_ * NH_ * D_];   // attn out (fp16)
__device__ __half g_Xh[(size_t)B_ * S_ * HID_];       // fp16 hidden states
__device__ __half g_Wqt[(size_t)(NH_ * D_) * HID_];   // [N,K] transposed fp16
__device__ __half g_Wkt[(size_t)(NKV_ * D_) * HID_];
__device__ __half g_Wvt[(size_t)(NKV_ * D_) * HID_];
__device__ __half g_Wot[(size_t)HID_ * (NH_ * D_)];

__device__ __forceinline__ float tf32rn(float x) {
    uint32_t u;
    asm("cvt.rn.tf32.f32 %0, %1;" : "=r"(u) : "f"(x));
    return __uint_as_float(u);
}
__device__ __forceinline__ uint32_t smem_u32(const void* p) {
    uint32_t a;
    asm("{ .reg .u64 t; cvta.to.shared.u64 t, %1; cvt.u32.u64 %0, t; }" : "=r"(a) : "l"(p));
    return a;
}

// ---------------- pre-pass kernels ------------------------------------------
__global__ void cvt_half_kernel(const float* __restrict__ in, __half* __restrict__ out, int n4) {
    int i = blockIdx.x * blockDim.x + threadIdx.x;
    if (i < n4) {
        float4 v = ((const float4*)in)[i];
        ((__half2*)out)[i * 2]     = __floats2half2_rn(v.x, v.y);
        ((__half2*)out)[i * 2 + 1] = __floats2half2_rn(v.z, v.w);
    }
}
// W[K,N] -> Wt[N,K] fp16
__global__ void transpose_half_kernel(const float* __restrict__ W, __half* __restrict__ Wt,
                                      int K, int N) {
    __shared__ float t[32][33];
    const int n0 = blockIdx.x * 32, k0 = blockIdx.y * 32;
    const int tx = threadIdx.x, ty = threadIdx.y;
#pragma unroll
    for (int j = 0; j < 32; j += 8)
        t[ty + j][tx] = W[(size_t)(k0 + ty + j) * N + n0 + tx];
    __syncthreads();
#pragma unroll
    for (int j = 0; j < 32; j += 8)
        Wt[(size_t)(n0 + ty + j) * K + k0 + tx] = __float2half_rn(t[tx][ty + j]);
}

// ---------------- mma helpers -------------------------------------------------
__device__ __forceinline__ void mma_f16(float* c, const uint32_t* a, const uint32_t* b) {
    asm volatile(
        "mma.sync.aligned.m16n8k16.row.col.f32.f16.f16.f32 "
        "{%0,%1,%2,%3}, {%4,%5,%6,%7}, {%8,%9}, {%0,%1,%2,%3};"
        : "+f"(c[0]), "+f"(c[1]), "+f"(c[2]), "+f"(c[3])
        : "r"(a[0]), "r"(a[1]), "r"(a[2]), "r"(a[3]), "r"(b[0]), "r"(b[1]));
}
__device__ __forceinline__ void mma_tf32(float* c, const uint32_t* a, const uint32_t* b) {
    asm volatile(
        "mma.sync.aligned.m16n8k8.row.col.f32.tf32.tf32.f32 "
        "{%0,%1,%2,%3}, {%4,%5,%6,%7}, {%8,%9}, {%0,%1,%2,%3};"
        : "+f"(c[0]), "+f"(c[1]), "+f"(c[2]), "+f"(c[3])
        : "r"(a[0]), "r"(a[1]), "r"(a[2]), "r"(a[3]), "r"(b[0]), "r"(b[1]));
}

// ---------------- fp16 mma.sync GEMM: C[M,N] = A[M,K] @ Bt[N,K]^T ------------
// CTA 128x128, BK=64, 256 threads, 2-stage cp.async. A,Bt are fp16.
#define BM 128
#define BN 128
#define BKH 64
#define TSTRH 72                        // halves per row (64 + 8 pad)
#define TILE_HALFS (128 * TSTRH)        // 9216 halves = 18432 B
#define GSM_BYTES (4 * TILE_HALFS * 2)  // 73728 B

__device__ __forceinline__ void g2s_cp_h(const __half* __restrict__ G, uint32_t sbase,
                                         int row0, int K, int k0, int tid) {
#pragma unroll
    for (int i = 0; i < 4; i++) {
        int lin = tid + i * 256;            // 1024 chunks: 128 rows x 8 x 16B
        int r = lin >> 3, c = lin & 7;
        uint32_t saddr = sbase + (uint32_t)(r * TSTRH + c * 8) * 2u;
        const __half* g = G + (size_t)(row0 + r) * K + k0 + c * 8;
        asm volatile("cp.async.cg.shared.global [%0], [%1], 16;" :: "r"(saddr), "l"(g));
    }
}

__global__ __launch_bounds__(256) void tc_gemm(const __half* __restrict__ A,
                                               const __half* __restrict__ Bt,
                                               float* __restrict__ C,
                                               int M, int N, int K) {
    extern __shared__ __half smh[];
    __half* As[2] = {smh, smh + 2 * TILE_HALFS};
    __half* Bs[2] = {smh + TILE_HALFS, smh + 3 * TILE_HALFS};
    const uint32_t asu[2] = {smem_u32(As[0]), smem_u32(As[1])};
    const uint32_t bsu[2] = {smem_u32(Bs[0]), smem_u32(Bs[1])};

    const int tid = threadIdx.x;
    const int lane = tid & 31, wid = tid >> 5;
    const int warpM = wid & 3;
    const int warpN = wid >> 2;
    const int ty8 = lane >> 2;
    const int tx4 = lane & 3;
    const int bm = blockIdx.y * BM, bn = blockIdx.x * BN;

    float acc[2][8][4];
#pragma unroll
    for (int mi = 0; mi < 2; mi++)
#pragma unroll
        for (int ni = 0; ni < 8; ni++)
#pragma unroll
            for (int r = 0; r < 4; r++) acc[mi][ni][r] = 0.f;

    g2s_cp_h(A, asu[0], bm, K, 0, tid);
    g2s_cp_h(Bt, bsu[0], bn, K, 0, tid);
    asm volatile("cp.async.commit_group;" ::: "memory");

    const int NK = K / BKH;
    for (int kt = 0; kt < NK; kt++) {
        const int buf = kt & 1;
        if (kt + 1 < NK) {
            g2s_cp_h(A, asu[buf ^ 1], bm, K, (kt + 1) * BKH, tid);
            g2s_cp_h(Bt, bsu[buf ^ 1], bn, K, (kt + 1) * BKH, tid);
            asm volatile("cp.async.commit_group;" ::: "memory");
            asm volatile("cp.async.wait_group 1;" ::: "memory");
        } else {
            asm volatile("cp.async.wait_group 0;" ::: "memory");
        }
        __syncthreads();

        const __half* Ab = As[buf];
        const __half* Bb = Bs[buf];
#pragma unroll
        for (int ks = 0; ks < 4; ks++) {            // k16 steps
            const int k16 = ks * 16;
            uint32_t af[2][4];
#pragma unroll
            for (int mi = 0; mi < 2; mi++) {
                const int rb = warpM * 32 + mi * 16 + ty8;
                af[mi][0] = *(const uint32_t*)&Ab[(rb) * TSTRH + k16 + 2 * tx4];
                af[mi][1] = *(const uint32_t*)&Ab[(rb + 8) * TSTRH + k16 + 2 * tx4];
                af[mi][2] = *(const uint32_t*)&Ab[(rb) * TSTRH + k16 + 2 * tx4 + 8];
                af[mi][3] = *(const uint32_t*)&Ab[(rb + 8) * TSTRH + k16 + 2 * tx4 + 8];
            }
            uint32_t bf[8][2];
#pragma unroll
            for (int ni = 0; ni < 8; ni++) {
                const int nc = warpN * 64 + ni * 8 + ty8;
                bf[ni][0] = *(const uint32_t*)&Bb[nc * TSTRH + k16 + 2 * tx4];
                bf[ni][1] = *(const uint32_t*)&Bb[nc * TSTRH + k16 + 2 * tx4 + 8];
            }
#pragma unroll
            for (int mi = 0; mi < 2; mi++)
#pragma unroll
                for (int ni = 0; ni < 8; ni++)
                    mma_f16(acc[mi][ni], af[mi], bf[ni]);
        }
        __syncthreads();
    }

#pragma unroll
    for (int mi = 0; mi < 2; mi++) {
        const int r0 = bm + warpM * 32 + mi * 16 + ty8;
#pragma unroll
        for (int ni = 0; ni < 8; ni++) {
            const int cc = bn + warpN * 64 + ni * 8 + 2 * tx4;
            *(float2*)(C + (size_t)r0 * N + cc)       = make_float2(acc[mi][ni][0], acc[mi][ni][1]);
            *(float2*)(C + (size_t)(r0 + 8) * N + cc) = make_float2(acc[mi][ni][2], acc[mi][ni][3]);
        }
    }
}

// ---------------- K RoPE (in-place fp32, float4) ------------------------------
__global__ __launch_bounds__(256) void rope_k_kernel(float* __restrict__ K,
                                                     const float* __restrict__ cosc,
                                                     const float* __restrict__ sinc) {
    const int idx = blockIdx.x * 256 + threadIdx.x;
    const int r = idx >> 4;
    const int c4 = (idx & 15) << 2;
    const int s = (r / NKV_) % S_;
    float* row = K + (size_t)r * D_;
    float4 x1 = *(float4*)(row + c4);
    float4 x2 = *(float4*)(row + c4 + 64);
    float4 c0 = *(const float4*)(cosc + s * D_ + c4);
    float4 s0 = *(const float4*)(sinc + s * D_ + c4);
    float4 c1 = *(const float4*)(cosc + s * D_ + c4 + 64);
    float4 s1 = *(const float4*)(sinc + s * D_ + c4 + 64);
    float4 o1, o2;
    o1.x = x1.x * c0.x - x2.x * s0.x;  o2.x = x2.x * c1.x + x1.x * s1.x;
    o1.y = x1.y * c0.y - x2.y * s0.y;  o2.y = x2.y * c1.y + x1.y * s1.y;
    o1.z = x1.z * c0.z - x2.z * s0.z;  o2.z = x2.z * c1.z + x1.z * s1.z;
    o1.w = x1.w * c0.w - x2.w * s0.w;  o2.w = x2.w * c1.w + x1.w * s1.w;
    *(float4*)(row + c4) = o1;
    *(float4*)(row + c4 + 64) = o2;
}

// ---------------- flash attention: fp16 QK (K hi/lo split) + tf32 PV ---------
// Q-tile 128 rows, K-tile 64 cols, 8 warps (warp = 16 q-rows).
// smem bytes: Kh 17408 | Kl 17408 | Vs 33792 | Ps 34816. Qstage overlaps Kh+Kl.
#define QS_STR  136                      // halves per Q row
#define KH_STR  136                      // halves per K row
#define VS_STR  132                      // floats
#define PS_STR  68                       // floats
#define OFF_KL_B  17408
#define OFF_VS_B  34816
#define OFF_PS_B  (34816 + 33792)
#define FL_SMEM_BYTES (OFF_PS_B + 128 * PS_STR * 4)   // 103424

__global__ __launch_bounds__(256) void flash_mma_kernel(
    const float* __restrict__ Qg, const float* __restrict__ Kg,
    const float* __restrict__ Vg, const float* __restrict__ cosc,
    const float* __restrict__ sinc, __half* __restrict__ Og) {
    extern __shared__ char smc[];
    __half* Kh = (__half*)(smc);
    __half* Kl = (__half*)(smc + OFF_KL_B);
    float*  Vs = (float*)(smc + OFF_VS_B);
    float*  Ps = (float*)(smc + OFF_PS_B);
    __half* Qstage = (__half*)smc;       // 128*136 halves = 34816 B, spans Kh+Kl

    const int tid = threadIdx.x;
    const int lane = tid & 31, wid = tid >> 5;
    const int ty8 = lane >> 2;
    const int tx4 = lane & 3;
    const int qt = blockIdx.x;
    const int h  = blockIdx.y;
    const int b  = blockIdx.z;
    const int kvh = h >> 2;
    const int qbase = qt * 128;
    const int wrow = wid * 16;
    const float scale = 0.08838834764831845f;

    // ---- stage Q: fused RoPE + scale + fp16 round ----
#pragma unroll
    for (int i = 0; i < 8; i++) {
        int lin = i * 256 + tid;            // 2048 = 128 rows * 16 quad-pairs
        int r = lin >> 4;
        int c4 = (lin & 15) << 2;
        const int sg = qbase + r;
        const float* qrow = Qg + ((size_t)((b * S_ + sg) * NH_ + h)) * D_;
        float4 x1 = *(const float4*)(qrow + c4);
        float4 x2 = *(const float4*)(qrow + c4 + 64);
        float4 c0 = *(const float4*)(cosc + sg * D_ + c4);
        float4 s0 = *(const float4*)(sinc + sg * D_ + c4);
        float4 c1 = *(const float4*)(cosc + sg * D_ + c4 + 64);
        float4 s1 = *(const float4*)(sinc + sg * D_ + c4 + 64);
        float o1[4], o2[4];
        o1[0] = x1.x * c0.x - x2.x * s0.x;  o2[0] = x2.x * c1.x + x1.x * s1.x;
        o1[1] = x1.y * c0.y - x2.y * s0.y;  o2[1] = x2.y * c1.y + x1.y * s1.y;
        o1[2] = x1.z * c0.z - x2.z * s0.z;  o2[2] = x2.z * c1.z + x1.z * s1.z;
        o1[3] = x1.w * c0.w - x2.w * s0.w;  o2[3] = x2.w * c1.w + x1.w * s1.w;
#pragma unroll
        for (int j = 0; j < 4; j++) {
            Qstage[r * QS_STR + c4 + j]      = __float2half_rn(o1[j] * scale);
            Qstage[r * QS_STR + c4 + 64 + j] = __float2half_rn(o2[j] * scale);
        }
    }
    __syncthreads();

    // ---- Q fragments: 8 k16-steps x 4 regs (half2 pairs) ----
    uint32_t qf[8][4];
#pragma unroll
    for (int ks = 0; ks < 8; ks++) {
        const int k16 = ks * 16;
        qf[ks][0] = *(const uint32_t*)&Qstage[(wrow + ty8) * QS_STR + k16 + 2 * tx4];
        qf[ks][1] = *(const uint32_t*)&Qstage[(wrow + ty8 + 8) * QS_STR + k16 + 2 * tx4];
        qf[ks][2] = *(const uint32_t*)&Qstage[(wrow + ty8) * QS_STR + k16 + 2 * tx4 + 8];
        qf[ks][3] = *(const uint32_t*)&Qstage[(wrow + ty8 + 8) * QS_STR + k16 + 2 * tx4 + 8];
    }
    __syncthreads();   // Qstage region (Kh/Kl) now reusable

    float m_i[2] = {-1e30f, -1e30f};
    float l_i[2] = {0.f, 0.f};
    float oacc[16][4];
#pragma unroll
    for (int ni = 0; ni < 16; ni++)
#pragma unroll
        for (int r = 0; r < 4; r++) oacc[ni][r] = 0.f;

    const int NKT = 2 * qt + 2;
    for (int kt = 0; kt < NKT; kt++) {
        const int kbase = kt * 64;
        // ---- stage K (fp16 hi/lo) and V (tf32) ----
#pragma unroll
        for (int i = 0; i < 8; i++) {
            int lin = i * 256 + tid;        // 2048 float4
            int r = lin >> 5;
            int c4 = (lin & 31) << 2;
            size_t gofs = ((size_t)((b * S_ + kbase + r) * NKV_ + kvh)) * D_ + c4;
            float4 kv = *(const float4*)(Kg + gofs);
            float kk[4] = {kv.x, kv.y, kv.z, kv.w};
#pragma unroll
            for (int j = 0; j < 4; j++) {
                __half hi = __float2half_rn(kk[j]);
                Kh[r * KH_STR + c4 + j] = hi;
                Kl[r * KH_STR + c4 + j] = __float2half_rn(kk[j] - __half2float(hi));
            }
            float4 vv = *(const float4*)(Vg + gofs);
            Vs[r * VS_STR + c4 + 0] = tf32rn(vv.x);
            Vs[r * VS_STR + c4 + 1] = tf32rn(vv.y);
            Vs[r * VS_STR + c4 + 2] = tf32rn(vv.z);
            Vs[r * VS_STR + c4 + 3] = tf32rn(vv.w);
        }
        __syncthreads();

        // ---- QK^T: sc = Q*Khi + Q*Klo (fp16 m16n8k16) ----
        float sc[8][4];
#pragma unroll
        for (int ni = 0; ni < 8; ni++)
#pragma unroll
            for (int r = 0; r < 4; r++) sc[ni][r] = 0.f;

#pragma unroll
        for (int ks = 0; ks < 8; ks++) {
            const int k16 = ks * 16;
#pragma unroll
            for (int ni = 0; ni < 8; ni++) {
                const int n = ni * 8 + ty8;
                uint32_t bh[2], bl[2];
                bh[0] = *(const uint32_t*)&Kh[n * KH_STR + k16 + 2 * tx4];
                bh[1] = *(const uint32_t*)&Kh[n * KH_STR + k16 + 2 * tx4 + 8];
                bl[0] = *(const uint32_t*)&Kl[n * KH_STR + k16 + 2 * tx4];
                bl[1] = *(const uint32_t*)&Kl[n * KH_STR + k16 + 2 * tx4 + 8];
                mma_f16(sc[ni], qf[ks], bh);
                mma_f16(sc[ni], qf[ks], bl);
            }
        }

        // ---- causal mask (last two k-tiles only) ----
        if (kbase + 63 > qbase) {
#pragma unroll
            for (int ni = 0; ni < 8; ni++) {
#pragma unroll
                for (int r = 0; r < 4; r++) {
                    int row = qbase + wrow + ty8 + ((r >= 2) ? 8 : 0);
                    int col = kbase + ni * 8 + 2 * tx4 + (r & 1);
                    if (col > row) sc[ni][r] = -1e30f;
                }
            }
        }

        // ---- online softmax ----
#pragma unroll
        for (int rh = 0; rh < 2; rh++) {
            const int i0 = rh * 2, i1 = rh * 2 + 1;
            float mloc = -1e30f;
#pragma unroll
            for (int ni = 0; ni < 8; ni++)
                mloc = fmaxf(mloc, fmaxf(sc[ni][i0], sc[ni][i1]));
            mloc = fmaxf(mloc, __shfl_xor_sync(0xffffffffu, mloc, 1));
            mloc = fmaxf(mloc, __shfl_xor_sync(0xffffffffu, mloc, 2));
            const float mnew = fmaxf(m_i[rh], mloc);
            const float fac = __expf(m_i[rh] - mnew);
            m_i[rh] = mnew;
            float rsum = 0.f;
#pragma unroll
            for (int ni = 0; ni < 8; ni++) {
                float p0 = __expf(sc[ni][i0] - mnew);
                float p1 = __expf(sc[ni][i1] - mnew);
                sc[ni][i0] = p0; sc[ni][i1] = p1;
                rsum += p0 + p1;
            }
            rsum += __shfl_xor_sync(0xffffffffu, rsum, 1);
            rsum += __shfl_xor_sync(0xffffffffu, rsum, 2);
            l_i[rh] = l_i[rh] * fac + rsum;
#pragma unroll
            for (int ni = 0; ni < 16; ni++) {
                oacc[ni][i0] *= fac;
                oacc[ni][i1] *= fac;
            }
        }

        // ---- P to smem (tf32, warp-private rows) ----
#pragma unroll
        for (int ni = 0; ni < 8; ni++) {
            const int cc = ni * 8 + 2 * tx4;
            *(float2*)&Ps[(wrow + ty8) * PS_STR + cc] =
                make_float2(tf32rn(sc[ni][0]), tf32rn(sc[ni][1]));
            *(float2*)&Ps[(wrow + ty8 + 8) * PS_STR + cc] =
                make_float2(tf32rn(sc[ni][2]), tf32rn(sc[ni][3]));
        }
        __syncwarp();

        // ---- PV (tf32): oacc += P @ V ----
#pragma unroll
        for (int ks = 0; ks < 8; ks++) {
            const int k8 = ks * 8;
            uint32_t af[4];
            af[0] = __float_as_uint(Ps[(wrow + ty8) * PS_STR + k8 + tx4]);
            af[1] = __float_as_uint(Ps[(wrow + ty8 + 8) * PS_STR + k8 + tx4]);
            af[2] = __float_as_uint(Ps[(wrow + ty8) * PS_STR + k8 + 4 + tx4]);
            af[3] = __float_as_uint(Ps[(wrow + ty8 + 8) * PS_STR + k8 + 4 + tx4]);
#pragma unroll
            for (int ni = 0; ni < 16; ni++) {
                const int n = ni * 8 + ty8;     // d-column
                uint32_t bf[2];
                bf[0] = __float_as_uint(Vs[(k8 + tx4) * VS_STR + n]);
                bf[1] = __float_as_uint(Vs[(k8 + 4 + tx4) * VS_STR + n]);
                mma_tf32(oacc[ni], af, bf);
            }
        }
        __syncthreads();
    }

    // ---- epilogue: normalize, fp16 round (feeds O-proj), store ----
    const float inv0 = 1.0f / l_i[0];
    const float inv1 = 1.0f / l_i[1];
    const int r0 = qbase + wrow + ty8;
#pragma unroll
    for (int ni = 0; ni < 16; ni++) {
        const int cc = ni * 8 + 2 * tx4;
        __half* p0 = Og + ((size_t)((b * S_ + r0) * NH_ + h)) * D_ + cc;
        __half* p1 = Og + ((size_t)((b * S_ + r0 + 8) * NH_ + h)) * D_ + cc;
        *(__half2*)p0 = __floats2half2_rn(oacc[ni][0] * inv0, oacc[ni][1] * inv0);
        *(__half2*)p1 = __floats2half2_rn(oacc[ni][2] * inv1, oacc[ni][3] * inv1);
    }
}

// ---------------- launch ----------------------------------------------------
extern "C" void kernel_launch(void* const* d_in, const int* in_sizes, int n_in,
                              void* d_out, int out_size) {
    const float* X    = (const float*)d_in[0];
    const float* Wq   = (const float*)d_in[1];
    const float* Wk   = (const float*)d_in[2];
    const float* Wv   = (const float*)d_in[3];
    const float* Wo   = (const float*)d_in[4];
    const float* cosc = (const float*)d_in[5];
    const float* sinc = (const float*)d_in[6];
    float* out = (float*)d_out;

    float *Qp, *Kp, *Vp;
    __half *Ah, *Xh, *Wqt, *Wkt, *Wvt, *Wot;
    cudaGetSymbolAddress((void**)&Qp, g_Q);
    cudaGetSymbolAddress((void**)&Kp, g_K);
    cudaGetSymbolAddress((void**)&Vp, g_V);
    cudaGetSymbolAddress((void**)&Ah, g_Ah);
    cudaGetSymbolAddress((void**)&Xh, g_Xh);
    cudaGetSymbolAddress((void**)&Wqt, g_Wqt);
    cudaGetSymbolAddress((void**)&Wkt, g_Wkt);
    cudaGetSymbolAddress((void**)&Wvt, g_Wvt);
    cudaGetSymbolAddress((void**)&Wot, g_Wot);

    const int M = B_ * S_;          // 4096
    const int NQ = NH_ * D_;        // 4096
    const int NKVD = NKV_ * D_;     // 1024

    // Pre-pass: X -> fp16; weights -> transposed fp16 [N,K]
    {
        int n4 = M * HID_ / 4;
        cvt_half_kernel<<<(n4 + 255) / 256, 256>>>(X, Xh, n4);
        dim3 blk(32, 8);
        transpose_half_kernel<<<dim3(NQ / 32, HID_ / 32), blk>>>(Wq, Wqt, HID_, NQ);
        transpose_half_kernel<<<dim3(NKVD / 32, HID_ / 32), blk>>>(Wk, Wkt, HID_, NKVD);
        transpose_half_kernel<<<dim3(NKVD / 32, HID_ / 32), blk>>>(Wv, Wvt, HID_, NKVD);
        transpose_half_kernel<<<dim3(HID_ / 32, NQ / 32), blk>>>(Wo, Wot, NQ, HID_);
    }

    cudaFuncSetAttribute(tc_gemm, cudaFuncAttributeMaxDynamicSharedMemorySize, GSM_BYTES);

    // Projections (fp16 mma, cp.async pipeline)
    tc_gemm<<<dim3(NQ / BN, M / BM), 256, GSM_BYTES>>>(Xh, Wqt, Qp, M, NQ, HID_);
    tc_gemm<<<dim3(NKVD / BN, M / BM), 256, GSM_BYTES>>>(Xh, Wkt, Kp, M, NKVD, HID_);
    tc_gemm<<<dim3(NKVD / BN, M / BM), 256, GSM_BYTES>>>(Xh, Wvt, Vp, M, NKVD, HID_);

    // K RoPE in-place (Q RoPE fused into flash staging)
    rope_k_kernel<<<(M * NKV_ * 16) / 256, 256>>>(Kp, cosc, sinc);

    // Flash attention (fp16 QK + tf32 PV); writes fp16 attn-out
    cudaFuncSetAttribute(flash_mma_kernel, cudaFuncAttributeMaxDynamicSharedMemorySize, FL_SMEM_BYTES);
    flash_mma_kernel<<<dim3(S_ / 128, NH_, B_), 256, FL_SMEM_BYTES>>>(Qp, Kp, Vp, cosc, sinc, Ah);

    // Output projection (fp16 A from flash epilogue)
    tc_gemm<<<dim3(HID_ / BN, M / BM), 256, GSM_BYTES>>>(Ah, Wot, out, M, HID_, NQ);
}

// round 10
// speedup vs baseline: 2.2821x; 1.1297x over previous
#include <cuda_runtime.h>
#include <cuda_fp16.h>
#include <cstdint>

// Problem constants
#define B_    2
#define S_    2048
#define HID_  4096
#define NH_   32
#define NKV_  8
#define D_    128

// ---------------- scratch (__device__ globals; allocation-free) -------------
__device__ float  g_Q[(size_t)B_ * S_ * NH_ * D_];    // fp32 (pre-rope)
__device__ float  g_K[(size_t)B_ * S_ * NKV_ * D_];   // fp32 (pre-rope)
__device__ float  g_V[(size_t)B_ * S_ * NKV_ * D_];   // fp32
__device__ __half g_Khh[(size_t)B_ * S_ * NKV_ * D_]; // roped K hi (fp16)
__device__ __half g_Khl[(size_t)B_ * S_ * NKV_ * D_]; // roped K lo (fp16)
__device__ __half g_Vt[(size_t)B_ * NKV_ * D_ * S_];  // V transposed [b,kvh,d,s] fp16
__device__ __half g_Ah[(size_t)B_ * S_ * NH_ * D_];   // attn out (fp16)
__device__ __half g_Xh[(size_t)B_ * S_ * HID_];       // fp16 hidden states
__device__ __half g_Wqt[(size_t)(NH_ * D_) * HID_];   // [N,K] transposed fp16
__device__ __half g_Wkt[(size_t)(NKV_ * D_) * HID_];
__device__ __half g_Wvt[(size_t)(NKV_ * D_) * HID_];
__device__ __half g_Wot[(size_t)HID_ * (NH_ * D_)];

__device__ __forceinline__ uint32_t smem_u32(const void* p) {
    uint32_t a;
    asm("{ .reg .u64 t; cvta.to.shared.u64 t, %1; cvt.u32.u64 %0, t; }" : "=r"(a) : "l"(p));
    return a;
}
__device__ __forceinline__ void cp16(uint32_t saddr, const void* g) {
    asm volatile("cp.async.cg.shared.global [%0], [%1], 16;" :: "r"(saddr), "l"(g));
}
#define CP_COMMIT() asm volatile("cp.async.commit_group;" ::: "memory")
#define CP_WAIT(n)  asm volatile("cp.async.wait_group %0;" :: "n"(n) : "memory")

// ---------------- pre-pass kernels ------------------------------------------
__global__ void cvt_half_kernel(const float* __restrict__ in, __half* __restrict__ out, int n4) {
    int i = blockIdx.x * blockDim.x + threadIdx.x;
    if (i < n4) {
        float4 v = ((const float4*)in)[i];
        ((__half2*)out)[i * 2]     = __floats2half2_rn(v.x, v.y);
        ((__half2*)out)[i * 2 + 1] = __floats2half2_rn(v.z, v.w);
    }
}
__global__ void transpose_half_kernel(const float* __restrict__ W, __half* __restrict__ Wt,
                                      int K, int N) {
    __shared__ float t[32][33];
    const int n0 = blockIdx.x * 32, k0 = blockIdx.y * 32;
    const int tx = threadIdx.x, ty = threadIdx.y;
#pragma unroll
    for (int j = 0; j < 32; j += 8)
        t[ty + j][tx] = W[(size_t)(k0 + ty + j) * N + n0 + tx];
    __syncthreads();
#pragma unroll
    for (int j = 0; j < 32; j += 8)
        Wt[(size_t)(n0 + ty + j) * K + k0 + tx] = __float2half_rn(t[tx][ty + j]);
}
// K RoPE -> fp16 hi/lo split
__global__ __launch_bounds__(256) void rope_khl_kernel(const float* __restrict__ K,
                                                       __half* __restrict__ Khh,
                                                       __half* __restrict__ Khl,
                                                       const float* __restrict__ cosc,
                                                       const float* __restrict__ sinc) {
    const int idx = blockIdx.x * 256 + threadIdx.x;
    const int r = idx >> 4;
    const int c4 = (idx & 15) << 2;
    const int s = (r / NKV_) % S_;
    const float* row = K + (size_t)r * D_;
    float4 x1 = *(const float4*)(row + c4);
    float4 x2 = *(const float4*)(row + c4 + 64);
    float4 c0 = *(const float4*)(cosc + s * D_ + c4);
    float4 s0 = *(const float4*)(sinc + s * D_ + c4);
    float4 c1 = *(const float4*)(cosc + s * D_ + c4 + 64);
    float4 s1 = *(const float4*)(sinc + s * D_ + c4 + 64);
    float o1[4], o2[4];
    o1[0] = x1.x * c0.x - x2.x * s0.x;  o2[0] = x2.x * c1.x + x1.x * s1.x;
    o1[1] = x1.y * c0.y - x2.y * s0.y;  o2[1] = x2.y * c1.y + x1.y * s1.y;
    o1[2] = x1.z * c0.z - x2.z * s0.z;  o2[2] = x2.z * c1.z + x1.z * s1.z;
    o1[3] = x1.w * c0.w - x2.w * s0.w;  o2[3] = x2.w * c1.w + x1.w * s1.w;
    __half h1[4], l1[4], h2[4], l2[4];
#pragma unroll
    for (int j = 0; j < 4; j++) {
        h1[j] = __float2half_rn(o1[j]);
        l1[j] = __float2half_rn(o1[j] - __half2float(h1[j]));
        h2[j] = __float2half_rn(o2[j]);
        l2[j] = __float2half_rn(o2[j] - __half2float(h2[j]));
    }
    __half* ph = Khh + (size_t)r * D_;
    __half* pl = Khl + (size_t)r * D_;
    *(__half2*)(ph + c4)     = __halves2half2(h1[0], h1[1]);
    *(__half2*)(ph + c4 + 2) = __halves2half2(h1[2], h1[3]);
    *(__half2*)(ph + c4 + 64)     = __halves2half2(h2[0], h2[1]);
    *(__half2*)(ph + c4 + 64 + 2) = __halves2half2(h2[2], h2[3]);
    *(__half2*)(pl + c4)     = __halves2half2(l1[0], l1[1]);
    *(__half2*)(pl + c4 + 2) = __halves2half2(l1[2], l1[3]);
    *(__half2*)(pl + c4 + 64)     = __halves2half2(l2[0], l2[1]);
    *(__half2*)(pl + c4 + 64 + 2) = __halves2half2(l2[2], l2[3]);
}
// V [b,s,kvh,d] fp32 -> Vt [b,kvh,d,s] fp16
__global__ void vt_transpose_kernel(const float* __restrict__ V, __half* __restrict__ Vt) {
    __shared__ float t[32][33];
    const int s0 = blockIdx.x * 32, d0 = blockIdx.y * 32;
    const int bk = blockIdx.z;                 // b*NKV + kvh
    const int tx = threadIdx.x, ty = threadIdx.y;
    const int b = bk / NKV_, kvh = bk % NKV_;
#pragma unroll
    for (int j = 0; j < 32; j += 8)
        t[ty + j][tx] = V[((size_t)((b * S_ + s0 + ty + j) * NKV_ + kvh)) * D_ + d0 + tx];
    __syncthreads();
#pragma unroll
    for (int j = 0; j < 32; j += 8)
        Vt[((size_t)(bk * D_ + d0 + ty + j)) * S_ + s0 + tx] = __float2half_rn(t[tx][ty + j]);
}

// ---------------- mma helper --------------------------------------------------
__device__ __forceinline__ void mma_f16(float* c, const uint32_t* a, const uint32_t* b) {
    asm volatile(
        "mma.sync.aligned.m16n8k16.row.col.f32.f16.f16.f32 "
        "{%0,%1,%2,%3}, {%4,%5,%6,%7}, {%8,%9}, {%0,%1,%2,%3};"
        : "+f"(c[0]), "+f"(c[1]), "+f"(c[2]), "+f"(c[3])
        : "r"(a[0]), "r"(a[1]), "r"(a[2]), "r"(a[3]), "r"(b[0]), "r"(b[1]));
}

// ---------------- fp16 mma.sync GEMM: C[M,N] = A[M,K] @ Bt[N,K]^T ------------
#define BM 128
#define BN 128
#define BKH 64
#define TSTRH 72
#define TILE_HALFS (128 * TSTRH)
#define GSM_BYTES (4 * TILE_HALFS * 2)

__device__ __forceinline__ void g2s_cp_h(const __half* __restrict__ G, uint32_t sbase,
                                         int row0, int K, int k0, int tid) {
#pragma unroll
    for (int i = 0; i < 4; i++) {
        int lin = tid + i * 256;
        int r = lin >> 3, c = lin & 7;
        cp16(sbase + (uint32_t)(r * TSTRH + c * 8) * 2u,
             G + (size_t)(row0 + r) * K + k0 + c * 8);
    }
}

__global__ __launch_bounds__(256) void tc_gemm(const __half* __restrict__ A,
                                               const __half* __restrict__ Bt,
                                               float* __restrict__ C,
                                               int M, int N, int K) {
    extern __shared__ __half smh[];
    __half* As[2] = {smh, smh + 2 * TILE_HALFS};
    __half* Bs[2] = {smh + TILE_HALFS, smh + 3 * TILE_HALFS};
    const uint32_t asu[2] = {smem_u32(As[0]), smem_u32(As[1])};
    const uint32_t bsu[2] = {smem_u32(Bs[0]), smem_u32(Bs[1])};

    const int tid = threadIdx.x;
    const int lane = tid & 31, wid = tid >> 5;
    const int warpM = wid & 3;
    const int warpN = wid >> 2;
    const int ty8 = lane >> 2;
    const int tx4 = lane & 3;
    const int bm = blockIdx.y * BM, bn = blockIdx.x * BN;

    float acc[2][8][4];
#pragma unroll
    for (int mi = 0; mi < 2; mi++)
#pragma unroll
        for (int ni = 0; ni < 8; ni++)
#pragma unroll
            for (int r = 0; r < 4; r++) acc[mi][ni][r] = 0.f;

    g2s_cp_h(A, asu[0], bm, K, 0, tid);
    g2s_cp_h(Bt, bsu[0], bn, K, 0, tid);
    CP_COMMIT();

    const int NK = K / BKH;
    for (int kt = 0; kt < NK; kt++) {
        const int buf = kt & 1;
        if (kt + 1 < NK) {
            g2s_cp_h(A, asu[buf ^ 1], bm, K, (kt + 1) * BKH, tid);
            g2s_cp_h(Bt, bsu[buf ^ 1], bn, K, (kt + 1) * BKH, tid);
            CP_COMMIT();
            CP_WAIT(1);
        } else {
            CP_WAIT(0);
        }
        __syncthreads();

        const __half* Ab = As[buf];
        const __half* Bb = Bs[buf];
#pragma unroll
        for (int ks = 0; ks < 4; ks++) {
            const int k16 = ks * 16;
            uint32_t af[2][4];
#pragma unroll
            for (int mi = 0; mi < 2; mi++) {
                const int rb = warpM * 32 + mi * 16 + ty8;
                af[mi][0] = *(const uint32_t*)&Ab[(rb) * TSTRH + k16 + 2 * tx4];
                af[mi][1] = *(const uint32_t*)&Ab[(rb + 8) * TSTRH + k16 + 2 * tx4];
                af[mi][2] = *(const uint32_t*)&Ab[(rb) * TSTRH + k16 + 2 * tx4 + 8];
                af[mi][3] = *(const uint32_t*)&Ab[(rb + 8) * TSTRH + k16 + 2 * tx4 + 8];
            }
            uint32_t bf[8][2];
#pragma unroll
            for (int ni = 0; ni < 8; ni++) {
                const int nc = warpN * 64 + ni * 8 + ty8;
                bf[ni][0] = *(const uint32_t*)&Bb[nc * TSTRH + k16 + 2 * tx4];
                bf[ni][1] = *(const uint32_t*)&Bb[nc * TSTRH + k16 + 2 * tx4 + 8];
            }
#pragma unroll
            for (int mi = 0; mi < 2; mi++)
#pragma unroll
                for (int ni = 0; ni < 8; ni++)
                    mma_f16(acc[mi][ni], af[mi], bf[ni]);
        }
        __syncthreads();
    }

#pragma unroll
    for (int mi = 0; mi < 2; mi++) {
        const int r0 = bm + warpM * 32 + mi * 16 + ty8;
#pragma unroll
        for (int ni = 0; ni < 8; ni++) {
            const int cc = bn + warpN * 64 + ni * 8 + 2 * tx4;
            *(float2*)(C + (size_t)r0 * N + cc)       = make_float2(acc[mi][ni][0], acc[mi][ni][1]);
            *(float2*)(C + (size_t)(r0 + 8) * N + cc) = make_float2(acc[mi][ni][2], acc[mi][ni][3]);
        }
    }
}

// ---------------- flash attention: all-fp16 MMA, cp.async double-buffered ----
// Q-tile 128 rows, K-tile 64 cols, 8 warps (warp = 16 q-rows).
// Stage (per kt): Kh[64][136]h | Kl[64][136]h | Vt[128][72]h. Two stages + P[128][72]h.
#define QS_STR  136
#define KH_STR  136
#define VT_STR  72
#define PST     72
#define KH_BYTES (64 * KH_STR * 2)       // 17408
#define VT_BYTES (128 * VT_STR * 2)      // 18432
#define STG_BYTES (2 * KH_BYTES + VT_BYTES)  // 53248
#define OFF_P_B (2 * STG_BYTES)          // 106496
#define FL_SMEM_BYTES (OFF_P_B + 128 * PST * 2)  // 124928

__device__ __forceinline__ void flash_stage(const __half* __restrict__ Khh,
                                            const __half* __restrict__ Khl,
                                            const __half* __restrict__ Vt,
                                            uint32_t sb, int b, int kvh,
                                            int kbase, int tid) {
#pragma unroll
    for (int i = 0; i < 4; i++) {        // Kh: 64 rows x 16 chunks
        int lin = tid + i * 256;
        int r = lin >> 4, c = lin & 15;
        size_t gofs = ((size_t)((b * S_ + kbase + r) * NKV_ + kvh)) * D_ + c * 8;
        cp16(sb + (uint32_t)(r * KH_STR + c * 8) * 2u, Khh + gofs);
        cp16(sb + KH_BYTES + (uint32_t)(r * KH_STR + c * 8) * 2u, Khl + gofs);
    }
#pragma unroll
    for (int i = 0; i < 4; i++) {        // Vt: 128 rows x 8 chunks
        int lin = tid + i * 256;
        int r = lin >> 3, c = lin & 7;
        cp16(sb + 2 * KH_BYTES + (uint32_t)(r * VT_STR + c * 8) * 2u,
             Vt + ((size_t)((b * NKV_ + kvh) * D_ + r)) * S_ + kbase + c * 8);
    }
}

__global__ __launch_bounds__(256) void flash_mma_kernel(
    const float* __restrict__ Qg, const __half* __restrict__ Khh,
    const __half* __restrict__ Khl, const __half* __restrict__ Vt,
    const float* __restrict__ cosc, const float* __restrict__ sinc,
    __half* __restrict__ Og) {
    extern __shared__ char smc[];
    const uint32_t smb = smem_u32(smc);
    __half* Ps = (__half*)(smc + OFF_P_B);
    __half* Qstage = (__half*)smc;       // 128*136 halves = 34816 B (inside stage 0)

    const int tid = threadIdx.x;
    const int lane = tid & 31, wid = tid >> 5;
    const int ty8 = lane >> 2;
    const int tx4 = lane & 3;
    const int qt = blockIdx.x;
    const int h  = blockIdx.y;
    const int b  = blockIdx.z;
    const int kvh = h >> 2;
    const int qbase = qt * 128;
    const int wrow = wid * 16;
    const float scale = 0.08838834764831845f;

    // ---- stage Q: fused RoPE + scale + fp16 round ----
#pragma unroll
    for (int i = 0; i < 8; i++) {
        int lin = i * 256 + tid;
        int r = lin >> 4;
        int c4 = (lin & 15) << 2;
        const int sg = qbase + r;
        const float* qrow = Qg + ((size_t)((b * S_ + sg) * NH_ + h)) * D_;
        float4 x1 = *(const float4*)(qrow + c4);
        float4 x2 = *(const float4*)(qrow + c4 + 64);
        float4 c0 = *(const float4*)(cosc + sg * D_ + c4);
        float4 s0 = *(const float4*)(sinc + sg * D_ + c4);
        float4 c1 = *(const float4*)(cosc + sg * D_ + c4 + 64);
        float4 s1 = *(const float4*)(sinc + sg * D_ + c4 + 64);
        float o1[4], o2[4];
        o1[0] = x1.x * c0.x - x2.x * s0.x;  o2[0] = x2.x * c1.x + x1.x * s1.x;
        o1[1] = x1.y * c0.y - x2.y * s0.y;  o2[1] = x2.y * c1.y + x1.y * s1.y;
        o1[2] = x1.z * c0.z - x2.z * s0.z;  o2[2] = x2.z * c1.z + x1.z * s1.z;
        o1[3] = x1.w * c0.w - x2.w * s0.w;  o2[3] = x2.w * c1.w + x1.w * s1.w;
#pragma unroll
        for (int j = 0; j < 4; j++) {
            Qstage[r * QS_STR + c4 + j]      = __float2half_rn(o1[j] * scale);
            Qstage[r * QS_STR + c4 + 64 + j] = __float2half_rn(o2[j] * scale);
        }
    }
    __syncthreads();

    // ---- Q fragments: 8 k16-steps x 4 regs ----
    uint32_t qf[8][4];
#pragma unroll
    for (int ks = 0; ks < 8; ks++) {
        const int k16 = ks * 16;
        qf[ks][0] = *(const uint32_t*)&Qstage[(wrow + ty8) * QS_STR + k16 + 2 * tx4];
        qf[ks][1] = *(const uint32_t*)&Qstage[(wrow + ty8 + 8) * QS_STR + k16 + 2 * tx4];
        qf[ks][2] = *(const uint32_t*)&Qstage[(wrow + ty8) * QS_STR + k16 + 2 * tx4 + 8];
        qf[ks][3] = *(const uint32_t*)&Qstage[(wrow + ty8 + 8) * QS_STR + k16 + 2 * tx4 + 8];
    }
    __syncthreads();   // Qstage (stage-0 region) now reusable

    float m_i[2] = {-1e30f, -1e30f};
    float l_i[2] = {0.f, 0.f};
    float oacc[16][4];
#pragma unroll
    for (int ni = 0; ni < 16; ni++)
#pragma unroll
        for (int r = 0; r < 4; r++) oacc[ni][r] = 0.f;

    const int NKT = 2 * qt + 2;
    flash_stage(Khh, Khl, Vt, smb, b, kvh, 0, tid);
    CP_COMMIT();

    for (int kt = 0; kt < NKT; kt++) {
        const int kbase = kt * 64;
        const int buf = kt & 1;
        if (kt + 1 < NKT) {
            flash_stage(Khh, Khl, Vt, smb + (buf ^ 1) * STG_BYTES, b, kvh, kbase + 64, tid);
            CP_COMMIT();
            CP_WAIT(1);
        } else {
            CP_WAIT(0);
        }
        __syncthreads();

        const __half* Kh = (const __half*)(smc + buf * STG_BYTES);
        const __half* Kl = (const __half*)(smc + buf * STG_BYTES + KH_BYTES);
        const __half* Vs = (const __half*)(smc + buf * STG_BYTES + 2 * KH_BYTES);

        // ---- QK^T: sc = Q*Khi + Q*Klo ----
        float sc[8][4];
#pragma unroll
        for (int ni = 0; ni < 8; ni++)
#pragma unroll
            for (int r = 0; r < 4; r++) sc[ni][r] = 0.f;

#pragma unroll
        for (int ks = 0; ks < 8; ks++) {
            const int k16 = ks * 16;
#pragma unroll
            for (int ni = 0; ni < 8; ni++) {
                const int n = ni * 8 + ty8;
                uint32_t bh[2], bl[2];
                bh[0] = *(const uint32_t*)&Kh[n * KH_STR + k16 + 2 * tx4];
                bh[1] = *(const uint32_t*)&Kh[n * KH_STR + k16 + 2 * tx4 + 8];
                bl[0] = *(const uint32_t*)&Kl[n * KH_STR + k16 + 2 * tx4];
                bl[1] = *(const uint32_t*)&Kl[n * KH_STR + k16 + 2 * tx4 + 8];
                mma_f16(sc[ni], qf[ks], bh);
                mma_f16(sc[ni], qf[ks], bl);
            }
        }

        // ---- causal mask ----
        if (kbase + 63 > qbase) {
#pragma unroll
            for (int ni = 0; ni < 8; ni++) {
#pragma unroll
                for (int r = 0; r < 4; r++) {
                    int row = qbase + wrow + ty8 + ((r >= 2) ? 8 : 0);
                    int col = kbase + ni * 8 + 2 * tx4 + (r & 1);
                    if (col > row) sc[ni][r] = -1e30f;
                }
            }
        }

        // ---- online softmax ----
#pragma unroll
        for (int rh = 0; rh < 2; rh++) {
            const int i0 = rh * 2, i1 = rh * 2 + 1;
            float mloc = -1e30f;
#pragma unroll
            for (int ni = 0; ni < 8; ni++)
                mloc = fmaxf(mloc, fmaxf(sc[ni][i0], sc[ni][i1]));
            mloc = fmaxf(mloc, __shfl_xor_sync(0xffffffffu, mloc, 1));
            mloc = fmaxf(mloc, __shfl_xor_sync(0xffffffffu, mloc, 2));
            const float mnew = fmaxf(m_i[rh], mloc);
            const float fac = __expf(m_i[rh] - mnew);
            m_i[rh] = mnew;
            float rsum = 0.f;
#pragma unroll
            for (int ni = 0; ni < 8; ni++) {
                float p0 = __expf(sc[ni][i0] - mnew);
                float p1 = __expf(sc[ni][i1] - mnew);
                sc[ni][i0] = p0; sc[ni][i1] = p1;
                rsum += p0 + p1;
            }
            rsum += __shfl_xor_sync(0xffffffffu, rsum, 1);
            rsum += __shfl_xor_sync(0xffffffffu, rsum, 2);
            l_i[rh] = l_i[rh] * fac + rsum;
#pragma unroll
            for (int ni = 0; ni < 16; ni++) {
                oacc[ni][i0] *= fac;
                oacc[ni][i1] *= fac;
            }
        }

        // ---- P to smem as fp16 (warp-private rows) ----
#pragma unroll
        for (int ni = 0; ni < 8; ni++) {
            const int cc = ni * 8 + 2 * tx4;
            *(__half2*)&Ps[(wrow + ty8) * PST + cc] =
                __floats2half2_rn(sc[ni][0], sc[ni][1]);
            *(__half2*)&Ps[(wrow + ty8 + 8) * PST + cc] =
                __floats2half2_rn(sc[ni][2], sc[ni][3]);
        }
        __syncwarp();

        // ---- PV (fp16 m16n8k16): oacc += P @ V ----
#pragma unroll
        for (int ks = 0; ks < 4; ks++) {
            const int k16 = ks * 16;
            uint32_t af[4];
            af[0] = *(const uint32_t*)&Ps[(wrow + ty8) * PST + k16 + 2 * tx4];
            af[1] = *(const uint32_t*)&Ps[(wrow + ty8 + 8) * PST + k16 + 2 * tx4];
            af[2] = *(const uint32_t*)&Ps[(wrow + ty8) * PST + k16 + 2 * tx4 + 8];
            af[3] = *(const uint32_t*)&Ps[(wrow + ty8 + 8) * PST + k16 + 2 * tx4 + 8];
#pragma unroll
            for (int ni = 0; ni < 16; ni++) {
                const int nd = ni * 8 + ty8;     // d-column
                uint32_t bf[2];
                bf[0] = *(const uint32_t*)&Vs[nd * VT_STR + k16 + 2 * tx4];
                bf[1] = *(const uint32_t*)&Vs[nd * VT_STR + k16 + 2 * tx4 + 8];
                mma_f16(oacc[ni], af, bf);
            }
        }
        __syncthreads();
    }

    // ---- epilogue: normalize, fp16 round (feeds O-proj), store ----
    const float inv0 = 1.0f / l_i[0];
    const float inv1 = 1.0f / l_i[1];
    const int r0 = qbase + wrow + ty8;
#pragma unroll
    for (int ni = 0; ni < 16; ni++) {
        const int cc = ni * 8 + 2 * tx4;
        __half* p0 = Og + ((size_t)((b * S_ + r0) * NH_ + h)) * D_ + cc;
        __half* p1 = Og + ((size_t)((b * S_ + r0 + 8) * NH_ + h)) * D_ + cc;
        *(__half2*)p0 = __floats2half2_rn(oacc[ni][0] * inv0, oacc[ni][1] * inv0);
        *(__half2*)p1 = __floats2half2_rn(oacc[ni][2] * inv1, oacc[ni][3] * inv1);
    }
}

// ---------------- launch ----------------------------------------------------
extern "C" void kernel_launch(void* const* d_in, const int* in_sizes, int n_in,
                              void* d_out, int out_size) {
    const float* X    = (const float*)d_in[0];
    const float* Wq   = (const float*)d_in[1];
    const float* Wk   = (const float*)d_in[2];
    const float* Wv   = (const float*)d_in[3];
    const float* Wo   = (const float*)d_in[4];
    const float* cosc = (const float*)d_in[5];
    const float* sinc = (const float*)d_in[6];
    float* out = (float*)d_out;

    float *Qp, *Kp, *Vp;
    __half *Khh, *Khl, *Vt, *Ah, *Xh, *Wqt, *Wkt, *Wvt, *Wot;
    cudaGetSymbolAddress((void**)&Qp, g_Q);
    cudaGetSymbolAddress((void**)&Kp, g_K);
    cudaGetSymbolAddress((void**)&Vp, g_V);
    cudaGetSymbolAddress((void**)&Khh, g_Khh);
    cudaGetSymbolAddress((void**)&Khl, g_Khl);
    cudaGetSymbolAddress((void**)&Vt, g_Vt);
    cudaGetSymbolAddress((void**)&Ah, g_Ah);
    cudaGetSymbolAddress((void**)&Xh, g_Xh);
    cudaGetSymbolAddress((void**)&Wqt, g_Wqt);
    cudaGetSymbolAddress((void**)&Wkt, g_Wkt);
    cudaGetSymbolAddress((void**)&Wvt, g_Wvt);
    cudaGetSymbolAddress((void**)&Wot, g_Wot);

    const int M = B_ * S_;          // 4096
    const int NQ = NH_ * D_;        // 4096
    const int NKVD = NKV_ * D_;     // 1024

    // Pre-pass: X -> fp16; weights -> transposed fp16 [N,K]
    {
        int n4 = M * HID_ / 4;
        cvt_half_kernel<<<(n4 + 255) / 256, 256>>>(X, Xh, n4);
        dim3 blk(32, 8);
        transpose_half_kernel<<<dim3(NQ / 32, HID_ / 32), blk>>>(Wq, Wqt, HID_, NQ);
        transpose_half_kernel<<<dim3(NKVD / 32, HID_ / 32), blk>>>(Wk, Wkt, HID_, NKVD);
        transpose_half_kernel<<<dim3(NKVD / 32, HID_ / 32), blk>>>(Wv, Wvt, HID_, NKVD);
        transpose_half_kernel<<<dim3(HID_ / 32, NQ / 32), blk>>>(Wo, Wot, NQ, HID_);
    }

    cudaFuncSetAttribute(tc_gemm, cudaFuncAttributeMaxDynamicSharedMemorySize, GSM_BYTES);

    // Projections (fp16 mma, cp.async pipeline)
    tc_gemm<<<dim3(NQ / BN, M / BM), 256, GSM_BYTES>>>(Xh, Wqt, Qp, M, NQ, HID_);
    tc_gemm<<<dim3(NKVD / BN, M / BM), 256, GSM_BYTES>>>(Xh, Wkt, Kp, M, NKVD, HID_);
    tc_gemm<<<dim3(NKVD / BN, M / BM), 256, GSM_BYTES>>>(Xh, Wvt, Vp, M, NKVD, HID_);

    // K RoPE -> fp16 hi/lo; V -> fp16 transposed
    rope_khl_kernel<<<(M * NKV_ * 16) / 256, 256>>>(Kp, Khh, Khl, cosc, sinc);
    {
        dim3 blk(32, 8);
        vt_transpose_kernel<<<dim3(S_ / 32, D_ / 32, B_ * NKV_), blk>>>(Vp, Vt);
    }

    // Flash attention (all-fp16 MMA, cp.async double-buffered staging)
    cudaFuncSetAttribute(flash_mma_kernel, cudaFuncAttributeMaxDynamicSharedMemorySize, FL_SMEM_BYTES);
    flash_mma_kernel<<<dim3(S_ / 128, NH_, B_), 256, FL_SMEM_BYTES>>>(
        Qp, Khh, Khl, Vt, cosc, sinc, Ah);

    // Output projection (fp16 A from flash epilogue)
    tc_gemm<<<dim3(HID_ / BN, M / BM), 256, GSM_BYTES>>>(Ah, Wot, out, M, HID_, NQ);
}

// round 11
// speedup vs baseline: 2.4106x; 1.0563x over previous
#include <cuda_runtime.h>
#include <cuda_fp16.h>
#include <cstdint>

// Problem constants
#define B_    2
#define S_    2048
#define HID_  4096
#define NH_   32
#define NKV_  8
#define D_    128
#define NQKV  (NH_ * D_ + 2 * NKV_ * D_)   // 6144

// ---------------- scratch (__device__ globals; allocation-free) -------------
__device__ float  g_QKV[(size_t)B_ * S_ * NQKV];       // fused QKV proj out (fp32)
__device__ __half g_Kh[(size_t)B_ * S_ * NKV_ * D_];   // roped K (fp16)
__device__ __half g_Vt[(size_t)B_ * NKV_ * D_ * S_];   // V transposed [b,kvh,d,s] fp16
__device__ __half g_Ah[(size_t)B_ * S_ * NH_ * D_];    // attn out (fp16)
__device__ __half g_Xh[(size_t)B_ * S_ * HID_];        // fp16 hidden states
__device__ __half g_Wqkvt[(size_t)NQKV * HID_];        // [6144, HID] transposed fp16
__device__ __half g_Wot[(size_t)HID_ * (NH_ * D_)];

__device__ __forceinline__ uint32_t smem_u32(const void* p) {
    uint32_t a;
    asm("{ .reg .u64 t; cvta.to.shared.u64 t, %1; cvt.u32.u64 %0, t; }" : "=r"(a) : "l"(p));
    return a;
}
__device__ __forceinline__ void cp16(uint32_t saddr, const void* g) {
    asm volatile("cp.async.cg.shared.global [%0], [%1], 16;" :: "r"(saddr), "l"(g));
}
#define CP_COMMIT() asm volatile("cp.async.commit_group;" ::: "memory")
#define CP_WAIT(n)  asm volatile("cp.async.wait_group %0;" :: "n"(n) : "memory")

// ---------------- pre-pass kernels ------------------------------------------
__global__ void cvt_half_kernel(const float* __restrict__ in, __half* __restrict__ out, int n4) {
    int i = blockIdx.x * blockDim.x + threadIdx.x;
    if (i < n4) {
        float4 v = ((const float4*)in)[i];
        ((__half2*)out)[i * 2]     = __floats2half2_rn(v.x, v.y);
        ((__half2*)out)[i * 2 + 1] = __floats2half2_rn(v.z, v.w);
    }
}
__global__ void transpose_half_kernel(const float* __restrict__ W, __half* __restrict__ Wt,
                                      int K, int N) {
    __shared__ float t[32][33];
    const int n0 = blockIdx.x * 32, k0 = blockIdx.y * 32;
    const int tx = threadIdx.x, ty = threadIdx.y;
#pragma unroll
    for (int j = 0; j < 32; j += 8)
        t[ty + j][tx] = W[(size_t)(k0 + ty + j) * N + n0 + tx];
    __syncthreads();
#pragma unroll
    for (int j = 0; j < 32; j += 8)
        Wt[(size_t)(n0 + ty + j) * K + k0 + tx] = __float2half_rn(t[tx][ty + j]);
}
// K RoPE -> single fp16 (reads K slice of fused QKV)
__global__ __launch_bounds__(256) void rope_kh_kernel(const float* __restrict__ QKV,
                                                      __half* __restrict__ Kh,
                                                      const float* __restrict__ cosc,
                                                      const float* __restrict__ sinc) {
    const int idx = blockIdx.x * 256 + threadIdx.x;
    const int r = idx >> 4;                       // row over (b*S+s)*NKV+kvh
    const int c4 = (idx & 15) << 2;
    const int bs = r / NKV_, kvh = r % NKV_;
    const int s = bs % S_;
    const float* row = QKV + (size_t)bs * NQKV + NH_ * D_ + kvh * D_;
    float4 x1 = *(const float4*)(row + c4);
    float4 x2 = *(const float4*)(row + c4 + 64);
    float4 c0 = *(const float4*)(cosc + s * D_ + c4);
    float4 s0 = *(const float4*)(sinc + s * D_ + c4);
    float4 c1 = *(const float4*)(cosc + s * D_ + c4 + 64);
    float4 s1 = *(const float4*)(sinc + s * D_ + c4 + 64);
    float o1[4], o2[4];
    o1[0] = x1.x * c0.x - x2.x * s0.x;  o2[0] = x2.x * c1.x + x1.x * s1.x;
    o1[1] = x1.y * c0.y - x2.y * s0.y;  o2[1] = x2.y * c1.y + x1.y * s1.y;
    o1[2] = x1.z * c0.z - x2.z * s0.z;  o2[2] = x2.z * c1.z + x1.z * s1.z;
    o1[3] = x1.w * c0.w - x2.w * s0.w;  o2[3] = x2.w * c1.w + x1.w * s1.w;
    __half* ph = Kh + (size_t)r * D_;
    *(__half2*)(ph + c4)     = __floats2half2_rn(o1[0], o1[1]);
    *(__half2*)(ph + c4 + 2) = __floats2half2_rn(o1[2], o1[3]);
    *(__half2*)(ph + c4 + 64)     = __floats2half2_rn(o2[0], o2[1]);
    *(__half2*)(ph + c4 + 64 + 2) = __floats2half2_rn(o2[2], o2[3]);
}
// V slice of QKV [b,s,kvh,d] fp32 -> Vt [b,kvh,d,s] fp16
__global__ void vt_transpose_kernel(const float* __restrict__ QKV, __half* __restrict__ Vt) {
    __shared__ float t[32][33];
    const int s0 = blockIdx.x * 32, d0 = blockIdx.y * 32;
    const int bk = blockIdx.z;                 // b*NKV + kvh
    const int tx = threadIdx.x, ty = threadIdx.y;
    const int b = bk / NKV_, kvh = bk % NKV_;
#pragma unroll
    for (int j = 0; j < 32; j += 8)
        t[ty + j][tx] = QKV[(size_t)(b * S_ + s0 + ty + j) * NQKV +
                            (NH_ + NKV_) * D_ + kvh * D_ + d0 + tx];
    __syncthreads();
#pragma unroll
    for (int j = 0; j < 32; j += 8)
        Vt[((size_t)(bk * D_ + d0 + ty + j)) * S_ + s0 + tx] = __float2half_rn(t[tx][ty + j]);
}

// ---------------- mma helper --------------------------------------------------
__device__ __forceinline__ void mma_f16(float* c, const uint32_t* a, const uint32_t* b) {
    asm volatile(
        "mma.sync.aligned.m16n8k16.row.col.f32.f16.f16.f32 "
        "{%0,%1,%2,%3}, {%4,%5,%6,%7}, {%8,%9}, {%0,%1,%2,%3};"
        : "+f"(c[0]), "+f"(c[1]), "+f"(c[2]), "+f"(c[3])
        : "r"(a[0]), "r"(a[1]), "r"(a[2]), "r"(a[3]), "r"(b[0]), "r"(b[1]));
}

// ---------------- fp16 mma.sync GEMM: C[M,N] = A[M,K] @ Bt[N,K]^T ------------
#define BM 128
#define BN 128
#define BKH 64
#define TSTRH 72
#define TILE_HALFS (128 * TSTRH)
#define GSM_BYTES (4 * TILE_HALFS * 2)

__device__ __forceinline__ void g2s_cp_h(const __half* __restrict__ G, uint32_t sbase,
                                         int row0, int K, int k0, int tid) {
#pragma unroll
    for (int i = 0; i < 4; i++) {
        int lin = tid + i * 256;
        int r = lin >> 3, c = lin & 7;
        cp16(sbase + (uint32_t)(r * TSTRH + c * 8) * 2u,
             G + (size_t)(row0 + r) * K + k0 + c * 8);
    }
}

__global__ __launch_bounds__(256) void tc_gemm(const __half* __restrict__ A,
                                               const __half* __restrict__ Bt,
                                               float* __restrict__ C,
                                               int M, int N, int K) {
    extern __shared__ __half smh[];
    __half* As[2] = {smh, smh + 2 * TILE_HALFS};
    __half* Bs[2] = {smh + TILE_HALFS, smh + 3 * TILE_HALFS};
    const uint32_t asu[2] = {smem_u32(As[0]), smem_u32(As[1])};
    const uint32_t bsu[2] = {smem_u32(Bs[0]), smem_u32(Bs[1])};

    const int tid = threadIdx.x;
    const int lane = tid & 31, wid = tid >> 5;
    const int warpM = wid & 3;
    const int warpN = wid >> 2;
    const int ty8 = lane >> 2;
    const int tx4 = lane & 3;
    const int bm = blockIdx.y * BM, bn = blockIdx.x * BN;

    float acc[2][8][4];
#pragma unroll
    for (int mi = 0; mi < 2; mi++)
#pragma unroll
        for (int ni = 0; ni < 8; ni++)
#pragma unroll
            for (int r = 0; r < 4; r++) acc[mi][ni][r] = 0.f;

    g2s_cp_h(A, asu[0], bm, K, 0, tid);
    g2s_cp_h(Bt, bsu[0], bn, K, 0, tid);
    CP_COMMIT();

    const int NK = K / BKH;
    for (int kt = 0; kt < NK; kt++) {
        const int buf = kt & 1;
        if (kt + 1 < NK) {
            g2s_cp_h(A, asu[buf ^ 1], bm, K, (kt + 1) * BKH, tid);
            g2s_cp_h(Bt, bsu[buf ^ 1], bn, K, (kt + 1) * BKH, tid);
            CP_COMMIT();
            CP_WAIT(1);
        } else {
            CP_WAIT(0);
        }
        __syncthreads();

        const __half* Ab = As[buf];
        const __half* Bb = Bs[buf];
#pragma unroll
        for (int ks = 0; ks < 4; ks++) {
            const int k16 = ks * 16;
            uint32_t af[2][4];
#pragma unroll
            for (int mi = 0; mi < 2; mi++) {
                const int rb = warpM * 32 + mi * 16 + ty8;
                af[mi][0] = *(const uint32_t*)&Ab[(rb) * TSTRH + k16 + 2 * tx4];
                af[mi][1] = *(const uint32_t*)&Ab[(rb + 8) * TSTRH + k16 + 2 * tx4];
                af[mi][2] = *(const uint32_t*)&Ab[(rb) * TSTRH + k16 + 2 * tx4 + 8];
                af[mi][3] = *(const uint32_t*)&Ab[(rb + 8) * TSTRH + k16 + 2 * tx4 + 8];
            }
            uint32_t bf[8][2];
#pragma unroll
            for (int ni = 0; ni < 8; ni++) {
                const int nc = warpN * 64 + ni * 8 + ty8;
                bf[ni][0] = *(const uint32_t*)&Bb[nc * TSTRH + k16 + 2 * tx4];
                bf[ni][1] = *(const uint32_t*)&Bb[nc * TSTRH + k16 + 2 * tx4 + 8];
            }
#pragma unroll
            for (int mi = 0; mi < 2; mi++)
#pragma unroll
                for (int ni = 0; ni < 8; ni++)
                    mma_f16(acc[mi][ni], af[mi], bf[ni]);
        }
        __syncthreads();
    }

#pragma unroll
    for (int mi = 0; mi < 2; mi++) {
        const int r0 = bm + warpM * 32 + mi * 16 + ty8;
#pragma unroll
        for (int ni = 0; ni < 8; ni++) {
            const int cc = bn + warpN * 64 + ni * 8 + 2 * tx4;
            *(float2*)(C + (size_t)r0 * N + cc)       = make_float2(acc[mi][ni][0], acc[mi][ni][1]);
            *(float2*)(C + (size_t)(r0 + 8) * N + cc) = make_float2(acc[mi][ni][2], acc[mi][ni][3]);
        }
    }
}

// ---------------- flash attention: fp16 MMA, single-K, 2 CTAs/SM -------------
// Q-tile 128 rows, K-tile 64 cols, 8 warps (warp = 16 q-rows).
// Stage (per kt): Kh[64][136]h | Vt[128][72]h. Two stages + P[128][72]h.
#define QS_STR  136
#define KH_STR  136
#define VT_STR  72
#define PST     72
#define KH_BYTES (64 * KH_STR * 2)           // 17408
#define VT_BYTES (128 * VT_STR * 2)          // 18432
#define STG_BYTES (KH_BYTES + VT_BYTES)      // 35840
#define OFF_P_B (2 * STG_BYTES)              // 71680
#define FL_SMEM_BYTES (OFF_P_B + 128 * PST * 2)  // 90112

__device__ __forceinline__ void flash_stage(const __half* __restrict__ Khg,
                                            const __half* __restrict__ Vt,
                                            uint32_t sb, int b, int kvh,
                                            int kbase, int tid) {
#pragma unroll
    for (int i = 0; i < 4; i++) {        // Kh: 64 rows x 16 chunks
        int lin = tid + i * 256;
        int r = lin >> 4, c = lin & 15;
        cp16(sb + (uint32_t)(r * KH_STR + c * 8) * 2u,
             Khg + ((size_t)((b * S_ + kbase + r) * NKV_ + kvh)) * D_ + c * 8);
    }
#pragma unroll
    for (int i = 0; i < 4; i++) {        // Vt: 128 rows x 8 chunks
        int lin = tid + i * 256;
        int r = lin >> 3, c = lin & 7;
        cp16(sb + KH_BYTES + (uint32_t)(r * VT_STR + c * 8) * 2u,
             Vt + ((size_t)((b * NKV_ + kvh) * D_ + r)) * S_ + kbase + c * 8);
    }
}

__global__ __launch_bounds__(256) void flash_mma_kernel(
    const float* __restrict__ QKV, const __half* __restrict__ Khg,
    const __half* __restrict__ Vt, const float* __restrict__ cosc,
    const float* __restrict__ sinc, __half* __restrict__ Og) {
    extern __shared__ char smc[];
    const uint32_t smb = smem_u32(smc);
    __half* Ps = (__half*)(smc + OFF_P_B);
    __half* Qstage = (__half*)smc;       // 128*136 halves = 34816 B (fits in stage 0)

    const int tid = threadIdx.x;
    const int lane = tid & 31, wid = tid >> 5;
    const int ty8 = lane >> 2;
    const int tx4 = lane & 3;
    const int qt = blockIdx.x;
    const int h  = blockIdx.y;
    const int b  = blockIdx.z;
    const int kvh = h >> 2;
    const int qbase = qt * 128;
    const int wrow = wid * 16;
    const float scale = 0.08838834764831845f;

    // ---- stage Q: fused RoPE + scale + fp16 round (Q slice of QKV) ----
#pragma unroll
    for (int i = 0; i < 8; i++) {
        int lin = i * 256 + tid;
        int r = lin >> 4;
        int c4 = (lin & 15) << 2;
        const int sg = qbase + r;
        const float* qrow = QKV + (size_t)(b * S_ + sg) * NQKV + h * D_;
        float4 x1 = *(const float4*)(qrow + c4);
        float4 x2 = *(const float4*)(qrow + c4 + 64);
        float4 c0 = *(const float4*)(cosc + sg * D_ + c4);
        float4 s0 = *(const float4*)(sinc + sg * D_ + c4);
        float4 c1 = *(const float4*)(cosc + sg * D_ + c4 + 64);
        float4 s1 = *(const float4*)(sinc + sg * D_ + c4 + 64);
        float o1[4], o2[4];
        o1[0] = x1.x * c0.x - x2.x * s0.x;  o2[0] = x2.x * c1.x + x1.x * s1.x;
        o1[1] = x1.y * c0.y - x2.y * s0.y;  o2[1] = x2.y * c1.y + x1.y * s1.y;
        o1[2] = x1.z * c0.z - x2.z * s0.z;  o2[2] = x2.z * c1.z + x1.z * s1.z;
        o1[3] = x1.w * c0.w - x2.w * s0.w;  o2[3] = x2.w * c1.w + x1.w * s1.w;
#pragma unroll
        for (int j = 0; j < 4; j++) {
            Qstage[r * QS_STR + c4 + j]      = __float2half_rn(o1[j] * scale);
            Qstage[r * QS_STR + c4 + 64 + j] = __float2half_rn(o2[j] * scale);
        }
    }
    __syncthreads();

    // ---- Q fragments: 8 k16-steps x 4 regs ----
    uint32_t qf[8][4];
#pragma unroll
    for (int ks = 0; ks < 8; ks++) {
        const int k16 = ks * 16;
        qf[ks][0] = *(const uint32_t*)&Qstage[(wrow + ty8) * QS_STR + k16 + 2 * tx4];
        qf[ks][1] = *(const uint32_t*)&Qstage[(wrow + ty8 + 8) * QS_STR + k16 + 2 * tx4];
        qf[ks][2] = *(const uint32_t*)&Qstage[(wrow + ty8) * QS_STR + k16 + 2 * tx4 + 8];
        qf[ks][3] = *(const uint32_t*)&Qstage[(wrow + ty8 + 8) * QS_STR + k16 + 2 * tx4 + 8];
    }
    __syncthreads();   // Qstage (stage-0 region) now reusable

    float m_i[2] = {-1e30f, -1e30f};
    float l_i[2] = {0.f, 0.f};
    float oacc[16][4];
#pragma unroll
    for (int ni = 0; ni < 16; ni++)
#pragma unroll
        for (int r = 0; r < 4; r++) oacc[ni][r] = 0.f;

    const int NKT = 2 * qt + 2;
    flash_stage(Khg, Vt, smb, b, kvh, 0, tid);
    CP_COMMIT();

    for (int kt = 0; kt < NKT; kt++) {
        const int kbase = kt * 64;
        const int buf = kt & 1;
        if (kt + 1 < NKT) {
            flash_stage(Khg, Vt, smb + (buf ^ 1) * STG_BYTES, b, kvh, kbase + 64, tid);
            CP_COMMIT();
            CP_WAIT(1);
        } else {
            CP_WAIT(0);
        }
        __syncthreads();

        const __half* Kh = (const __half*)(smc + buf * STG_BYTES);
        const __half* Vs = (const __half*)(smc + buf * STG_BYTES + KH_BYTES);

        // ---- QK^T (fp16, single K) ----
        float sc[8][4];
#pragma unroll
        for (int ni = 0; ni < 8; ni++)
#pragma unroll
            for (int r = 0; r < 4; r++) sc[ni][r] = 0.f;

#pragma unroll
        for (int ks = 0; ks < 8; ks++) {
            const int k16 = ks * 16;
#pragma unroll
            for (int ni = 0; ni < 8; ni++) {
                const int n = ni * 8 + ty8;
                uint32_t bh[2];
                bh[0] = *(const uint32_t*)&Kh[n * KH_STR + k16 + 2 * tx4];
                bh[1] = *(const uint32_t*)&Kh[n * KH_STR + k16 + 2 * tx4 + 8];
                mma_f16(sc[ni], qf[ks], bh);
            }
        }

        // ---- causal mask ----
        if (kbase + 63 > qbase) {
#pragma unroll
            for (int ni = 0; ni < 8; ni++) {
#pragma unroll
                for (int r = 0; r < 4; r++) {
                    int row = qbase + wrow + ty8 + ((r >= 2) ? 8 : 0);
                    int col = kbase + ni * 8 + 2 * tx4 + (r & 1);
                    if (col > row) sc[ni][r] = -1e30f;
                }
            }
        }

        // ---- online softmax ----
#pragma unroll
        for (int rh = 0; rh < 2; rh++) {
            const int i0 = rh * 2, i1 = rh * 2 + 1;
            float mloc = -1e30f;
#pragma unroll
            for (int ni = 0; ni < 8; ni++)
                mloc = fmaxf(mloc, fmaxf(sc[ni][i0], sc[ni][i1]));
            mloc = fmaxf(mloc, __shfl_xor_sync(0xffffffffu, mloc, 1));
            mloc = fmaxf(mloc, __shfl_xor_sync(0xffffffffu, mloc, 2));
            const float mnew = fmaxf(m_i[rh], mloc);
            const float fac = __expf(m_i[rh] - mnew);
            m_i[rh] = mnew;
            float rsum = 0.f;
#pragma unroll
            for (int ni = 0; ni < 8; ni++) {
                float p0 = __expf(sc[ni][i0] - mnew);
                float p1 = __expf(sc[ni][i1] - mnew);
                sc[ni][i0] = p0; sc[ni][i1] = p1;
                rsum += p0 + p1;
            }
            rsum += __shfl_xor_sync(0xffffffffu, rsum, 1);
            rsum += __shfl_xor_sync(0xffffffffu, rsum, 2);
            l_i[rh] = l_i[rh] * fac + rsum;
#pragma unroll
            for (int ni = 0; ni < 16; ni++) {
                oacc[ni][i0] *= fac;
                oacc[ni][i1] *= fac;
            }
        }

        // ---- P to smem as fp16 (warp-private rows) ----
#pragma unroll
        for (int ni = 0; ni < 8; ni++) {
            const int cc = ni * 8 + 2 * tx4;
            *(__half2*)&Ps[(wrow + ty8) * PST + cc] =
                __floats2half2_rn(sc[ni][0], sc[ni][1]);
            *(__half2*)&Ps[(wrow + ty8 + 8) * PST + cc] =
                __floats2half2_rn(sc[ni][2], sc[ni][3]);
        }
        __syncwarp();

        // ---- PV (fp16): oacc += P @ V ----
#pragma unroll
        for (int ks = 0; ks < 4; ks++) {
            const int k16 = ks * 16;
            uint32_t af[4];
            af[0] = *(const uint32_t*)&Ps[(wrow + ty8) * PST + k16 + 2 * tx4];
            af[1] = *(const uint32_t*)&Ps[(wrow + ty8 + 8) * PST + k16 + 2 * tx4];
            af[2] = *(const uint32_t*)&Ps[(wrow + ty8) * PST + k16 + 2 * tx4 + 8];
            af[3] = *(const uint32_t*)&Ps[(wrow + ty8 + 8) * PST + k16 + 2 * tx4 + 8];
#pragma unroll
            for (int ni = 0; ni < 16; ni++) {
                const int nd = ni * 8 + ty8;     // d-column
                uint32_t bf[2];
                bf[0] = *(const uint32_t*)&Vs[nd * VT_STR + k16 + 2 * tx4];
                bf[1] = *(const uint32_t*)&Vs[nd * VT_STR + k16 + 2 * tx4 + 8];
                mma_f16(oacc[ni], af, bf);
            }
        }
        __syncthreads();
    }

    // ---- epilogue: normalize, fp16 round (feeds O-proj), store ----
    const float inv0 = 1.0f / l_i[0];
    const float inv1 = 1.0f / l_i[1];
    const int r0 = qbase + wrow + ty8;
#pragma unroll
    for (int ni = 0; ni < 16; ni++) {
        const int cc = ni * 8 + 2 * tx4;
        __half* p0 = Og + ((size_t)((b * S_ + r0) * NH_ + h)) * D_ + cc;
        __half* p1 = Og + ((size_t)((b * S_ + r0 + 8) * NH_ + h)) * D_ + cc;
        *(__half2*)p0 = __floats2half2_rn(oacc[ni][0] * inv0, oacc[ni][1] * inv0);
        *(__half2*)p1 = __floats2half2_rn(oacc[ni][2] * inv1, oacc[ni][3] * inv1);
    }
}

// ---------------- launch ----------------------------------------------------
extern "C" void kernel_launch(void* const* d_in, const int* in_sizes, int n_in,
                              void* d_out, int out_size) {
    const float* X    = (const float*)d_in[0];
    const float* Wq   = (const float*)d_in[1];
    const float* Wk   = (const float*)d_in[2];
    const float* Wv   = (const float*)d_in[3];
    const float* Wo   = (const float*)d_in[4];
    const float* cosc = (const float*)d_in[5];
    const float* sinc = (const float*)d_in[6];
    float* out = (float*)d_out;

    float *QKVp;
    __half *Khp, *Vtp, *Ah, *Xh, *Wqkvt, *Wot;
    cudaGetSymbolAddress((void**)&QKVp, g_QKV);
    cudaGetSymbolAddress((void**)&Khp, g_Kh);
    cudaGetSymbolAddress((void**)&Vtp, g_Vt);
    cudaGetSymbolAddress((void**)&Ah, g_Ah);
    cudaGetSymbolAddress((void**)&Xh, g_Xh);
    cudaGetSymbolAddress((void**)&Wqkvt, g_Wqkvt);
    cudaGetSymbolAddress((void**)&Wot, g_Wot);

    const int M = B_ * S_;          // 4096
    const int NQ = NH_ * D_;        // 4096
    const int NKVD = NKV_ * D_;     // 1024

    // Pre-pass: X -> fp16; weights -> transposed fp16 slices of one buffer
    {
        int n4 = M * HID_ / 4;
        cvt_half_kernel<<<(n4 + 255) / 256, 256>>>(X, Xh, n4);
        dim3 blk(32, 8);
        transpose_half_kernel<<<dim3(NQ / 32, HID_ / 32), blk>>>(Wq, Wqkvt, HID_, NQ);
        transpose_half_kernel<<<dim3(NKVD / 32, HID_ / 32), blk>>>(
            Wk, Wqkvt + (size_t)NQ * HID_, HID_, NKVD);
        transpose_half_kernel<<<dim3(NKVD / 32, HID_ / 32), blk>>>(
            Wv, Wqkvt + (size_t)(NQ + NKVD) * HID_, HID_, NKVD);
        transpose_half_kernel<<<dim3(HID_ / 32, NQ / 32), blk>>>(Wo, Wot, NQ, HID_);
    }

    cudaFuncSetAttribute(tc_gemm, cudaFuncAttributeMaxDynamicSharedMemorySize, GSM_BYTES);

    // Fused QKV projection (one GEMM, N=6144)
    tc_gemm<<<dim3(NQKV / BN, M / BM), 256, GSM_BYTES>>>(Xh, Wqkvt, QKVp, M, NQKV, HID_);

    // K RoPE -> fp16; V -> fp16 transposed
    rope_kh_kernel<<<(M * NKV_ * 16) / 256, 256>>>(QKVp, Khp, cosc, sinc);
    {
        dim3 blk(32, 8);
        vt_transpose_kernel<<<dim3(S_ / 32, D_ / 32, B_ * NKV_), blk>>>(QKVp, Vtp);
    }

    // Flash attention (fp16 single-K, 2 CTAs/SM)
    cudaFuncSetAttribute(flash_mma_kernel, cudaFuncAttributeMaxDynamicSharedMemorySize, FL_SMEM_BYTES);
    flash_mma_kernel<<<dim3(S_ / 128, NH_, B_), 256, FL_SMEM_BYTES>>>(
        QKVp, Khp, Vtp, cosc, sinc, Ah);

    // Output projection
    tc_gemm<<<dim3(HID_ / BN, M / BM), 256, GSM_BYTES>>>(Ah, Wot, out, M, HID_, NQ);
}

// round 12
// speedup vs baseline: 3.3084x; 1.3725x over previous
#include <cuda_runtime.h>
#include <cuda_fp16.h>
#include <cstdint>

// Problem constants
#define B_    2
#define S_    2048
#define HID_  4096
#define NH_   32
#define NKV_  8
#define D_    128
#define NQKV  (NH_ * D_ + 2 * NKV_ * D_)   // 6144

// ---------------- scratch (__device__ globals; allocation-free) -------------
__device__ float  g_QKV[(size_t)B_ * S_ * NQKV];       // fused QKV proj out (fp32)
__device__ __half g_Kh[(size_t)B_ * S_ * NKV_ * D_];   // roped K (fp16)
__device__ __half g_Vt[(size_t)B_ * NKV_ * D_ * S_];   // V transposed [b,kvh,d,s] fp16
__device__ __half g_Ah[(size_t)B_ * S_ * NH_ * D_];    // attn out (fp16)
__device__ __half g_Xh[(size_t)B_ * S_ * HID_];        // fp16 hidden states
__device__ __half g_Wqkvt[(size_t)NQKV * HID_];        // [6144, HID] transposed fp16
__device__ __half g_Wot[(size_t)HID_ * (NH_ * D_)];

__device__ __forceinline__ uint32_t smem_u32(const void* p) {
    uint32_t a;
    asm("{ .reg .u64 t; cvta.to.shared.u64 t, %1; cvt.u32.u64 %0, t; }" : "=r"(a) : "l"(p));
    return a;
}
__device__ __forceinline__ void cp16(uint32_t saddr, const void* g) {
    asm volatile("cp.async.cg.shared.global [%0], [%1], 16;" :: "r"(saddr), "l"(g));
}
#define CP_COMMIT() asm volatile("cp.async.commit_group;" ::: "memory")
#define CP_WAIT(n)  asm volatile("cp.async.wait_group %0;" :: "n"(n) : "memory")

__device__ __forceinline__ void ldm_x4(uint32_t* r, uint32_t addr) {
    asm volatile("ldmatrix.sync.aligned.m8n8.x4.shared.b16 {%0,%1,%2,%3}, [%4];"
        : "=r"(r[0]), "=r"(r[1]), "=r"(r[2]), "=r"(r[3]) : "r"(addr));
}

// ---------------- pre-pass kernels ------------------------------------------
__global__ void cvt_half_kernel(const float* __restrict__ in, __half* __restrict__ out, int n4) {
    int i = blockIdx.x * blockDim.x + threadIdx.x;
    if (i < n4) {
        float4 v = ((const float4*)in)[i];
        ((__half2*)out)[i * 2]     = __floats2half2_rn(v.x, v.y);
        ((__half2*)out)[i * 2 + 1] = __floats2half2_rn(v.z, v.w);
    }
}
__global__ void transpose_half_kernel(const float* __restrict__ W, __half* __restrict__ Wt,
                                      int K, int N) {
    __shared__ float t[32][33];
    const int n0 = blockIdx.x * 32, k0 = blockIdx.y * 32;
    const int tx = threadIdx.x, ty = threadIdx.y;
#pragma unroll
    for (int j = 0; j < 32; j += 8)
        t[ty + j][tx] = W[(size_t)(k0 + ty + j) * N + n0 + tx];
    __syncthreads();
#pragma unroll
    for (int j = 0; j < 32; j += 8)
        Wt[(size_t)(n0 + ty + j) * K + k0 + tx] = __float2half_rn(t[tx][ty + j]);
}
// K RoPE -> single fp16 (reads K slice of fused QKV)
__global__ __launch_bounds__(256) void rope_kh_kernel(const float* __restrict__ QKV,
                                                      __half* __restrict__ Kh,
                                                      const float* __restrict__ cosc,
                                                      const float* __restrict__ sinc) {
    const int idx = blockIdx.x * 256 + threadIdx.x;
    const int r = idx >> 4;
    const int c4 = (idx & 15) << 2;
    const int bs = r / NKV_, kvh = r % NKV_;
    const int s = bs % S_;
    const float* row = QKV + (size_t)bs * NQKV + NH_ * D_ + kvh * D_;
    float4 x1 = *(const float4*)(row + c4);
    float4 x2 = *(const float4*)(row + c4 + 64);
    float4 c0 = *(const float4*)(cosc + s * D_ + c4);
    float4 s0 = *(const float4*)(sinc + s * D_ + c4);
    float4 c1 = *(const float4*)(cosc + s * D_ + c4 + 64);
    float4 s1 = *(const float4*)(sinc + s * D_ + c4 + 64);
    float o1[4], o2[4];
    o1[0] = x1.x * c0.x - x2.x * s0.x;  o2[0] = x2.x * c1.x + x1.x * s1.x;
    o1[1] = x1.y * c0.y - x2.y * s0.y;  o2[1] = x2.y * c1.y + x1.y * s1.y;
    o1[2] = x1.z * c0.z - x2.z * s0.z;  o2[2] = x2.z * c1.z + x1.z * s1.z;
    o1[3] = x1.w * c0.w - x2.w * s0.w;  o2[3] = x2.w * c1.w + x1.w * s1.w;
    __half* ph = Kh + (size_t)r * D_;
    *(__half2*)(ph + c4)     = __floats2half2_rn(o1[0], o1[1]);
    *(__half2*)(ph + c4 + 2) = __floats2half2_rn(o1[2], o1[3]);
    *(__half2*)(ph + c4 + 64)     = __floats2half2_rn(o2[0], o2[1]);
    *(__half2*)(ph + c4 + 64 + 2) = __floats2half2_rn(o2[2], o2[3]);
}
// V slice of QKV [b,s,kvh,d] fp32 -> Vt [b,kvh,d,s] fp16
__global__ void vt_transpose_kernel(const float* __restrict__ QKV, __half* __restrict__ Vt) {
    __shared__ float t[32][33];
    const int s0 = blockIdx.x * 32, d0 = blockIdx.y * 32;
    const int bk = blockIdx.z;
    const int tx = threadIdx.x, ty = threadIdx.y;
    const int b = bk / NKV_, kvh = bk % NKV_;
#pragma unroll
    for (int j = 0; j < 32; j += 8)
        t[ty + j][tx] = QKV[(size_t)(b * S_ + s0 + ty + j) * NQKV +
                            (NH_ + NKV_) * D_ + kvh * D_ + d0 + tx];
    __syncthreads();
#pragma unroll
    for (int j = 0; j < 32; j += 8)
        Vt[((size_t)(bk * D_ + d0 + ty + j)) * S_ + s0 + tx] = __float2half_rn(t[tx][ty + j]);
}

// ---------------- mma helper --------------------------------------------------
__device__ __forceinline__ void mma_f16(float* c, const uint32_t* a, const uint32_t* b) {
    asm volatile(
        "mma.sync.aligned.m16n8k16.row.col.f32.f16.f16.f32 "
        "{%0,%1,%2,%3}, {%4,%5,%6,%7}, {%8,%9}, {%0,%1,%2,%3};"
        : "+f"(c[0]), "+f"(c[1]), "+f"(c[2]), "+f"(c[3])
        : "r"(a[0]), "r"(a[1]), "r"(a[2]), "r"(a[3]), "r"(b[0]), "r"(b[1]));
}

// ---------------- fp16 mma.sync GEMM: C[M,N] = A[M,K] @ Bt[N,K]^T ------------
#define BM 128
#define BN 128
#define BKH 64
#define TSTRH 72
#define TILE_HALFS (128 * TSTRH)
#define GSM_BYTES (4 * TILE_HALFS * 2)

__device__ __forceinline__ void g2s_cp_h(const __half* __restrict__ G, uint32_t sbase,
                                         int row0, int K, int k0, int tid) {
#pragma unroll
    for (int i = 0; i < 4; i++) {
        int lin = tid + i * 256;
        int r = lin >> 3, c = lin & 7;
        cp16(sbase + (uint32_t)(r * TSTRH + c * 8) * 2u,
             G + (size_t)(row0 + r) * K + k0 + c * 8);
    }
}

__global__ __launch_bounds__(256) void tc_gemm(const __half* __restrict__ A,
                                               const __half* __restrict__ Bt,
                                               float* __restrict__ C,
                                               int M, int N, int K) {
    extern __shared__ __half smh[];
    __half* As[2] = {smh, smh + 2 * TILE_HALFS};
    __half* Bs[2] = {smh + TILE_HALFS, smh + 3 * TILE_HALFS};
    const uint32_t asu[2] = {smem_u32(As[0]), smem_u32(As[1])};
    const uint32_t bsu[2] = {smem_u32(Bs[0]), smem_u32(Bs[1])};

    const int tid = threadIdx.x;
    const int lane = tid & 31, wid = tid >> 5;
    const int warpM = wid & 3;
    const int warpN = wid >> 2;
    const int ty8 = lane >> 2;
    const int tx4 = lane & 3;
    const int lane7 = lane & 7, seg = lane >> 3;
    const int bm = blockIdx.y * BM, bn = blockIdx.x * BN;

    // ldmatrix lane-address offsets (bytes, relative to tile base)
    uint32_t a_offb[2], b_offb[4];
#pragma unroll
    for (int mi = 0; mi < 2; mi++)
        a_offb[mi] = (uint32_t)(((warpM * 32 + mi * 16 + (seg & 1) * 8 + lane7) * TSTRH
                                 + (seg >> 1) * 8) * 2);
#pragma unroll
    for (int p = 0; p < 4; p++)
        b_offb[p] = (uint32_t)(((warpN * 64 + p * 16 + (seg >> 1) * 8 + lane7) * TSTRH
                                 + (seg & 1) * 8) * 2);

    float acc[2][8][4];
#pragma unroll
    for (int mi = 0; mi < 2; mi++)
#pragma unroll
        for (int ni = 0; ni < 8; ni++)
#pragma unroll
            for (int r = 0; r < 4; r++) acc[mi][ni][r] = 0.f;

    g2s_cp_h(A, asu[0], bm, K, 0, tid);
    g2s_cp_h(Bt, bsu[0], bn, K, 0, tid);
    CP_COMMIT();

    const int NK = K / BKH;
    for (int kt = 0; kt < NK; kt++) {
        const int buf = kt & 1;
        if (kt + 1 < NK) {
            g2s_cp_h(A, asu[buf ^ 1], bm, K, (kt + 1) * BKH, tid);
            g2s_cp_h(Bt, bsu[buf ^ 1], bn, K, (kt + 1) * BKH, tid);
            CP_COMMIT();
            CP_WAIT(1);
        } else {
            CP_WAIT(0);
        }
        __syncthreads();

#pragma unroll
        for (int ks = 0; ks < 4; ks++) {
            const uint32_t kb = (uint32_t)(ks * 16 * 2);
            uint32_t af[2][4];
            ldm_x4(af[0], asu[buf] + a_offb[0] + kb);
            ldm_x4(af[1], asu[buf] + a_offb[1] + kb);
            uint32_t bf[8][2];
#pragma unroll
            for (int p = 0; p < 4; p++) {
                uint32_t t[4];
                ldm_x4(t, bsu[buf] + b_offb[p] + kb);
                bf[2 * p][0] = t[0];     bf[2 * p][1] = t[1];
                bf[2 * p + 1][0] = t[2]; bf[2 * p + 1][1] = t[3];
            }
#pragma unroll
            for (int mi = 0; mi < 2; mi++)
#pragma unroll
                for (int ni = 0; ni < 8; ni++)
                    mma_f16(acc[mi][ni], af[mi], bf[ni]);
        }
        __syncthreads();
    }

#pragma unroll
    for (int mi = 0; mi < 2; mi++) {
        const int r0 = bm + warpM * 32 + mi * 16 + ty8;
#pragma unroll
        for (int ni = 0; ni < 8; ni++) {
            const int cc = bn + warpN * 64 + ni * 8 + 2 * tx4;
            *(float2*)(C + (size_t)r0 * N + cc)       = make_float2(acc[mi][ni][0], acc[mi][ni][1]);
            *(float2*)(C + (size_t)(r0 + 8) * N + cc) = make_float2(acc[mi][ni][2], acc[mi][ni][3]);
        }
    }
}

// ---------------- flash attention: fp16 MMA + ldmatrix, 2 CTAs/SM ------------
#define QS_STR  136
#define KH_STR  136
#define VT_STR  72
#define PST     72
#define KH_BYTES (64 * KH_STR * 2)           // 17408
#define VT_BYTES (128 * VT_STR * 2)          // 18432
#define STG_BYTES (KH_BYTES + VT_BYTES)      // 35840
#define OFF_P_B (2 * STG_BYTES)              // 71680
#define FL_SMEM_BYTES (OFF_P_B + 128 * PST * 2)  // 90112

__device__ __forceinline__ void flash_stage(const __half* __restrict__ Khg,
                                            const __half* __restrict__ Vt,
                                            uint32_t sb, int b, int kvh,
                                            int kbase, int tid) {
#pragma unroll
    for (int i = 0; i < 4; i++) {
        int lin = tid + i * 256;
        int r = lin >> 4, c = lin & 15;
        cp16(sb + (uint32_t)(r * KH_STR + c * 8) * 2u,
             Khg + ((size_t)((b * S_ + kbase + r) * NKV_ + kvh)) * D_ + c * 8);
    }
#pragma unroll
    for (int i = 0; i < 4; i++) {
        int lin = tid + i * 256;
        int r = lin >> 3, c = lin & 7;
        cp16(sb + KH_BYTES + (uint32_t)(r * VT_STR + c * 8) * 2u,
             Vt + ((size_t)((b * NKV_ + kvh) * D_ + r)) * S_ + kbase + c * 8);
    }
}

__global__ __launch_bounds__(256) void flash_mma_kernel(
    const float* __restrict__ QKV, const __half* __restrict__ Khg,
    const __half* __restrict__ Vt, const float* __restrict__ cosc,
    const float* __restrict__ sinc, __half* __restrict__ Og) {
    extern __shared__ char smc[];
    const uint32_t smb = smem_u32(smc);
    __half* Ps = (__half*)(smc + OFF_P_B);
    __half* Qstage = (__half*)smc;

    const int tid = threadIdx.x;
    const int lane = tid & 31, wid = tid >> 5;
    const int ty8 = lane >> 2;
    const int tx4 = lane & 3;
    const int lane7 = lane & 7, seg = lane >> 3;
    const int qt = blockIdx.x;
    const int h  = blockIdx.y;
    const int b  = blockIdx.z;
    const int kvh = h >> 2;
    const int qbase = qt * 128;
    const int wrow = wid * 16;
    const float scale = 0.08838834764831845f;

    // ldmatrix lane-address offsets (bytes)
    const uint32_t qa_offb = (uint32_t)(((wrow + (seg & 1) * 8 + lane7) * QS_STR
                                         + (seg >> 1) * 8) * 2);
    uint32_t kb_offb[4];
#pragma unroll
    for (int p = 0; p < 4; p++)
        kb_offb[p] = (uint32_t)(((p * 16 + (seg >> 1) * 8 + lane7) * KH_STR
                                  + (seg & 1) * 8) * 2);
    const uint32_t pa_offb = (uint32_t)(((wrow + (seg & 1) * 8 + lane7) * PST
                                         + (seg >> 1) * 8) * 2);
    uint32_t vb_offb[8];
#pragma unroll
    for (int p = 0; p < 8; p++)
        vb_offb[p] = (uint32_t)(((p * 16 + (seg >> 1) * 8 + lane7) * VT_STR
                                  + (seg & 1) * 8) * 2);
    const uint32_t psu = smb + OFF_P_B;

    // ---- stage Q: fused RoPE + scale + fp16 round ----
#pragma unroll
    for (int i = 0; i < 8; i++) {
        int lin = i * 256 + tid;
        int r = lin >> 4;
        int c4 = (lin & 15) << 2;
        const int sg = qbase + r;
        const float* qrow = QKV + (size_t)(b * S_ + sg) * NQKV + h * D_;
        float4 x1 = *(const float4*)(qrow + c4);
        float4 x2 = *(const float4*)(qrow + c4 + 64);
        float4 c0 = *(const float4*)(cosc + sg * D_ + c4);
        float4 s0 = *(const float4*)(sinc + sg * D_ + c4);
        float4 c1 = *(const float4*)(cosc + sg * D_ + c4 + 64);
        float4 s1 = *(const float4*)(sinc + sg * D_ + c4 + 64);
        float o1[4], o2[4];
        o1[0] = x1.x * c0.x - x2.x * s0.x;  o2[0] = x2.x * c1.x + x1.x * s1.x;
        o1[1] = x1.y * c0.y - x2.y * s0.y;  o2[1] = x2.y * c1.y + x1.y * s1.y;
        o1[2] = x1.z * c0.z - x2.z * s0.z;  o2[2] = x2.z * c1.z + x1.z * s1.z;
        o1[3] = x1.w * c0.w - x2.w * s0.w;  o2[3] = x2.w * c1.w + x1.w * s1.w;
#pragma unroll
        for (int j = 0; j < 4; j++) {
            Qstage[r * QS_STR + c4 + j]      = __float2half_rn(o1[j] * scale);
            Qstage[r * QS_STR + c4 + 64 + j] = __float2half_rn(o2[j] * scale);
        }
    }
    __syncthreads();

    // ---- Q fragments via ldmatrix: 8 k16-steps x 4 regs ----
    uint32_t qf[8][4];
#pragma unroll
    for (int ks = 0; ks < 8; ks++)
        ldm_x4(qf[ks], smb + qa_offb + (uint32_t)(ks * 32));
    __syncthreads();   // Qstage (stage-0 region) now reusable

    float m_i[2] = {-1e30f, -1e30f};
    float l_i[2] = {0.f, 0.f};
    float oacc[16][4];
#pragma unroll
    for (int ni = 0; ni < 16; ni++)
#pragma unroll
        for (int r = 0; r < 4; r++) oacc[ni][r] = 0.f;

    const int NKT = 2 * qt + 2;
    flash_stage(Khg, Vt, smb, b, kvh, 0, tid);
    CP_COMMIT();

    for (int kt = 0; kt < NKT; kt++) {
        const int kbase = kt * 64;
        const int buf = kt & 1;
        if (kt + 1 < NKT) {
            flash_stage(Khg, Vt, smb + (buf ^ 1) * STG_BYTES, b, kvh, kbase + 64, tid);
            CP_COMMIT();
            CP_WAIT(1);
        } else {
            CP_WAIT(0);
        }
        __syncthreads();

        const uint32_t khu = smb + buf * STG_BYTES;
        const uint32_t vsu = khu + KH_BYTES;

        // ---- QK^T via ldmatrix ----
        float sc[8][4];
#pragma unroll
        for (int ni = 0; ni < 8; ni++)
#pragma unroll
            for (int r = 0; r < 4; r++) sc[ni][r] = 0.f;

#pragma unroll
        for (int ks = 0; ks < 8; ks++) {
            const uint32_t kb = (uint32_t)(ks * 32);
#pragma unroll
            for (int p = 0; p < 4; p++) {
                uint32_t t[4];
                ldm_x4(t, khu + kb_offb[p] + kb);
                mma_f16(sc[2 * p], qf[ks], t);
                mma_f16(sc[2 * p + 1], qf[ks], t + 2);
            }
        }

        // ---- causal mask ----
        if (kbase + 63 > qbase) {
#pragma unroll
            for (int ni = 0; ni < 8; ni++) {
#pragma unroll
                for (int r = 0; r < 4; r++) {
                    int row = qbase + wrow + ty8 + ((r >= 2) ? 8 : 0);
                    int col = kbase + ni * 8 + 2 * tx4 + (r & 1);
                    if (col > row) sc[ni][r] = -1e30f;
                }
            }
        }

        // ---- online softmax ----
#pragma unroll
        for (int rh = 0; rh < 2; rh++) {
            const int i0 = rh * 2, i1 = rh * 2 + 1;
            float mloc = -1e30f;
#pragma unroll
            for (int ni = 0; ni < 8; ni++)
                mloc = fmaxf(mloc, fmaxf(sc[ni][i0], sc[ni][i1]));
            mloc = fmaxf(mloc, __shfl_xor_sync(0xffffffffu, mloc, 1));
            mloc = fmaxf(mloc, __shfl_xor_sync(0xffffffffu, mloc, 2));
            const float mnew = fmaxf(m_i[rh], mloc);
            const float fac = __expf(m_i[rh] - mnew);
            m_i[rh] = mnew;
            float rsum = 0.f;
#pragma unroll
            for (int ni = 0; ni < 8; ni++) {
                float p0 = __expf(sc[ni][i0] - mnew);
                float p1 = __expf(sc[ni][i1] - mnew);
                sc[ni][i0] = p0; sc[ni][i1] = p1;
                rsum += p0 + p1;
            }
            rsum += __shfl_xor_sync(0xffffffffu, rsum, 1);
            rsum += __shfl_xor_sync(0xffffffffu, rsum, 2);
            l_i[rh] = l_i[rh] * fac + rsum;
#pragma unroll
            for (int ni = 0; ni < 16; ni++) {
                oacc[ni][i0] *= fac;
                oacc[ni][i1] *= fac;
            }
        }

        // ---- P to smem as fp16 (warp-private rows) ----
#pragma unroll
        for (int ni = 0; ni < 8; ni++) {
            const int cc = ni * 8 + 2 * tx4;
            *(__half2*)&Ps[(wrow + ty8) * PST + cc] =
                __floats2half2_rn(sc[ni][0], sc[ni][1]);
            *(__half2*)&Ps[(wrow + ty8 + 8) * PST + cc] =
                __floats2half2_rn(sc[ni][2], sc[ni][3]);
        }
        __syncwarp();

        // ---- PV via ldmatrix ----
#pragma unroll
        for (int ks = 0; ks < 4; ks++) {
            const uint32_t kb = (uint32_t)(ks * 32);
            uint32_t af[4];
            ldm_x4(af, psu + pa_offb + kb);
#pragma unroll
            for (int p = 0; p < 8; p++) {
                uint32_t t[4];
                ldm_x4(t, vsu + vb_offb[p] + kb);
                mma_f16(oacc[2 * p], af, t);
                mma_f16(oacc[2 * p + 1], af, t + 2);
            }
        }
        __syncthreads();
    }

    // ---- epilogue: normalize, fp16 round (feeds O-proj), store ----
    const float inv0 = 1.0f / l_i[0];
    const float inv1 = 1.0f / l_i[1];
    const int r0 = qbase + wrow + ty8;
#pragma unroll
    for (int ni = 0; ni < 16; ni++) {
        const int cc = ni * 8 + 2 * tx4;
        __half* p0 = Og + ((size_t)((b * S_ + r0) * NH_ + h)) * D_ + cc;
        __half* p1 = Og + ((size_t)((b * S_ + r0 + 8) * NH_ + h)) * D_ + cc;
        *(__half2*)p0 = __floats2half2_rn(oacc[ni][0] * inv0, oacc[ni][1] * inv0);
        *(__half2*)p1 = __floats2half2_rn(oacc[ni][2] * inv1, oacc[ni][3] * inv1);
    }
}

// ---------------- launch ----------------------------------------------------
extern "C" void kernel_launch(void* const* d_in, const int* in_sizes, int n_in,
                              void* d_out, int out_size) {
    const float* X    = (const float*)d_in[0];
    const float* Wq   = (const float*)d_in[1];
    const float* Wk   = (const float*)d_in[2];
    const float* Wv   = (const float*)d_in[3];
    const float* Wo   = (const float*)d_in[4];
    const float* cosc = (const float*)d_in[5];
    const float* sinc = (const float*)d_in[6];
    float* out = (float*)d_out;

    float *QKVp;
    __half *Khp, *Vtp, *Ah, *Xh, *Wqkvt, *Wot;
    cudaGetSymbolAddress((void**)&QKVp, g_QKV);
    cudaGetSymbolAddress((void**)&Khp, g_Kh);
    cudaGetSymbolAddress((void**)&Vtp, g_Vt);
    cudaGetSymbolAddress((void**)&Ah, g_Ah);
    cudaGetSymbolAddress((void**)&Xh, g_Xh);
    cudaGetSymbolAddress((void**)&Wqkvt, g_Wqkvt);
    cudaGetSymbolAddress((void**)&Wot, g_Wot);

    const int M = B_ * S_;          // 4096
    const int NQ = NH_ * D_;        // 4096
    const int NKVD = NKV_ * D_;     // 1024

    {
        int n4 = M * HID_ / 4;
        cvt_half_kernel<<<(n4 + 255) / 256, 256>>>(X, Xh, n4);
        dim3 blk(32, 8);
        transpose_half_kernel<<<dim3(NQ / 32, HID_ / 32), blk>>>(Wq, Wqkvt, HID_, NQ);
        transpose_half_kernel<<<dim3(NKVD / 32, HID_ / 32), blk>>>(
            Wk, Wqkvt + (size_t)NQ * HID_, HID_, NKVD);
        transpose_half_kernel<<<dim3(NKVD / 32, HID_ / 32), blk>>>(
            Wv, Wqkvt + (size_t)(NQ + NKVD) * HID_, HID_, NKVD);
        transpose_half_kernel<<<dim3(HID_ / 32, NQ / 32), blk>>>(Wo, Wot, NQ, HID_);
    }

    cudaFuncSetAttribute(tc_gemm, cudaFuncAttributeMaxDynamicSharedMemorySize, GSM_BYTES);

    // Fused QKV projection
    tc_gemm<<<dim3(NQKV / BN, M / BM), 256, GSM_BYTES>>>(Xh, Wqkvt, QKVp, M, NQKV, HID_);

    // K RoPE -> fp16; V -> fp16 transposed
    rope_kh_kernel<<<(M * NKV_ * 16) / 256, 256>>>(QKVp, Khp, cosc, sinc);
    {
        dim3 blk(32, 8);
        vt_transpose_kernel<<<dim3(S_ / 32, D_ / 32, B_ * NKV_), blk>>>(QKVp, Vtp);
    }

    // Flash attention
    cudaFuncSetAttribute(flash_mma_kernel, cudaFuncAttributeMaxDynamicSharedMemorySize, FL_SMEM_BYTES);
    flash_mma_kernel<<<dim3(S_ / 128, NH_, B_), 256, FL_SMEM_BYTES>>>(
        QKVp, Khp, Vtp, cosc, sinc, Ah);

    // Output projection
    tc_gemm<<<dim3(HID_ / BN, M / BM), 256, GSM_BYTES>>>(Ah, Wot, out, M, HID_, NQ);
}

// round 13
// speedup vs baseline: 3.3959x; 1.0264x over previous
#include <cuda_runtime.h>
#include <cuda_fp16.h>
#include <cstdint>

// Problem constants
#define B_    2
#define S_    2048
#define HID_  4096
#define NH_   32
#define NKV_  8
#define D_    128
#define NQKV  (NH_ * D_ + 2 * NKV_ * D_)   // 6144

// ---------------- scratch (__device__ globals; allocation-free) -------------
__device__ __half g_QKVh[(size_t)B_ * S_ * NQKV];      // fused QKV proj out (fp16)
__device__ __half g_Kh[(size_t)B_ * S_ * NKV_ * D_];   // roped K (fp16)
__device__ __half g_Vt[(size_t)B_ * NKV_ * D_ * S_];   // V transposed [b,kvh,d,s] fp16
__device__ __half g_Ah[(size_t)B_ * S_ * NH_ * D_];    // attn out (fp16)
__device__ __half g_Xh[(size_t)B_ * S_ * HID_];        // fp16 hidden states
__device__ __half g_Wqkvt[(size_t)NQKV * HID_];        // [6144, HID] transposed fp16
__device__ __half g_Wot[(size_t)HID_ * (NH_ * D_)];

__device__ __forceinline__ uint32_t smem_u32(const void* p) {
    uint32_t a;
    asm("{ .reg .u64 t; cvta.to.shared.u64 t, %1; cvt.u32.u64 %0, t; }" : "=r"(a) : "l"(p));
    return a;
}
__device__ __forceinline__ void cp16(uint32_t saddr, const void* g) {
    asm volatile("cp.async.cg.shared.global [%0], [%1], 16;" :: "r"(saddr), "l"(g));
}
#define CP_COMMIT() asm volatile("cp.async.commit_group;" ::: "memory")
#define CP_WAIT(n)  asm volatile("cp.async.wait_group %0;" :: "n"(n) : "memory")

__device__ __forceinline__ void ldm_x4(uint32_t* r, uint32_t addr) {
    asm volatile("ldmatrix.sync.aligned.m8n8.x4.shared.b16 {%0,%1,%2,%3}, [%4];"
        : "=r"(r[0]), "=r"(r[1]), "=r"(r[2]), "=r"(r[3]) : "r"(addr));
}

// Epilogue store helpers (fp32 or fp16 C)
__device__ __forceinline__ void store2(float* p, float a, float b) {
    *(float2*)p = make_float2(a, b);
}
__device__ __forceinline__ void store2(__half* p, float a, float b) {
    *(__half2*)p = __floats2half2_rn(a, b);
}

// ---------------- pre-pass kernels ------------------------------------------
__global__ void cvt_half_kernel(const float* __restrict__ in, __half* __restrict__ out, int n4) {
    int i = blockIdx.x * blockDim.x + threadIdx.x;
    if (i < n4) {
        float4 v = ((const float4*)in)[i];
        ((__half2*)out)[i * 2]     = __floats2half2_rn(v.x, v.y);
        ((__half2*)out)[i * 2 + 1] = __floats2half2_rn(v.z, v.w);
    }
}
__global__ void transpose_half_kernel(const float* __restrict__ W, __half* __restrict__ Wt,
                                      int K, int N) {
    __shared__ float t[32][33];
    const int n0 = blockIdx.x * 32, k0 = blockIdx.y * 32;
    const int tx = threadIdx.x, ty = threadIdx.y;
#pragma unroll
    for (int j = 0; j < 32; j += 8)
        t[ty + j][tx] = W[(size_t)(k0 + ty + j) * N + n0 + tx];
    __syncthreads();
#pragma unroll
    for (int j = 0; j < 32; j += 8)
        Wt[(size_t)(n0 + ty + j) * K + k0 + tx] = __float2half_rn(t[tx][ty + j]);
}
// K RoPE -> single fp16 (reads fp16 K slice of fused QKV)
__global__ __launch_bounds__(256) void rope_kh_kernel(const __half* __restrict__ QKV,
                                                      __half* __restrict__ Kh,
                                                      const float* __restrict__ cosc,
                                                      const float* __restrict__ sinc) {
    const int idx = blockIdx.x * 256 + threadIdx.x;
    const int r = idx >> 4;
    const int c4 = (idx & 15) << 2;
    const int bs = r / NKV_, kvh = r % NKV_;
    const int s = bs % S_;
    const __half* row = QKV + (size_t)bs * NQKV + NH_ * D_ + kvh * D_;
    __half2 a0 = *(const __half2*)(row + c4);
    __half2 a1 = *(const __half2*)(row + c4 + 2);
    __half2 b0 = *(const __half2*)(row + c4 + 64);
    __half2 b1 = *(const __half2*)(row + c4 + 66);
    float x1[4] = {__low2float(a0), __high2float(a0), __low2float(a1), __high2float(a1)};
    float x2[4] = {__low2float(b0), __high2float(b0), __low2float(b1), __high2float(b1)};
    float4 c0 = *(const float4*)(cosc + s * D_ + c4);
    float4 s0 = *(const float4*)(sinc + s * D_ + c4);
    float4 c1 = *(const float4*)(cosc + s * D_ + c4 + 64);
    float4 s1 = *(const float4*)(sinc + s * D_ + c4 + 64);
    float cc0[4] = {c0.x, c0.y, c0.z, c0.w}, ss0[4] = {s0.x, s0.y, s0.z, s0.w};
    float cc1[4] = {c1.x, c1.y, c1.z, c1.w}, ss1[4] = {s1.x, s1.y, s1.z, s1.w};
    float o1[4], o2[4];
#pragma unroll
    for (int j = 0; j < 4; j++) {
        o1[j] = x1[j] * cc0[j] - x2[j] * ss0[j];
        o2[j] = x2[j] * cc1[j] + x1[j] * ss1[j];
    }
    __half* ph = Kh + (size_t)r * D_;
    *(__half2*)(ph + c4)     = __floats2half2_rn(o1[0], o1[1]);
    *(__half2*)(ph + c4 + 2) = __floats2half2_rn(o1[2], o1[3]);
    *(__half2*)(ph + c4 + 64)     = __floats2half2_rn(o2[0], o2[1]);
    *(__half2*)(ph + c4 + 64 + 2) = __floats2half2_rn(o2[2], o2[3]);
}
// V slice of QKV [b,s,kvh,d] fp16 -> Vt [b,kvh,d,s] fp16
__global__ void vt_transpose_kernel(const __half* __restrict__ QKV, __half* __restrict__ Vt) {
    __shared__ __half t[32][40];
    const int s0 = blockIdx.x * 32, d0 = blockIdx.y * 32;
    const int bk = blockIdx.z;
    const int tx = threadIdx.x, ty = threadIdx.y;
    const int b = bk / NKV_, kvh = bk % NKV_;
#pragma unroll
    for (int j = 0; j < 32; j += 8)
        t[ty + j][tx] = QKV[(size_t)(b * S_ + s0 + ty + j) * NQKV +
                            (NH_ + NKV_) * D_ + kvh * D_ + d0 + tx];
    __syncthreads();
#pragma unroll
    for (int j = 0; j < 32; j += 8)
        Vt[((size_t)(bk * D_ + d0 + ty + j)) * S_ + s0 + tx] = t[tx][ty + j];
}

// ---------------- mma helper --------------------------------------------------
__device__ __forceinline__ void mma_f16(float* c, const uint32_t* a, const uint32_t* b) {
    asm volatile(
        "mma.sync.aligned.m16n8k16.row.col.f32.f16.f16.f32 "
        "{%0,%1,%2,%3}, {%4,%5,%6,%7}, {%8,%9}, {%0,%1,%2,%3};"
        : "+f"(c[0]), "+f"(c[1]), "+f"(c[2]), "+f"(c[3])
        : "r"(a[0]), "r"(a[1]), "r"(a[2]), "r"(a[3]), "r"(b[0]), "r"(b[1]));
}

// ---------------- fp16 mma.sync GEMM: C[M,N] = A[M,K] @ Bt[N,K]^T ------------
#define BM 128
#define BN 128
#define BKH 64
#define TSTRH 72
#define TILE_HALFS (128 * TSTRH)
#define GSM_BYTES (4 * TILE_HALFS * 2)

__device__ __forceinline__ void g2s_cp_h(const __half* __restrict__ G, uint32_t sbase,
                                         int row0, int K, int k0, int tid) {
#pragma unroll
    for (int i = 0; i < 4; i++) {
        int lin = tid + i * 256;
        int r = lin >> 3, c = lin & 7;
        cp16(sbase + (uint32_t)(r * TSTRH + c * 8) * 2u,
             G + (size_t)(row0 + r) * K + k0 + c * 8);
    }
}

template <typename OutT>
__global__ __launch_bounds__(256) void tc_gemm(const __half* __restrict__ A,
                                               const __half* __restrict__ Bt,
                                               OutT* __restrict__ C,
                                               int M, int N, int K) {
    extern __shared__ __half smh[];
    const uint32_t asu[2] = {smem_u32(smh), smem_u32(smh + 2 * TILE_HALFS)};
    const uint32_t bsu[2] = {smem_u32(smh + TILE_HALFS), smem_u32(smh + 3 * TILE_HALFS)};

    const int tid = threadIdx.x;
    const int lane = tid & 31, wid = tid >> 5;
    const int warpM = wid & 3;
    const int warpN = wid >> 2;
    const int ty8 = lane >> 2;
    const int tx4 = lane & 3;
    const int lane7 = lane & 7, seg = lane >> 3;
    const int bm = blockIdx.y * BM, bn = blockIdx.x * BN;

    uint32_t a_offb[2], b_offb[4];
#pragma unroll
    for (int mi = 0; mi < 2; mi++)
        a_offb[mi] = (uint32_t)(((warpM * 32 + mi * 16 + (seg & 1) * 8 + lane7) * TSTRH
                                 + (seg >> 1) * 8) * 2);
#pragma unroll
    for (int p = 0; p < 4; p++)
        b_offb[p] = (uint32_t)(((warpN * 64 + p * 16 + (seg >> 1) * 8 + lane7) * TSTRH
                                 + (seg & 1) * 8) * 2);

    float acc[2][8][4];
#pragma unroll
    for (int mi = 0; mi < 2; mi++)
#pragma unroll
        for (int ni = 0; ni < 8; ni++)
#pragma unroll
            for (int r = 0; r < 4; r++) acc[mi][ni][r] = 0.f;

    g2s_cp_h(A, asu[0], bm, K, 0, tid);
    g2s_cp_h(Bt, bsu[0], bn, K, 0, tid);
    CP_COMMIT();

    const int NK = K / BKH;
    for (int kt = 0; kt < NK; kt++) {
        const int buf = kt & 1;
        if (kt + 1 < NK) {
            g2s_cp_h(A, asu[buf ^ 1], bm, K, (kt + 1) * BKH, tid);
            g2s_cp_h(Bt, bsu[buf ^ 1], bn, K, (kt + 1) * BKH, tid);
            CP_COMMIT();
            CP_WAIT(1);
        } else {
            CP_WAIT(0);
        }
        __syncthreads();

#pragma unroll
        for (int ks = 0; ks < 4; ks++) {
            const uint32_t kb = (uint32_t)(ks * 16 * 2);
            uint32_t af[2][4];
            ldm_x4(af[0], asu[buf] + a_offb[0] + kb);
            ldm_x4(af[1], asu[buf] + a_offb[1] + kb);
            uint32_t bf[8][2];
#pragma unroll
            for (int p = 0; p < 4; p++) {
                uint32_t t[4];
                ldm_x4(t, bsu[buf] + b_offb[p] + kb);
                bf[2 * p][0] = t[0];     bf[2 * p][1] = t[1];
                bf[2 * p + 1][0] = t[2]; bf[2 * p + 1][1] = t[3];
            }
#pragma unroll
            for (int mi = 0; mi < 2; mi++)
#pragma unroll
                for (int ni = 0; ni < 8; ni++)
                    mma_f16(acc[mi][ni], af[mi], bf[ni]);
        }
        __syncthreads();
    }

#pragma unroll
    for (int mi = 0; mi < 2; mi++) {
        const int r0 = bm + warpM * 32 + mi * 16 + ty8;
#pragma unroll
        for (int ni = 0; ni < 8; ni++) {
            const int cc = bn + warpN * 64 + ni * 8 + 2 * tx4;
            store2(C + (size_t)r0 * N + cc, acc[mi][ni][0], acc[mi][ni][1]);
            store2(C + (size_t)(r0 + 8) * N + cc, acc[mi][ni][2], acc[mi][ni][3]);
        }
    }
}

// ---------------- flash attention: fp16 MMA + ldmatrix, 2 CTAs/SM ------------
#define QS_STR  136
#define KH_STR  136
#define VT_STR  72
#define PST     72
#define KH_BYTES (64 * KH_STR * 2)           // 17408
#define VT_BYTES (128 * VT_STR * 2)          // 18432
#define STG_BYTES (KH_BYTES + VT_BYTES)      // 35840
#define OFF_P_B (2 * STG_BYTES)              // 71680
#define FL_SMEM_BYTES (OFF_P_B + 128 * PST * 2)  // 90112

__device__ __forceinline__ void flash_stage(const __half* __restrict__ Khg,
                                            const __half* __restrict__ Vt,
                                            uint32_t sb, int b, int kvh,
                                            int kbase, int tid) {
#pragma unroll
    for (int i = 0; i < 4; i++) {
        int lin = tid + i * 256;
        int r = lin >> 4, c = lin & 15;
        cp16(sb + (uint32_t)(r * KH_STR + c * 8) * 2u,
             Khg + ((size_t)((b * S_ + kbase + r) * NKV_ + kvh)) * D_ + c * 8);
    }
#pragma unroll
    for (int i = 0; i < 4; i++) {
        int lin = tid + i * 256;
        int r = lin >> 3, c = lin & 7;
        cp16(sb + KH_BYTES + (uint32_t)(r * VT_STR + c * 8) * 2u,
             Vt + ((size_t)((b * NKV_ + kvh) * D_ + r)) * S_ + kbase + c * 8);
    }
}

__global__ __launch_bounds__(256) void flash_mma_kernel(
    const __half* __restrict__ QKV, const __half* __restrict__ Khg,
    const __half* __restrict__ Vt, const float* __restrict__ cosc,
    const float* __restrict__ sinc, __half* __restrict__ Og) {
    extern __shared__ char smc[];
    const uint32_t smb = smem_u32(smc);
    __half* Ps = (__half*)(smc + OFF_P_B);
    __half* Qstage = (__half*)smc;

    const int tid = threadIdx.x;
    const int lane = tid & 31, wid = tid >> 5;
    const int ty8 = lane >> 2;
    const int tx4 = lane & 3;
    const int lane7 = lane & 7, seg = lane >> 3;
    const int qt = (int)gridDim.x - 1 - (int)blockIdx.x;   // LPT: heaviest tiles first
    const int h  = blockIdx.y;
    const int b  = blockIdx.z;
    const int kvh = h >> 2;
    const int qbase = qt * 128;
    const int wrow = wid * 16;
    const float scale = 0.08838834764831845f;

    const uint32_t qa_offb = (uint32_t)(((wrow + (seg & 1) * 8 + lane7) * QS_STR
                                         + (seg >> 1) * 8) * 2);
    uint32_t kb_offb[4];
#pragma unroll
    for (int p = 0; p < 4; p++)
        kb_offb[p] = (uint32_t)(((p * 16 + (seg >> 1) * 8 + lane7) * KH_STR
                                  + (seg & 1) * 8) * 2);
    const uint32_t pa_offb = (uint32_t)(((wrow + (seg & 1) * 8 + lane7) * PST
                                         + (seg >> 1) * 8) * 2);
    uint32_t vb_offb[8];
#pragma unroll
    for (int p = 0; p < 8; p++)
        vb_offb[p] = (uint32_t)(((p * 16 + (seg >> 1) * 8 + lane7) * VT_STR
                                  + (seg & 1) * 8) * 2);
    const uint32_t psu = smb + OFF_P_B;

    // ---- stage Q: fused RoPE + scale + fp16 round (fp16 Q slice) ----
#pragma unroll
    for (int i = 0; i < 8; i++) {
        int lin = i * 256 + tid;
        int r = lin >> 4;
        int c4 = (lin & 15) << 2;
        const int sg = qbase + r;
        const __half* qrow = QKV + (size_t)(b * S_ + sg) * NQKV + h * D_;
        __half2 a0 = *(const __half2*)(qrow + c4);
        __half2 a1 = *(const __half2*)(qrow + c4 + 2);
        __half2 b0h = *(const __half2*)(qrow + c4 + 64);
        __half2 b1h = *(const __half2*)(qrow + c4 + 66);
        float x1[4] = {__low2float(a0), __high2float(a0), __low2float(a1), __high2float(a1)};
        float x2[4] = {__low2float(b0h), __high2float(b0h), __low2float(b1h), __high2float(b1h)};
        float4 c0 = *(const float4*)(cosc + sg * D_ + c4);
        float4 s0 = *(const float4*)(sinc + sg * D_ + c4);
        float4 c1 = *(const float4*)(cosc + sg * D_ + c4 + 64);
        float4 s1 = *(const float4*)(sinc + sg * D_ + c4 + 64);
        float cc0[4] = {c0.x, c0.y, c0.z, c0.w}, ss0[4] = {s0.x, s0.y, s0.z, s0.w};
        float cc1[4] = {c1.x, c1.y, c1.z, c1.w}, ss1[4] = {s1.x, s1.y, s1.z, s1.w};
#pragma unroll
        for (int j = 0; j < 4; j++) {
            float o1 = x1[j] * cc0[j] - x2[j] * ss0[j];
            float o2 = x2[j] * cc1[j] + x1[j] * ss1[j];
            Qstage[r * QS_STR + c4 + j]      = __float2half_rn(o1 * scale);
            Qstage[r * QS_STR + c4 + 64 + j] = __float2half_rn(o2 * scale);
        }
    }
    __syncthreads();

    // ---- Q fragments via ldmatrix ----
    uint32_t qf[8][4];
#pragma unroll
    for (int ks = 0; ks < 8; ks++)
        ldm_x4(qf[ks], smb + qa_offb + (uint32_t)(ks * 32));
    __syncthreads();

    float m_i[2] = {-1e30f, -1e30f};
    float l_i[2] = {0.f, 0.f};
    float oacc[16][4];
#pragma unroll
    for (int ni = 0; ni < 16; ni++)
#pragma unroll
        for (int r = 0; r < 4; r++) oacc[ni][r] = 0.f;

    const int NKT = 2 * qt + 2;
    flash_stage(Khg, Vt, smb, b, kvh, 0, tid);
    CP_COMMIT();

    for (int kt = 0; kt < NKT; kt++) {
        const int kbase = kt * 64;
        const int buf = kt & 1;
        if (kt + 1 < NKT) {
            flash_stage(Khg, Vt, smb + (buf ^ 1) * STG_BYTES, b, kvh, kbase + 64, tid);
            CP_COMMIT();
            CP_WAIT(1);
        } else {
            CP_WAIT(0);
        }
        __syncthreads();

        const uint32_t khu = smb + buf * STG_BYTES;
        const uint32_t vsu = khu + KH_BYTES;

        // ---- QK^T via ldmatrix ----
        float sc[8][4];
#pragma unroll
        for (int ni = 0; ni < 8; ni++)
#pragma unroll
            for (int r = 0; r < 4; r++) sc[ni][r] = 0.f;

#pragma unroll
        for (int ks = 0; ks < 8; ks++) {
            const uint32_t kb = (uint32_t)(ks * 32);
#pragma unroll
            for (int p = 0; p < 4; p++) {
                uint32_t t[4];
                ldm_x4(t, khu + kb_offb[p] + kb);
                mma_f16(sc[2 * p], qf[ks], t);
                mma_f16(sc[2 * p + 1], qf[ks], t + 2);
            }
        }

        // ---- causal mask ----
        if (kbase + 63 > qbase) {
#pragma unroll
            for (int ni = 0; ni < 8; ni++) {
#pragma unroll
                for (int r = 0; r < 4; r++) {
                    int row = qbase + wrow + ty8 + ((r >= 2) ? 8 : 0);
                    int col = kbase + ni * 8 + 2 * tx4 + (r & 1);
                    if (col > row) sc[ni][r] = -1e30f;
                }
            }
        }

        // ---- online softmax ----
#pragma unroll
        for (int rh = 0; rh < 2; rh++) {
            const int i0 = rh * 2, i1 = rh * 2 + 1;
            float mloc = -1e30f;
#pragma unroll
            for (int ni = 0; ni < 8; ni++)
                mloc = fmaxf(mloc, fmaxf(sc[ni][i0], sc[ni][i1]));
            mloc = fmaxf(mloc, __shfl_xor_sync(0xffffffffu, mloc, 1));
            mloc = fmaxf(mloc, __shfl_xor_sync(0xffffffffu, mloc, 2));
            const float mnew = fmaxf(m_i[rh], mloc);
            const float fac = __expf(m_i[rh] - mnew);
            m_i[rh] = mnew;
            float rsum = 0.f;
#pragma unroll
            for (int ni = 0; ni < 8; ni++) {
                float p0 = __expf(sc[ni][i0] - mnew);
                float p1 = __expf(sc[ni][i1] - mnew);
                sc[ni][i0] = p0; sc[ni][i1] = p1;
                rsum += p0 + p1;
            }
            rsum += __shfl_xor_sync(0xffffffffu, rsum, 1);
            rsum += __shfl_xor_sync(0xffffffffu, rsum, 2);
            l_i[rh] = l_i[rh] * fac + rsum;
#pragma unroll
            for (int ni = 0; ni < 16; ni++) {
                oacc[ni][i0] *= fac;
                oacc[ni][i1] *= fac;
            }
        }

        // ---- P to smem as fp16 ----
#pragma unroll
        for (int ni = 0; ni < 8; ni++) {
            const int cc = ni * 8 + 2 * tx4;
            *(__half2*)&Ps[(wrow + ty8) * PST + cc] =
                __floats2half2_rn(sc[ni][0], sc[ni][1]);
            *(__half2*)&Ps[(wrow + ty8 + 8) * PST + cc] =
                __floats2half2_rn(sc[ni][2], sc[ni][3]);
        }
        __syncwarp();

        // ---- PV via ldmatrix ----
#pragma unroll
        for (int ks = 0; ks < 4; ks++) {
            const uint32_t kb = (uint32_t)(ks * 32);
            uint32_t af[4];
            ldm_x4(af, psu + pa_offb + kb);
#pragma unroll
            for (int p = 0; p < 8; p++) {
                uint32_t t[4];
                ldm_x4(t, vsu + vb_offb[p] + kb);
                mma_f16(oacc[2 * p], af, t);
                mma_f16(oacc[2 * p + 1], af, t + 2);
            }
        }
        __syncthreads();
    }

    // ---- epilogue ----
    const float inv0 = 1.0f / l_i[0];
    const float inv1 = 1.0f / l_i[1];
    const int r0 = qbase + wrow + ty8;
#pragma unroll
    for (int ni = 0; ni < 16; ni++) {
        const int cc = ni * 8 + 2 * tx4;
        __half* p0 = Og + ((size_t)((b * S_ + r0) * NH_ + h)) * D_ + cc;
        __half* p1 = Og + ((size_t)((b * S_ + r0 + 8) * NH_ + h)) * D_ + cc;
        *(__half2*)p0 = __floats2half2_rn(oacc[ni][0] * inv0, oacc[ni][1] * inv0);
        *(__half2*)p1 = __floats2half2_rn(oacc[ni][2] * inv1, oacc[ni][3] * inv1);
    }
}

// ---------------- launch ----------------------------------------------------
extern "C" void kernel_launch(void* const* d_in, const int* in_sizes, int n_in,
                              void* d_out, int out_size) {
    const float* X    = (const float*)d_in[0];
    const float* Wq   = (const float*)d_in[1];
    const float* Wk   = (const float*)d_in[2];
    const float* Wv   = (const float*)d_in[3];
    const float* Wo   = (const float*)d_in[4];
    const float* cosc = (const float*)d_in[5];
    const float* sinc = (const float*)d_in[6];
    float* out = (float*)d_out;

    __half *QKVh, *Khp, *Vtp, *Ah, *Xh, *Wqkvt, *Wot;
    cudaGetSymbolAddress((void**)&QKVh, g_QKVh);
    cudaGetSymbolAddress((void**)&Khp, g_Kh);
    cudaGetSymbolAddress((void**)&Vtp, g_Vt);
    cudaGetSymbolAddress((void**)&Ah, g_Ah);
    cudaGetSymbolAddress((void**)&Xh, g_Xh);
    cudaGetSymbolAddress((void**)&Wqkvt, g_Wqkvt);
    cudaGetSymbolAddress((void**)&Wot, g_Wot);

    const int M = B_ * S_;          // 4096
    const int NQ = NH_ * D_;        // 4096
    const int NKVD = NKV_ * D_;     // 1024

    {
        int n4 = M * HID_ / 4;
        cvt_half_kernel<<<(n4 + 255) / 256, 256>>>(X, Xh, n4);
        dim3 blk(32, 8);
        transpose_half_kernel<<<dim3(NQ / 32, HID_ / 32), blk>>>(Wq, Wqkvt, HID_, NQ);
        transpose_half_kernel<<<dim3(NKVD / 32, HID_ / 32), blk>>>(
            Wk, Wqkvt + (size_t)NQ * HID_, HID_, NKVD);
        transpose_half_kernel<<<dim3(NKVD / 32, HID_ / 32), blk>>>(
            Wv, Wqkvt + (size_t)(NQ + NKVD) * HID_, HID_, NKVD);
        transpose_half_kernel<<<dim3(HID_ / 32, NQ / 32), blk>>>(Wo, Wot, NQ, HID_);
    }

    cudaFuncSetAttribute(tc_gemm<__half>, cudaFuncAttributeMaxDynamicSharedMemorySize, GSM_BYTES);
    cudaFuncSetAttribute(tc_gemm<float>, cudaFuncAttributeMaxDynamicSharedMemorySize, GSM_BYTES);

    // Fused QKV projection (fp16 output)
    tc_gemm<__half><<<dim3(NQKV / BN, M / BM), 256, GSM_BYTES>>>(Xh, Wqkvt, QKVh, M, NQKV, HID_);

    // K RoPE -> fp16; V -> fp16 transposed
    rope_kh_kernel<<<(M * NKV_ * 16) / 256, 256>>>(QKVh, Khp, cosc, sinc);
    {
        dim3 blk(32, 8);
        vt_transpose_kernel<<<dim3(S_ / 32, D_ / 32, B_ * NKV_), blk>>>(QKVh, Vtp);
    }

    // Flash attention (LPT scheduling)
    cudaFuncSetAttribute(flash_mma_kernel, cudaFuncAttributeMaxDynamicSharedMemorySize, FL_SMEM_BYTES);
    flash_mma_kernel<<<dim3(S_ / 128, NH_, B_), 256, FL_SMEM_BYTES>>>(
        QKVh, Khp, Vtp, cosc, sinc, Ah);

    // Output projection (fp32 output)
    tc_gemm<float><<<dim3(HID_ / BN, M / BM), 256, GSM_BYTES>>>(Ah, Wot, out, M, HID_, NQ);
}

// round 14
// speedup vs baseline: 3.4135x; 1.0052x over previous
#include <cuda_runtime.h>
#include <cuda_fp16.h>
#include <cstdint>

// Problem constants
#define B_    2
#define S_    2048
#define HID_  4096
#define NH_   32
#define NKV_  8
#define D_    128
#define NQKV  (NH_ * D_ + 2 * NKV_ * D_)   // 6144

// ---------------- scratch (__device__ globals; allocation-free) -------------
__device__ __half g_QKVh[(size_t)B_ * S_ * NQKV];      // fused QKV proj out (fp16)
__device__ __half g_Kh[(size_t)B_ * S_ * NKV_ * D_];   // roped K (fp16)
__device__ __half g_Vt[(size_t)B_ * NKV_ * D_ * S_];   // V transposed [b,kvh,d,s] fp16
__device__ __half g_Ah[(size_t)B_ * S_ * NH_ * D_];    // attn out (fp16)
__device__ __half g_Xh[(size_t)B_ * S_ * HID_];        // fp16 hidden states
__device__ __half g_Wqkvt[(size_t)NQKV * HID_];        // [6144, HID] transposed fp16
__device__ __half g_Wot[(size_t)HID_ * (NH_ * D_)];

__device__ __forceinline__ uint32_t smem_u32(const void* p) {
    uint32_t a;
    asm("{ .reg .u64 t; cvta.to.shared.u64 t, %1; cvt.u32.u64 %0, t; }" : "=r"(a) : "l"(p));
    return a;
}
__device__ __forceinline__ void cp16(uint32_t saddr, const void* g) {
    asm volatile("cp.async.cg.shared.global [%0], [%1], 16;" :: "r"(saddr), "l"(g));
}
#define CP_COMMIT() asm volatile("cp.async.commit_group;" ::: "memory")
#define CP_WAIT(n)  asm volatile("cp.async.wait_group %0;" :: "n"(n) : "memory")

__device__ __forceinline__ void ldm_x4(uint32_t* r, uint32_t addr) {
    asm volatile("ldmatrix.sync.aligned.m8n8.x4.shared.b16 {%0,%1,%2,%3}, [%4];"
        : "=r"(r[0]), "=r"(r[1]), "=r"(r[2]), "=r"(r[3]) : "r"(addr));
}
__device__ __forceinline__ float ex2f(float x) {
    float y;
    asm("ex2.approx.f32 %0, %1;" : "=f"(y) : "f"(x));
    return y;
}

// Epilogue store helpers (fp32 or fp16 C)
__device__ __forceinline__ void store2(float* p, float a, float b) {
    *(float2*)p = make_float2(a, b);
}
__device__ __forceinline__ void store2(__half* p, float a, float b) {
    *(__half2*)p = __floats2half2_rn(a, b);
}

// ---------------- pre-pass kernels ------------------------------------------
__global__ void cvt_half_kernel(const float* __restrict__ in, __half* __restrict__ out, int n4) {
    int i = blockIdx.x * blockDim.x + threadIdx.x;
    if (i < n4) {
        float4 v = ((const float4*)in)[i];
        ((__half2*)out)[i * 2]     = __floats2half2_rn(v.x, v.y);
        ((__half2*)out)[i * 2 + 1] = __floats2half2_rn(v.z, v.w);
    }
}
__global__ void transpose_half_kernel(const float* __restrict__ W, __half* __restrict__ Wt,
                                      int K, int N) {
    __shared__ float t[32][33];
    const int n0 = blockIdx.x * 32, k0 = blockIdx.y * 32;
    const int tx = threadIdx.x, ty = threadIdx.y;
#pragma unroll
    for (int j = 0; j < 32; j += 8)
        t[ty + j][tx] = W[(size_t)(k0 + ty + j) * N + n0 + tx];
    __syncthreads();
#pragma unroll
    for (int j = 0; j < 32; j += 8)
        Wt[(size_t)(n0 + ty + j) * K + k0 + tx] = __float2half_rn(t[tx][ty + j]);
}
// K RoPE -> single fp16 (reads fp16 K slice of fused QKV)
__global__ __launch_bounds__(256) void rope_kh_kernel(const __half* __restrict__ QKV,
                                                      __half* __restrict__ Kh,
                                                      const float* __restrict__ cosc,
                                                      const float* __restrict__ sinc) {
    const int idx = blockIdx.x * 256 + threadIdx.x;
    const int r = idx >> 4;
    const int c4 = (idx & 15) << 2;
    const int bs = r / NKV_, kvh = r % NKV_;
    const int s = bs % S_;
    const __half* row = QKV + (size_t)bs * NQKV + NH_ * D_ + kvh * D_;
    __half2 a0 = *(const __half2*)(row + c4);
    __half2 a1 = *(const __half2*)(row + c4 + 2);
    __half2 b0 = *(const __half2*)(row + c4 + 64);
    __half2 b1 = *(const __half2*)(row + c4 + 66);
    float x1[4] = {__low2float(a0), __high2float(a0), __low2float(a1), __high2float(a1)};
    float x2[4] = {__low2float(b0), __high2float(b0), __low2float(b1), __high2float(b1)};
    float4 c0 = *(const float4*)(cosc + s * D_ + c4);
    float4 s0 = *(const float4*)(sinc + s * D_ + c4);
    float4 c1 = *(const float4*)(cosc + s * D_ + c4 + 64);
    float4 s1 = *(const float4*)(sinc + s * D_ + c4 + 64);
    float cc0[4] = {c0.x, c0.y, c0.z, c0.w}, ss0[4] = {s0.x, s0.y, s0.z, s0.w};
    float cc1[4] = {c1.x, c1.y, c1.z, c1.w}, ss1[4] = {s1.x, s1.y, s1.z, s1.w};
    float o1[4], o2[4];
#pragma unroll
    for (int j = 0; j < 4; j++) {
        o1[j] = x1[j] * cc0[j] - x2[j] * ss0[j];
        o2[j] = x2[j] * cc1[j] + x1[j] * ss1[j];
    }
    __half* ph = Kh + (size_t)r * D_;
    *(__half2*)(ph + c4)     = __floats2half2_rn(o1[0], o1[1]);
    *(__half2*)(ph + c4 + 2) = __floats2half2_rn(o1[2], o1[3]);
    *(__half2*)(ph + c4 + 64)     = __floats2half2_rn(o2[0], o2[1]);
    *(__half2*)(ph + c4 + 64 + 2) = __floats2half2_rn(o2[2], o2[3]);
}
// V slice of QKV [b,s,kvh,d] fp16 -> Vt [b,kvh,d,s] fp16
__global__ void vt_transpose_kernel(const __half* __restrict__ QKV, __half* __restrict__ Vt) {
    __shared__ __half t[32][40];
    const int s0 = blockIdx.x * 32, d0 = blockIdx.y * 32;
    const int bk = blockIdx.z;
    const int tx = threadIdx.x, ty = threadIdx.y;
    const int b = bk / NKV_, kvh = bk % NKV_;
#pragma unroll
    for (int j = 0; j < 32; j += 8)
        t[ty + j][tx] = QKV[(size_t)(b * S_ + s0 + ty + j) * NQKV +
                            (NH_ + NKV_) * D_ + kvh * D_ + d0 + tx];
    __syncthreads();
#pragma unroll
    for (int j = 0; j < 32; j += 8)
        Vt[((size_t)(bk * D_ + d0 + ty + j)) * S_ + s0 + tx] = t[tx][ty + j];
}

// ---------------- mma helper --------------------------------------------------
__device__ __forceinline__ void mma_f16(float* c, const uint32_t* a, const uint32_t* b) {
    asm volatile(
        "mma.sync.aligned.m16n8k16.row.col.f32.f16.f16.f32 "
        "{%0,%1,%2,%3}, {%4,%5,%6,%7}, {%8,%9}, {%0,%1,%2,%3};"
        : "+f"(c[0]), "+f"(c[1]), "+f"(c[2]), "+f"(c[3])
        : "r"(a[0]), "r"(a[1]), "r"(a[2]), "r"(a[3]), "r"(b[0]), "r"(b[1]));
}

// ---------------- fp16 mma.sync GEMM: C[M,N] = A[M,K] @ Bt[N,K]^T ------------
// 3-stage cp.async pipeline, 2 CTAs/SM.
#define BM 128
#define BN 128
#define BKH 64
#define TSTRH 72
#define TILE_HALFS (128 * TSTRH)
#define STAGE_HALFS (2 * TILE_HALFS)
#define NSTG 3
#define GSM_BYTES (NSTG * STAGE_HALFS * 2)   // 110592

__device__ __forceinline__ void g2s_cp_h(const __half* __restrict__ G, uint32_t sbase,
                                         int row0, int K, int k0, int tid) {
#pragma unroll
    for (int i = 0; i < 4; i++) {
        int lin = tid + i * 256;
        int r = lin >> 3, c = lin & 7;
        cp16(sbase + (uint32_t)(r * TSTRH + c * 8) * 2u,
             G + (size_t)(row0 + r) * K + k0 + c * 8);
    }
}

template <typename OutT>
__global__ __launch_bounds__(256) void tc_gemm(const __half* __restrict__ A,
                                               const __half* __restrict__ Bt,
                                               OutT* __restrict__ C,
                                               int M, int N, int K) {
    extern __shared__ __half smh[];
    const uint32_t smb = smem_u32(smh);

    const int tid = threadIdx.x;
    const int lane = tid & 31, wid = tid >> 5;
    const int warpM = wid & 3;
    const int warpN = wid >> 2;
    const int ty8 = lane >> 2;
    const int tx4 = lane & 3;
    const int lane7 = lane & 7, seg = lane >> 3;
    const int bm = blockIdx.y * BM, bn = blockIdx.x * BN;

    uint32_t a_offb[2], b_offb[4];
#pragma unroll
    for (int mi = 0; mi < 2; mi++)
        a_offb[mi] = (uint32_t)(((warpM * 32 + mi * 16 + (seg & 1) * 8 + lane7) * TSTRH
                                 + (seg >> 1) * 8) * 2);
#pragma unroll
    for (int p = 0; p < 4; p++)
        b_offb[p] = (uint32_t)(((warpN * 64 + p * 16 + (seg >> 1) * 8 + lane7) * TSTRH
                                 + (seg & 1) * 8) * 2);

    float acc[2][8][4];
#pragma unroll
    for (int mi = 0; mi < 2; mi++)
#pragma unroll
        for (int ni = 0; ni < 8; ni++)
#pragma unroll
            for (int r = 0; r < 4; r++) acc[mi][ni][r] = 0.f;

    const int NK = K / BKH;
    // Prologue: stages 0 and 1
    g2s_cp_h(A, smb, bm, K, 0, tid);
    g2s_cp_h(Bt, smb + TILE_HALFS * 2, bn, K, 0, tid);
    CP_COMMIT();
    if (NK > 1) {
        g2s_cp_h(A, smb + STAGE_HALFS * 2, bm, K, BKH, tid);
        g2s_cp_h(Bt, smb + (STAGE_HALFS + TILE_HALFS) * 2, bn, K, BKH, tid);
        CP_COMMIT();
    }

    int buf = 0;
    for (int kt = 0; kt < NK; kt++) {
        if (kt + 2 < NK) {
            int pre = buf + 2; if (pre >= NSTG) pre -= NSTG;
            g2s_cp_h(A, smb + (uint32_t)(pre * STAGE_HALFS) * 2, bm, K, (kt + 2) * BKH, tid);
            g2s_cp_h(Bt, smb + (uint32_t)(pre * STAGE_HALFS + TILE_HALFS) * 2, bn, K, (kt + 2) * BKH, tid);
            CP_COMMIT();
            CP_WAIT(2);
        } else if (kt + 1 < NK) {
            CP_WAIT(1);
        } else {
            CP_WAIT(0);
        }
        __syncthreads();

        const uint32_t asu = smb + (uint32_t)(buf * STAGE_HALFS) * 2;
        const uint32_t bsu = asu + TILE_HALFS * 2;
#pragma unroll
        for (int ks = 0; ks < 4; ks++) {
            const uint32_t kb = (uint32_t)(ks * 16 * 2);
            uint32_t af[2][4];
            ldm_x4(af[0], asu + a_offb[0] + kb);
            ldm_x4(af[1], asu + a_offb[1] + kb);
            uint32_t bf[8][2];
#pragma unroll
            for (int p = 0; p < 4; p++) {
                uint32_t t[4];
                ldm_x4(t, bsu + b_offb[p] + kb);
                bf[2 * p][0] = t[0];     bf[2 * p][1] = t[1];
                bf[2 * p + 1][0] = t[2]; bf[2 * p + 1][1] = t[3];
            }
#pragma unroll
            for (int mi = 0; mi < 2; mi++)
#pragma unroll
                for (int ni = 0; ni < 8; ni++)
                    mma_f16(acc[mi][ni], af[mi], bf[ni]);
        }
        __syncthreads();
        if (++buf == NSTG) buf = 0;
    }

#pragma unroll
    for (int mi = 0; mi < 2; mi++) {
        const int r0 = bm + warpM * 32 + mi * 16 + ty8;
#pragma unroll
        for (int ni = 0; ni < 8; ni++) {
            const int cc = bn + warpN * 64 + ni * 8 + 2 * tx4;
            store2(C + (size_t)r0 * N + cc, acc[mi][ni][0], acc[mi][ni][1]);
            store2(C + (size_t)(r0 + 8) * N + cc, acc[mi][ni][2], acc[mi][ni][3]);
        }
    }
}

// ---------------- flash attention: fp16 MMA + ldmatrix, base-2 softmax -------
#define QS_STR  136
#define KH_STR  136
#define VT_STR  72
#define PST     72
#define KH_BYTES (64 * KH_STR * 2)           // 17408
#define VT_BYTES (128 * VT_STR * 2)          // 18432
#define STG_BYTES (KH_BYTES + VT_BYTES)      // 35840
#define OFF_P_B (2 * STG_BYTES)              // 71680
#define FL_SMEM_BYTES (OFF_P_B + 128 * PST * 2)  // 90112

__device__ __forceinline__ void flash_stage(const __half* __restrict__ Khg,
                                            const __half* __restrict__ Vt,
                                            uint32_t sb, int b, int kvh,
                                            int kbase, int tid) {
#pragma unroll
    for (int i = 0; i < 4; i++) {
        int lin = tid + i * 256;
        int r = lin >> 4, c = lin & 15;
        cp16(sb + (uint32_t)(r * KH_STR + c * 8) * 2u,
             Khg + ((size_t)((b * S_ + kbase + r) * NKV_ + kvh)) * D_ + c * 8);
    }
#pragma unroll
    for (int i = 0; i < 4; i++) {
        int lin = tid + i * 256;
        int r = lin >> 3, c = lin & 7;
        cp16(sb + KH_BYTES + (uint32_t)(r * VT_STR + c * 8) * 2u,
             Vt + ((size_t)((b * NKV_ + kvh) * D_ + r)) * S_ + kbase + c * 8);
    }
}

__global__ __launch_bounds__(256) void flash_mma_kernel(
    const __half* __restrict__ QKV, const __half* __restrict__ Khg,
    const __half* __restrict__ Vt, const float* __restrict__ cosc,
    const float* __restrict__ sinc, __half* __restrict__ Og) {
    extern __shared__ char smc[];
    const uint32_t smb = smem_u32(smc);
    __half* Ps = (__half*)(smc + OFF_P_B);
    __half* Qstage = (__half*)smc;

    const int tid = threadIdx.x;
    const int lane = tid & 31, wid = tid >> 5;
    const int ty8 = lane >> 2;
    const int tx4 = lane & 3;
    const int lane7 = lane & 7, seg = lane >> 3;
    const int qt = (int)gridDim.x - 1 - (int)blockIdx.x;   // LPT
    const int h  = blockIdx.y;
    const int b  = blockIdx.z;
    const int kvh = h >> 2;
    const int qbase = qt * 128;
    const int wrow = wid * 16;
    // scale * log2(e): base-2 softmax (exp -> ex2, no per-exp multiply)
    const float scale = 0.08838834764831845f * 1.44269504088896340f;

    const uint32_t qa_offb = (uint32_t)(((wrow + (seg & 1) * 8 + lane7) * QS_STR
                                         + (seg >> 1) * 8) * 2);
    uint32_t kb_offb[4];
#pragma unroll
    for (int p = 0; p < 4; p++)
        kb_offb[p] = (uint32_t)(((p * 16 + (seg >> 1) * 8 + lane7) * KH_STR
                                  + (seg & 1) * 8) * 2);
    const uint32_t pa_offb = (uint32_t)(((wrow + (seg & 1) * 8 + lane7) * PST
                                         + (seg >> 1) * 8) * 2);
    uint32_t vb_offb[8];
#pragma unroll
    for (int p = 0; p < 8; p++)
        vb_offb[p] = (uint32_t)(((p * 16 + (seg >> 1) * 8 + lane7) * VT_STR
                                  + (seg & 1) * 8) * 2);
    const uint32_t psu = smb + OFF_P_B;

    // ---- stage Q: fused RoPE + scale*log2e + fp16 round ----
#pragma unroll
    for (int i = 0; i < 8; i++) {
        int lin = i * 256 + tid;
        int r = lin >> 4;
        int c4 = (lin & 15) << 2;
        const int sg = qbase + r;
        const __half* qrow = QKV + (size_t)(b * S_ + sg) * NQKV + h * D_;
        __half2 a0 = *(const __half2*)(qrow + c4);
        __half2 a1 = *(const __half2*)(qrow + c4 + 2);
        __half2 b0h = *(const __half2*)(qrow + c4 + 64);
        __half2 b1h = *(const __half2*)(qrow + c4 + 66);
        float x1[4] = {__low2float(a0), __high2float(a0), __low2float(a1), __high2float(a1)};
        float x2[4] = {__low2float(b0h), __high2float(b0h), __low2float(b1h), __high2float(b1h)};
        float4 c0 = *(const float4*)(cosc + sg * D_ + c4);
        float4 s0 = *(const float4*)(sinc + sg * D_ + c4);
        float4 c1 = *(const float4*)(cosc + sg * D_ + c4 + 64);
        float4 s1 = *(const float4*)(sinc + sg * D_ + c4 + 64);
        float cc0[4] = {c0.x, c0.y, c0.z, c0.w}, ss0[4] = {s0.x, s0.y, s0.z, s0.w};
        float cc1[4] = {c1.x, c1.y, c1.z, c1.w}, ss1[4] = {s1.x, s1.y, s1.z, s1.w};
#pragma unroll
        for (int j = 0; j < 4; j++) {
            float o1 = x1[j] * cc0[j] - x2[j] * ss0[j];
            float o2 = x2[j] * cc1[j] + x1[j] * ss1[j];
            Qstage[r * QS_STR + c4 + j]      = __float2half_rn(o1 * scale);
            Qstage[r * QS_STR + c4 + 64 + j] = __float2half_rn(o2 * scale);
        }
    }
    __syncthreads();

    uint32_t qf[8][4];
#pragma unroll
    for (int ks = 0; ks < 8; ks++)
        ldm_x4(qf[ks], smb + qa_offb + (uint32_t)(ks * 32));
    __syncthreads();

    float m_i[2] = {-1e30f, -1e30f};
    float l_i[2] = {0.f, 0.f};
    float oacc[16][4];
#pragma unroll
    for (int ni = 0; ni < 16; ni++)
#pragma unroll
        for (int r = 0; r < 4; r++) oacc[ni][r] = 0.f;

    const int NKT = 2 * qt + 2;
    flash_stage(Khg, Vt, smb, b, kvh, 0, tid);
    CP_COMMIT();

    for (int kt = 0; kt < NKT; kt++) {
        const int kbase = kt * 64;
        const int buf = kt & 1;
        if (kt + 1 < NKT) {
            flash_stage(Khg, Vt, smb + (buf ^ 1) * STG_BYTES, b, kvh, kbase + 64, tid);
            CP_COMMIT();
            CP_WAIT(1);
        } else {
            CP_WAIT(0);
        }
        __syncthreads();

        const uint32_t khu = smb + buf * STG_BYTES;
        const uint32_t vsu = khu + KH_BYTES;

        // ---- QK^T (scores already in base-2 domain) ----
        float sc[8][4];
#pragma unroll
        for (int ni = 0; ni < 8; ni++)
#pragma unroll
            for (int r = 0; r < 4; r++) sc[ni][r] = 0.f;

#pragma unroll
        for (int ks = 0; ks < 8; ks++) {
            const uint32_t kb = (uint32_t)(ks * 32);
#pragma unroll
            for (int p = 0; p < 4; p++) {
                uint32_t t[4];
                ldm_x4(t, khu + kb_offb[p] + kb);
                mma_f16(sc[2 * p], qf[ks], t);
                mma_f16(sc[2 * p + 1], qf[ks], t + 2);
            }
        }

        // ---- causal mask ----
        if (kbase + 63 > qbase) {
#pragma unroll
            for (int ni = 0; ni < 8; ni++) {
#pragma unroll
                for (int r = 0; r < 4; r++) {
                    int row = qbase + wrow + ty8 + ((r >= 2) ? 8 : 0);
                    int col = kbase + ni * 8 + 2 * tx4 + (r & 1);
                    if (col > row) sc[ni][r] = -1e30f;
                }
            }
        }

        // ---- online softmax (base-2, ballot-gated rescale) ----
#pragma unroll
        for (int rh = 0; rh < 2; rh++) {
            const int i0 = rh * 2, i1 = rh * 2 + 1;
            float mloc = -1e30f;
#pragma unroll
            for (int ni = 0; ni < 8; ni++)
                mloc = fmaxf(mloc, fmaxf(sc[ni][i0], sc[ni][i1]));
            mloc = fmaxf(mloc, __shfl_xor_sync(0xffffffffu, mloc, 1));
            mloc = fmaxf(mloc, __shfl_xor_sync(0xffffffffu, mloc, 2));
            const float mnew = fmaxf(m_i[rh], mloc);
            const bool changed = mnew > m_i[rh];
            const float fac = ex2f(m_i[rh] - mnew);   // ==1 when unchanged
            m_i[rh] = mnew;
            float rsum = 0.f;
#pragma unroll
            for (int ni = 0; ni < 8; ni++) {
                float p0 = ex2f(sc[ni][i0] - mnew);
                float p1 = ex2f(sc[ni][i1] - mnew);
                sc[ni][i0] = p0; sc[ni][i1] = p1;
                rsum += p0 + p1;
            }
            rsum += __shfl_xor_sync(0xffffffffu, rsum, 1);
            rsum += __shfl_xor_sync(0xffffffffu, rsum, 2);
            l_i[rh] = l_i[rh] * fac + rsum;
            if (__any_sync(0xffffffffu, changed)) {
#pragma unroll
                for (int ni = 0; ni < 16; ni++) {
                    oacc[ni][i0] *= fac;
                    oacc[ni][i1] *= fac;
                }
            }
        }

        // ---- P to smem as fp16 ----
#pragma unroll
        for (int ni = 0; ni < 8; ni++) {
            const int cc = ni * 8 + 2 * tx4;
            *(__half2*)&Ps[(wrow + ty8) * PST + cc] =
                __floats2half2_rn(sc[ni][0], sc[ni][1]);
            *(__half2*)&Ps[(wrow + ty8 + 8) * PST + cc] =
                __floats2half2_rn(sc[ni][2], sc[ni][3]);
        }
        __syncwarp();

        // ---- PV via ldmatrix ----
#pragma unroll
        for (int ks = 0; ks < 4; ks++) {
            const uint32_t kb = (uint32_t)(ks * 32);
            uint32_t af[4];
            ldm_x4(af, psu + pa_offb + kb);
#pragma unroll
            for (int p = 0; p < 8; p++) {
                uint32_t t[4];
                ldm_x4(t, vsu + vb_offb[p] + kb);
                mma_f16(oacc[2 * p], af, t);
                mma_f16(oacc[2 * p + 1], af, t + 2);
            }
        }
        __syncthreads();
    }

    // ---- epilogue ----
    const float inv0 = 1.0f / l_i[0];
    const float inv1 = 1.0f / l_i[1];
    const int r0 = qbase + wrow + ty8;
#pragma unroll
    for (int ni = 0; ni < 16; ni++) {
        const int cc = ni * 8 + 2 * tx4;
        __half* p0 = Og + ((size_t)((b * S_ + r0) * NH_ + h)) * D_ + cc;
        __half* p1 = Og + ((size_t)((b * S_ + r0 + 8) * NH_ + h)) * D_ + cc;
        *(__half2*)p0 = __floats2half2_rn(oacc[ni][0] * inv0, oacc[ni][1] * inv0);
        *(__half2*)p1 = __floats2half2_rn(oacc[ni][2] * inv1, oacc[ni][3] * inv1);
    }
}

// ---------------- launch ----------------------------------------------------
extern "C" void kernel_launch(void* const* d_in, const int* in_sizes, int n_in,
                              void* d_out, int out_size) {
    const float* X    = (const float*)d_in[0];
    const float* Wq   = (const float*)d_in[1];
    const float* Wk   = (const float*)d_in[2];
    const float* Wv   = (const float*)d_in[3];
    const float* Wo   = (const float*)d_in[4];
    const float* cosc = (const float*)d_in[5];
    const float* sinc = (const float*)d_in[6];
    float* out = (float*)d_out;

    __half *QKVh, *Khp, *Vtp, *Ah, *Xh, *Wqkvt, *Wot;
    cudaGetSymbolAddress((void**)&QKVh, g_QKVh);
    cudaGetSymbolAddress((void**)&Khp, g_Kh);
    cudaGetSymbolAddress((void**)&Vtp, g_Vt);
    cudaGetSymbolAddress((void**)&Ah, g_Ah);
    cudaGetSymbolAddress((void**)&Xh, g_Xh);
    cudaGetSymbolAddress((void**)&Wqkvt, g_Wqkvt);
    cudaGetSymbolAddress((void**)&Wot, g_Wot);

    const int M = B_ * S_;          // 4096
    const int NQ = NH_ * D_;        // 4096
    const int NKVD = NKV_ * D_;     // 1024

    {
        int n4 = M * HID_ / 4;
        cvt_half_kernel<<<(n4 + 255) / 256, 256>>>(X, Xh, n4);
        dim3 blk(32, 8);
        transpose_half_kernel<<<dim3(NQ / 32, HID_ / 32), blk>>>(Wq, Wqkvt, HID_, NQ);
        transpose_half_kernel<<<dim3(NKVD / 32, HID_ / 32), blk>>>(
            Wk, Wqkvt + (size_t)NQ * HID_, HID_, NKVD);
        transpose_half_kernel<<<dim3(NKVD / 32, HID_ / 32), blk>>>(
            Wv, Wqkvt + (size_t)(NQ + NKVD) * HID_, HID_, NKVD);
        transpose_half_kernel<<<dim3(HID_ / 32, NQ / 32), blk>>>(Wo, Wot, NQ, HID_);
    }

    cudaFuncSetAttribute(tc_gemm<__half>, cudaFuncAttributeMaxDynamicSharedMemorySize, GSM_BYTES);
    cudaFuncSetAttribute(tc_gemm<float>, cudaFuncAttributeMaxDynamicSharedMemorySize, GSM_BYTES);

    // Fused QKV projection (fp16 output)
    tc_gemm<__half><<<dim3(NQKV / BN, M / BM), 256, GSM_BYTES>>>(Xh, Wqkvt, QKVh, M, NQKV, HID_);

    // K RoPE -> fp16; V -> fp16 transposed
    rope_kh_kernel<<<(M * NKV_ * 16) / 256, 256>>>(QKVh, Khp, cosc, sinc);
    {
        dim3 blk(32, 8);
        vt_transpose_kernel<<<dim3(S_ / 32, D_ / 32, B_ * NKV_), blk>>>(QKVh, Vtp);
    }

    // Flash attention
    cudaFuncSetAttribute(flash_mma_kernel, cudaFuncAttributeMaxDynamicSharedMemorySize, FL_SMEM_BYTES);
    flash_mma_kernel<<<dim3(S_ / 128, NH_, B_), 256, FL_SMEM_BYTES>>>(
        QKVh, Khp, Vtp, cosc, sinc, Ah);

    // Output projection (fp32 output)
    tc_gemm<float><<<dim3(HID_ / BN, M / BM), 256, GSM_BYTES>>>(Ah, Wot, out, M, HID_, NQ);
}

// round 15
// speedup vs baseline: 3.5873x; 1.0509x over previous
#include <cuda_runtime.h>
#include <cuda_fp16.h>
#include <cstdint>

// Problem constants
#define B_    2
#define S_    2048
#define HID_  4096
#define NH_   32
#define NKV_  8
#define D_    128
#define NQKV  (NH_ * D_ + 2 * NKV_ * D_)   // 6144
#define NTASK (16 * NH_ * B_)              // 1024 flash tasks

// ---------------- scratch (__device__ globals; allocation-free) -------------
__device__ __half g_QKVh[(size_t)B_ * S_ * NQKV];      // fused QKV proj out (fp16)
__device__ __half g_Kh[(size_t)B_ * S_ * NKV_ * D_];   // roped K (fp16)
__device__ __half g_Vt[(size_t)B_ * NKV_ * D_ * S_];   // V transposed [b,kvh,d,s] fp16
__device__ __half g_Ah[(size_t)B_ * S_ * NH_ * D_];    // attn out (fp16)
__device__ __half g_Xh[(size_t)B_ * S_ * HID_];        // fp16 hidden states
__device__ __half g_Wqkvt[(size_t)NQKV * HID_];        // [6144, HID] transposed fp16
__device__ __half g_Wot[(size_t)HID_ * (NH_ * D_)];
__device__ int    g_ctr;                               // flash work-queue counter

__device__ __forceinline__ uint32_t smem_u32(const void* p) {
    uint32_t a;
    asm("{ .reg .u64 t; cvta.to.shared.u64 t, %1; cvt.u32.u64 %0, t; }" : "=r"(a) : "l"(p));
    return a;
}
__device__ __forceinline__ void cp16(uint32_t saddr, const void* g) {
    asm volatile("cp.async.cg.shared.global [%0], [%1], 16;" :: "r"(saddr), "l"(g));
}
#define CP_COMMIT() asm volatile("cp.async.commit_group;" ::: "memory")
#define CP_WAIT(n)  asm volatile("cp.async.wait_group %0;" :: "n"(n) : "memory")

__device__ __forceinline__ void ldm_x4(uint32_t* r, uint32_t addr) {
    asm volatile("ldmatrix.sync.aligned.m8n8.x4.shared.b16 {%0,%1,%2,%3}, [%4];"
        : "=r"(r[0]), "=r"(r[1]), "=r"(r[2]), "=r"(r[3]) : "r"(addr));
}
__device__ __forceinline__ float ex2f(float x) {
    float y;
    asm("ex2.approx.f32 %0, %1;" : "=f"(y) : "f"(x));
    return y;
}
__device__ __forceinline__ uint32_t packh2(float a, float b) {
    __half2 h = __floats2half2_rn(a, b);
    return *(uint32_t*)&h;
}

// Epilogue store helpers (fp32 or fp16 C)
__device__ __forceinline__ void store2(float* p, float a, float b) {
    *(float2*)p = make_float2(a, b);
}
__device__ __forceinline__ void store2(__half* p, float a, float b) {
    *(__half2*)p = __floats2half2_rn(a, b);
}

// ---------------- pre-pass kernels ------------------------------------------
__global__ void cvt_half_kernel(const float* __restrict__ in, __half* __restrict__ out, int n4) {
    int i = blockIdx.x * blockDim.x + threadIdx.x;
    if (i < n4) {
        float4 v = ((const float4*)in)[i];
        ((__half2*)out)[i * 2]     = __floats2half2_rn(v.x, v.y);
        ((__half2*)out)[i * 2 + 1] = __floats2half2_rn(v.z, v.w);
    }
}
__global__ void zero_ctr_kernel() { g_ctr = 0; }

__global__ void transpose_half_kernel(const float* __restrict__ W, __half* __restrict__ Wt,
                                      int K, int N) {
    __shared__ float t[32][33];
    const int n0 = blockIdx.x * 32, k0 = blockIdx.y * 32;
    const int tx = threadIdx.x, ty = threadIdx.y;
#pragma unroll
    for (int j = 0; j < 32; j += 8)
        t[ty + j][tx] = W[(size_t)(k0 + ty + j) * N + n0 + tx];
    __syncthreads();
#pragma unroll
    for (int j = 0; j < 32; j += 8)
        Wt[(size_t)(n0 + ty + j) * K + k0 + tx] = __float2half_rn(t[tx][ty + j]);
}
// K RoPE -> single fp16 (reads fp16 K slice of fused QKV)
__global__ __launch_bounds__(256) void rope_kh_kernel(const __half* __restrict__ QKV,
                                                      __half* __restrict__ Kh,
                                                      const float* __restrict__ cosc,
                                                      const float* __restrict__ sinc) {
    const int idx = blockIdx.x * 256 + threadIdx.x;
    const int r = idx >> 4;
    const int c4 = (idx & 15) << 2;
    const int bs = r / NKV_, kvh = r % NKV_;
    const int s = bs % S_;
    const __half* row = QKV + (size_t)bs * NQKV + NH_ * D_ + kvh * D_;
    __half2 a0 = *(const __half2*)(row + c4);
    __half2 a1 = *(const __half2*)(row + c4 + 2);
    __half2 b0 = *(const __half2*)(row + c4 + 64);
    __half2 b1 = *(const __half2*)(row + c4 + 66);
    float x1[4] = {__low2float(a0), __high2float(a0), __low2float(a1), __high2float(a1)};
    float x2[4] = {__low2float(b0), __high2float(b0), __low2float(b1), __high2float(b1)};
    float4 c0 = *(const float4*)(cosc + s * D_ + c4);
    float4 s0 = *(const float4*)(sinc + s * D_ + c4);
    float4 c1 = *(const float4*)(cosc + s * D_ + c4 + 64);
    float4 s1 = *(const float4*)(sinc + s * D_ + c4 + 64);
    float cc0[4] = {c0.x, c0.y, c0.z, c0.w}, ss0[4] = {s0.x, s0.y, s0.z, s0.w};
    float cc1[4] = {c1.x, c1.y, c1.z, c1.w}, ss1[4] = {s1.x, s1.y, s1.z, s1.w};
    float o1[4], o2[4];
#pragma unroll
    for (int j = 0; j < 4; j++) {
        o1[j] = x1[j] * cc0[j] - x2[j] * ss0[j];
        o2[j] = x2[j] * cc1[j] + x1[j] * ss1[j];
    }
    __half* ph = Kh + (size_t)r * D_;
    *(__half2*)(ph + c4)     = __floats2half2_rn(o1[0], o1[1]);
    *(__half2*)(ph + c4 + 2) = __floats2half2_rn(o1[2], o1[3]);
    *(__half2*)(ph + c4 + 64)     = __floats2half2_rn(o2[0], o2[1]);
    *(__half2*)(ph + c4 + 64 + 2) = __floats2half2_rn(o2[2], o2[3]);
}
// V slice of QKV [b,s,kvh,d] fp16 -> Vt [b,kvh,d,s] fp16
__global__ void vt_transpose_kernel(const __half* __restrict__ QKV, __half* __restrict__ Vt) {
    __shared__ __half t[32][40];
    const int s0 = blockIdx.x * 32, d0 = blockIdx.y * 32;
    const int bk = blockIdx.z;
    const int tx = threadIdx.x, ty = threadIdx.y;
    const int b = bk / NKV_, kvh = bk % NKV_;
#pragma unroll
    for (int j = 0; j < 32; j += 8)
        t[ty + j][tx] = QKV[(size_t)(b * S_ + s0 + ty + j) * NQKV +
                            (NH_ + NKV_) * D_ + kvh * D_ + d0 + tx];
    __syncthreads();
#pragma unroll
    for (int j = 0; j < 32; j += 8)
        Vt[((size_t)(bk * D_ + d0 + ty + j)) * S_ + s0 + tx] = t[tx][ty + j];
}

// ---------------- mma helper --------------------------------------------------
__device__ __forceinline__ void mma_f16(float* c, const uint32_t* a, const uint32_t* b) {
    asm volatile(
        "mma.sync.aligned.m16n8k16.row.col.f32.f16.f16.f32 "
        "{%0,%1,%2,%3}, {%4,%5,%6,%7}, {%8,%9}, {%0,%1,%2,%3};"
        : "+f"(c[0]), "+f"(c[1]), "+f"(c[2]), "+f"(c[3])
        : "r"(a[0]), "r"(a[1]), "r"(a[2]), "r"(a[3]), "r"(b[0]), "r"(b[1]));
}

// ---------------- fp16 mma.sync GEMM (3-stage cp.async) ----------------------
#define BM 128
#define BN 128
#define BKH 64
#define TSTRH 72
#define TILE_HALFS (128 * TSTRH)
#define STAGE_HALFS (2 * TILE_HALFS)
#define NSTG 3
#define GSM_BYTES (NSTG * STAGE_HALFS * 2)   // 110592

__device__ __forceinline__ void g2s_cp_h(const __half* __restrict__ G, uint32_t sbase,
                                         int row0, int K, int k0, int tid) {
#pragma unroll
    for (int i = 0; i < 4; i++) {
        int lin = tid + i * 256;
        int r = lin >> 3, c = lin & 7;
        cp16(sbase + (uint32_t)(r * TSTRH + c * 8) * 2u,
             G + (size_t)(row0 + r) * K + k0 + c * 8);
    }
}

template <typename OutT>
__global__ __launch_bounds__(256) void tc_gemm(const __half* __restrict__ A,
                                               const __half* __restrict__ Bt,
                                               OutT* __restrict__ C,
                                               int M, int N, int K) {
    extern __shared__ __half smh[];
    const uint32_t smb = smem_u32(smh);

    const int tid = threadIdx.x;
    const int lane = tid & 31, wid = tid >> 5;
    const int warpM = wid & 3;
    const int warpN = wid >> 2;
    const int ty8 = lane >> 2;
    const int tx4 = lane & 3;
    const int lane7 = lane & 7, seg = lane >> 3;
    const int bm = blockIdx.y * BM, bn = blockIdx.x * BN;

    uint32_t a_offb[2], b_offb[4];
#pragma unroll
    for (int mi = 0; mi < 2; mi++)
        a_offb[mi] = (uint32_t)(((warpM * 32 + mi * 16 + (seg & 1) * 8 + lane7) * TSTRH
                                 + (seg >> 1) * 8) * 2);
#pragma unroll
    for (int p = 0; p < 4; p++)
        b_offb[p] = (uint32_t)(((warpN * 64 + p * 16 + (seg >> 1) * 8 + lane7) * TSTRH
                                 + (seg & 1) * 8) * 2);

    float acc[2][8][4];
#pragma unroll
    for (int mi = 0; mi < 2; mi++)
#pragma unroll
        for (int ni = 0; ni < 8; ni++)
#pragma unroll
            for (int r = 0; r < 4; r++) acc[mi][ni][r] = 0.f;

    const int NK = K / BKH;
    g2s_cp_h(A, smb, bm, K, 0, tid);
    g2s_cp_h(Bt, smb + TILE_HALFS * 2, bn, K, 0, tid);
    CP_COMMIT();
    if (NK > 1) {
        g2s_cp_h(A, smb + STAGE_HALFS * 2, bm, K, BKH, tid);
        g2s_cp_h(Bt, smb + (STAGE_HALFS + TILE_HALFS) * 2, bn, K, BKH, tid);
        CP_COMMIT();
    }

    int buf = 0;
    for (int kt = 0; kt < NK; kt++) {
        if (kt + 2 < NK) {
            int pre = buf + 2; if (pre >= NSTG) pre -= NSTG;
            g2s_cp_h(A, smb + (uint32_t)(pre * STAGE_HALFS) * 2, bm, K, (kt + 2) * BKH, tid);
            g2s_cp_h(Bt, smb + (uint32_t)(pre * STAGE_HALFS + TILE_HALFS) * 2, bn, K, (kt + 2) * BKH, tid);
            CP_COMMIT();
            CP_WAIT(2);
        } else if (kt + 1 < NK) {
            CP_WAIT(1);
        } else {
            CP_WAIT(0);
        }
        __syncthreads();

        const uint32_t asu = smb + (uint32_t)(buf * STAGE_HALFS) * 2;
        const uint32_t bsu = asu + TILE_HALFS * 2;
#pragma unroll
        for (int ks = 0; ks < 4; ks++) {
            const uint32_t kb = (uint32_t)(ks * 16 * 2);
            uint32_t af[2][4];
            ldm_x4(af[0], asu + a_offb[0] + kb);
            ldm_x4(af[1], asu + a_offb[1] + kb);
            uint32_t bf[8][2];
#pragma unroll
            for (int p = 0; p < 4; p++) {
                uint32_t t[4];
                ldm_x4(t, bsu + b_offb[p] + kb);
                bf[2 * p][0] = t[0];     bf[2 * p][1] = t[1];
                bf[2 * p + 1][0] = t[2]; bf[2 * p + 1][1] = t[3];
            }
#pragma unroll
            for (int mi = 0; mi < 2; mi++)
#pragma unroll
                for (int ni = 0; ni < 8; ni++)
                    mma_f16(acc[mi][ni], af[mi], bf[ni]);
        }
        __syncthreads();
        if (++buf == NSTG) buf = 0;
    }

#pragma unroll
    for (int mi = 0; mi < 2; mi++) {
        const int r0 = bm + warpM * 32 + mi * 16 + ty8;
#pragma unroll
        for (int ni = 0; ni < 8; ni++) {
            const int cc = bn + warpN * 64 + ni * 8 + 2 * tx4;
            store2(C + (size_t)r0 * N + cc, acc[mi][ni][0], acc[mi][ni][1]);
            store2(C + (size_t)(r0 + 8) * N + cc, acc[mi][ni][2], acc[mi][ni][3]);
        }
    }
}

// ---------------- persistent flash attention ---------------------------------
// P kept in registers (QK C-frag == PV A-frag). 296 CTAs, atomic work queue.
#define QS_STR  136
#define KH_STR  136
#define VT_STR  72
#define KH_BYTES (64 * KH_STR * 2)           // 17408
#define VT_BYTES (128 * VT_STR * 2)          // 18432
#define STG_BYTES (KH_BYTES + VT_BYTES)      // 35840
#define FL_SMEM_BYTES (2 * STG_BYTES)        // 71680
#define FL_GRID 296

__device__ __forceinline__ void flash_stage(const __half* __restrict__ Khg,
                                            const __half* __restrict__ Vt,
                                            uint32_t sb, int b, int kvh,
                                            int kbase, int tid) {
#pragma unroll
    for (int i = 0; i < 4; i++) {
        int lin = tid + i * 256;
        int r = lin >> 4, c = lin & 15;
        cp16(sb + (uint32_t)(r * KH_STR + c * 8) * 2u,
             Khg + ((size_t)((b * S_ + kbase + r) * NKV_ + kvh)) * D_ + c * 8);
    }
#pragma unroll
    for (int i = 0; i < 4; i++) {
        int lin = tid + i * 256;
        int r = lin >> 3, c = lin & 7;
        cp16(sb + KH_BYTES + (uint32_t)(r * VT_STR + c * 8) * 2u,
             Vt + ((size_t)((b * NKV_ + kvh) * D_ + r)) * S_ + kbase + c * 8);
    }
}

__global__ __launch_bounds__(256) void flash_mma_kernel(
    const __half* __restrict__ QKV, const __half* __restrict__ Khg,
    const __half* __restrict__ Vt, const float* __restrict__ cosc,
    const float* __restrict__ sinc, __half* __restrict__ Og) {
    extern __shared__ char smc[];
    __shared__ int s_task;
    const uint32_t smb = smem_u32(smc);
    __half* Qstage = (__half*)smc;

    const int tid = threadIdx.x;
    const int lane = tid & 31, wid = tid >> 5;
    const int ty8 = lane >> 2;
    const int tx4 = lane & 3;
    const int lane7 = lane & 7, seg = lane >> 3;
    const int wrow = wid * 16;
    const float scale = 0.08838834764831845f * 1.44269504088896340f;

    const uint32_t qa_offb = (uint32_t)(((wrow + (seg & 1) * 8 + lane7) * QS_STR
                                         + (seg >> 1) * 8) * 2);
    uint32_t kb_offb[4];
#pragma unroll
    for (int p = 0; p < 4; p++)
        kb_offb[p] = (uint32_t)(((p * 16 + (seg >> 1) * 8 + lane7) * KH_STR
                                  + (seg & 1) * 8) * 2);
    uint32_t vb_offb[8];
#pragma unroll
    for (int p = 0; p < 8; p++)
        vb_offb[p] = (uint32_t)(((p * 16 + (seg >> 1) * 8 + lane7) * VT_STR
                                  + (seg & 1) * 8) * 2);

    for (;;) {
        if (tid == 0) s_task = atomicAdd(&g_ctr, 1);
        __syncthreads();
        const int t = s_task;
        __syncthreads();
        if (t >= NTASK) break;
        // LPT order: qt descends (heaviest tasks first)
        const int qt = 15 - (t >> 6);
        const int h  = t & 31;
        const int b  = (t >> 5) & 1;
        const int kvh = h >> 2;
        const int qbase = qt * 128;

        // ---- stage Q: fused RoPE + scale*log2e + fp16 ----
#pragma unroll
        for (int i = 0; i < 8; i++) {
            int lin = i * 256 + tid;
            int r = lin >> 4;
            int c4 = (lin & 15) << 2;
            const int sg = qbase + r;
            const __half* qrow = QKV + (size_t)(b * S_ + sg) * NQKV + h * D_;
            __half2 a0 = *(const __half2*)(qrow + c4);
            __half2 a1 = *(const __half2*)(qrow + c4 + 2);
            __half2 b0h = *(const __half2*)(qrow + c4 + 64);
            __half2 b1h = *(const __half2*)(qrow + c4 + 66);
            float x1[4] = {__low2float(a0), __high2float(a0), __low2float(a1), __high2float(a1)};
            float x2[4] = {__low2float(b0h), __high2float(b0h), __low2float(b1h), __high2float(b1h)};
            float4 c0 = *(const float4*)(cosc + sg * D_ + c4);
            float4 s0 = *(const float4*)(sinc + sg * D_ + c4);
            float4 c1 = *(const float4*)(cosc + sg * D_ + c4 + 64);
            float4 s1 = *(const float4*)(sinc + sg * D_ + c4 + 64);
            float cc0[4] = {c0.x, c0.y, c0.z, c0.w}, ss0[4] = {s0.x, s0.y, s0.z, s0.w};
            float cc1[4] = {c1.x, c1.y, c1.z, c1.w}, ss1[4] = {s1.x, s1.y, s1.z, s1.w};
#pragma unroll
            for (int j = 0; j < 4; j++) {
                float o1 = x1[j] * cc0[j] - x2[j] * ss0[j];
                float o2 = x2[j] * cc1[j] + x1[j] * ss1[j];
                Qstage[r * QS_STR + c4 + j]      = __float2half_rn(o1 * scale);
                Qstage[r * QS_STR + c4 + 64 + j] = __float2half_rn(o2 * scale);
            }
        }
        __syncthreads();

        uint32_t qf[8][4];
#pragma unroll
        for (int ks = 0; ks < 8; ks++)
            ldm_x4(qf[ks], smb + qa_offb + (uint32_t)(ks * 32));
        __syncthreads();

        float m_i[2] = {-1e30f, -1e30f};
        float l_i[2] = {0.f, 0.f};
        float oacc[16][4];
#pragma unroll
        for (int ni = 0; ni < 16; ni++)
#pragma unroll
            for (int r = 0; r < 4; r++) oacc[ni][r] = 0.f;

        const int NKT = 2 * qt + 2;
        flash_stage(Khg, Vt, smb, b, kvh, 0, tid);
        CP_COMMIT();

        for (int kt = 0; kt < NKT; kt++) {
            const int kbase = kt * 64;
            const int buf = kt & 1;
            if (kt + 1 < NKT) {
                flash_stage(Khg, Vt, smb + (buf ^ 1) * STG_BYTES, b, kvh, kbase + 64, tid);
                CP_COMMIT();
                CP_WAIT(1);
            } else {
                CP_WAIT(0);
            }
            __syncthreads();

            // Fully-masked warp skip (diagonal overhang): all cols > all rows
            const bool active = (qbase + wrow + 15 >= kbase);
            if (active) {
                const uint32_t khu = smb + buf * STG_BYTES;
                const uint32_t vsu = khu + KH_BYTES;

                // ---- QK^T ----
                float sc[8][4];
#pragma unroll
                for (int ni = 0; ni < 8; ni++)
#pragma unroll
                    for (int r = 0; r < 4; r++) sc[ni][r] = 0.f;
#pragma unroll
                for (int ks = 0; ks < 8; ks++) {
                    const uint32_t kb = (uint32_t)(ks * 32);
#pragma unroll
                    for (int p = 0; p < 4; p++) {
                        uint32_t kf[4];
                        ldm_x4(kf, khu + kb_offb[p] + kb);
                        mma_f16(sc[2 * p], qf[ks], kf);
                        mma_f16(sc[2 * p + 1], qf[ks], kf + 2);
                    }
                }

                // ---- causal mask ----
                if (kbase + 63 > qbase) {
#pragma unroll
                    for (int ni = 0; ni < 8; ni++) {
#pragma unroll
                        for (int r = 0; r < 4; r++) {
                            int row = qbase + wrow + ty8 + ((r >= 2) ? 8 : 0);
                            int col = kbase + ni * 8 + 2 * tx4 + (r & 1);
                            if (col > row) sc[ni][r] = -1e30f;
                        }
                    }
                }

                // ---- online softmax (base-2) ----
#pragma unroll
                for (int rh = 0; rh < 2; rh++) {
                    const int i0 = rh * 2, i1 = rh * 2 + 1;
                    float mloc = -1e30f;
#pragma unroll
                    for (int ni = 0; ni < 8; ni++)
                        mloc = fmaxf(mloc, fmaxf(sc[ni][i0], sc[ni][i1]));
                    mloc = fmaxf(mloc, __shfl_xor_sync(0xffffffffu, mloc, 1));
                    mloc = fmaxf(mloc, __shfl_xor_sync(0xffffffffu, mloc, 2));
                    const float mnew = fmaxf(m_i[rh], mloc);
                    const bool changed = mnew > m_i[rh];
                    const float fac = ex2f(m_i[rh] - mnew);
                    m_i[rh] = mnew;
                    float rsum = 0.f;
#pragma unroll
                    for (int ni = 0; ni < 8; ni++) {
                        float p0 = ex2f(sc[ni][i0] - mnew);
                        float p1 = ex2f(sc[ni][i1] - mnew);
                        sc[ni][i0] = p0; sc[ni][i1] = p1;
                        rsum += p0 + p1;
                    }
                    rsum += __shfl_xor_sync(0xffffffffu, rsum, 1);
                    rsum += __shfl_xor_sync(0xffffffffu, rsum, 2);
                    l_i[rh] = l_i[rh] * fac + rsum;
                    if (__any_sync(0xffffffffu, changed)) {
#pragma unroll
                        for (int ni = 0; ni < 16; ni++) {
                            oacc[ni][i0] *= fac;
                            oacc[ni][i1] *= fac;
                        }
                    }
                }

                // ---- PV: P never leaves registers (C-frag == A-frag) ----
#pragma unroll
                for (int ks = 0; ks < 4; ks++) {
                    uint32_t af[4];
                    af[0] = packh2(sc[2 * ks][0], sc[2 * ks][1]);
                    af[1] = packh2(sc[2 * ks][2], sc[2 * ks][3]);
                    af[2] = packh2(sc[2 * ks + 1][0], sc[2 * ks + 1][1]);
                    af[3] = packh2(sc[2 * ks + 1][2], sc[2 * ks + 1][3]);
                    const uint32_t kb = (uint32_t)(ks * 32);
#pragma unroll
                    for (int p = 0; p < 8; p++) {
                        uint32_t vf[4];
                        ldm_x4(vf, vsu + vb_offb[p] + kb);
                        mma_f16(oacc[2 * p], af, vf);
                        mma_f16(oacc[2 * p + 1], af, vf + 2);
                    }
                }
            }
            __syncthreads();
        }

        // ---- epilogue ----
        const float inv0 = 1.0f / l_i[0];
        const float inv1 = 1.0f / l_i[1];
        const int r0 = qbase + wrow + ty8;
#pragma unroll
        for (int ni = 0; ni < 16; ni++) {
            const int cc = ni * 8 + 2 * tx4;
            __half* p0 = Og + ((size_t)((b * S_ + r0) * NH_ + h)) * D_ + cc;
            __half* p1 = Og + ((size_t)((b * S_ + r0 + 8) * NH_ + h)) * D_ + cc;
            *(__half2*)p0 = __floats2half2_rn(oacc[ni][0] * inv0, oacc[ni][1] * inv0);
            *(__half2*)p1 = __floats2half2_rn(oacc[ni][2] * inv1, oacc[ni][3] * inv1);
        }
    }
}

// ---------------- launch ----------------------------------------------------
extern "C" void kernel_launch(void* const* d_in, const int* in_sizes, int n_in,
                              void* d_out, int out_size) {
    const float* X    = (const float*)d_in[0];
    const float* Wq   = (const float*)d_in[1];
    const float* Wk   = (const float*)d_in[2];
    const float* Wv   = (const float*)d_in[3];
    const float* Wo   = (const float*)d_in[4];
    const float* cosc = (const float*)d_in[5];
    const float* sinc = (const float*)d_in[6];
    float* out = (float*)d_out;

    __half *QKVh, *Khp, *Vtp, *Ah, *Xh, *Wqkvt, *Wot;
    cudaGetSymbolAddress((void**)&QKVh, g_QKVh);
    cudaGetSymbolAddress((void**)&Khp, g_Kh);
    cudaGetSymbolAddress((void**)&Vtp, g_Vt);
    cudaGetSymbolAddress((void**)&Ah, g_Ah);
    cudaGetSymbolAddress((void**)&Xh, g_Xh);
    cudaGetSymbolAddress((void**)&Wqkvt, g_Wqkvt);
    cudaGetSymbolAddress((void**)&Wot, g_Wot);

    const int M = B_ * S_;          // 4096
    const int NQ = NH_ * D_;        // 4096
    const int NKVD = NKV_ * D_;     // 1024

    {
        int n4 = M * HID_ / 4;
        cvt_half_kernel<<<(n4 + 255) / 256, 256>>>(X, Xh, n4);
        zero_ctr_kernel<<<1, 1>>>();
        dim3 blk(32, 8);
        transpose_half_kernel<<<dim3(NQ / 32, HID_ / 32), blk>>>(Wq, Wqkvt, HID_, NQ);
        transpose_half_kernel<<<dim3(NKVD / 32, HID_ / 32), blk>>>(
            Wk, Wqkvt + (size_t)NQ * HID_, HID_, NKVD);
        transpose_half_kernel<<<dim3(NKVD / 32, HID_ / 32), blk>>>(
            Wv, Wqkvt + (size_t)(NQ + NKVD) * HID_, HID_, NKVD);
        transpose_half_kernel<<<dim3(HID_ / 32, NQ / 32), blk>>>(Wo, Wot, NQ, HID_);
    }

    cudaFuncSetAttribute(tc_gemm<__half>, cudaFuncAttributeMaxDynamicSharedMemorySize, GSM_BYTES);
    cudaFuncSetAttribute(tc_gemm<float>, cudaFuncAttributeMaxDynamicSharedMemorySize, GSM_BYTES);

    // Fused QKV projection (fp16 output)
    tc_gemm<__half><<<dim3(NQKV / BN, M / BM), 256, GSM_BYTES>>>(Xh, Wqkvt, QKVh, M, NQKV, HID_);

    // K RoPE -> fp16; V -> fp16 transposed
    rope_kh_kernel<<<(M * NKV_ * 16) / 256, 256>>>(QKVh, Khp, cosc, sinc);
    {
        dim3 blk(32, 8);
        vt_transpose_kernel<<<dim3(S_ / 32, D_ / 32, B_ * NKV_), blk>>>(QKVh, Vtp);
    }

    // Persistent flash attention (atomic work queue, counter pre-zeroed)
    cudaFuncSetAttribute(flash_mma_kernel, cudaFuncAttributeMaxDynamicSharedMemorySize, FL_SMEM_BYTES);
    flash_mma_kernel<<<FL_GRID, 256, FL_SMEM_BYTES>>>(QKVh, Khp, Vtp, cosc, sinc, Ah);

    // Output projection (fp32 output)
    tc_gemm<float><<<dim3(HID_ / BN, M / BM), 256, GSM_BYTES>>>(Ah, Wot, out, M, HID_, NQ);
}